// round 1
// baseline (speedup 1.0000x reference)
#include <cuda_runtime.h>
#include <cstdint>

// Problem constants
constexpr int Vv = 50257, Cc = 384, Tt = 1024, Hh = 6, HSs = 64, NLl = 3, Bb = 2;
constexpr int M_ROWS = Bb * Tt;   // 2048
constexpr int BH = Bb * Hh;       // 12

// ---------------- scratch (__device__ globals; no allocation allowed) --------
__device__ float g_h[M_ROWS * Cc];
__device__ float g_a[M_ROWS * Cc];
__device__ float g_q[M_ROWS * Cc];
__device__ float g_k[M_ROWS * Cc];
__device__ float g_v[M_ROWS * Cc];
__device__ float g_att[M_ROWS * Cc];
__device__ float g_m[M_ROWS * Cc];
__device__ float g_S[(size_t)BH * Tt * Tt];     // ST[bh][k][t] (scores transposed)
__device__ float g_Wqr[NLl * Cc * Cc];
__device__ float g_Wkr[NLl * Cc * Cc];
__device__ float g_Wvr[NLl * Cc * Cc];

// ---------------- embedding --------------------------------------------------
__global__ void embed_kernel(const int* __restrict__ x, const float* __restrict__ tok,
                             const float* __restrict__ pos, float* __restrict__ h) {
    int i = blockIdx.x * blockDim.x + threadIdx.x;
    if (i >= M_ROWS * Cc) return;
    int row = i / Cc, c = i % Cc;
    int t = row % Tt;
    h[i] = tok[(size_t)x[row] * Cc + c] + pos[t * Cc + c];
}

// ---------------- repack (H,C,HS) -> (C, H*HS) per layer ---------------------
__global__ void repack_kernel(const float* __restrict__ W, float* __restrict__ Wr) {
    int i = blockIdx.x * blockDim.x + threadIdx.x;
    int total = NLl * Hh * Cc * HSs;
    if (i >= total) return;
    int s = i % HSs; int tmp = i / HSs;
    int c = tmp % Cc; tmp /= Cc;
    int h = tmp % Hh; int l = tmp / Hh;
    Wr[(l * Cc + c) * Cc + h * HSs + s] = W[i];
}

// ---------------- layernorm (one block per row) ------------------------------
__global__ void ln_kernel(const float* __restrict__ x, const float* __restrict__ g,
                          const float* __restrict__ b, float* __restrict__ y) {
    int row = blockIdx.x;
    const float* xr = x + (size_t)row * Cc;
    float* yr = y + (size_t)row * Cc;
    float lsum = 0.f, lsq = 0.f;
    for (int c = threadIdx.x; c < Cc; c += blockDim.x) {
        float v = xr[c]; lsum += v; lsq += v * v;
    }
    __shared__ float sh[64];
    int lane = threadIdx.x & 31, wid = threadIdx.x >> 5;
#pragma unroll
    for (int o = 16; o; o >>= 1) {
        lsum += __shfl_xor_sync(0xffffffffu, lsum, o);
        lsq  += __shfl_xor_sync(0xffffffffu, lsq,  o);
    }
    if (lane == 0) { sh[wid] = lsum; sh[wid + 32] = lsq; }
    __syncthreads();
    int nw = blockDim.x >> 5;
    if (threadIdx.x == 0) {
        float s = 0.f, q = 0.f;
        for (int w = 0; w < nw; w++) { s += sh[w]; q += sh[w + 32]; }
        sh[0] = s; sh[32] = q;
    }
    __syncthreads();
    float mu = sh[0] / Cc;
    float var = sh[32] / Cc - mu * mu;
    float rstd = rsqrtf(var + 1e-5f);
    for (int c = threadIdx.x; c < Cc; c += blockDim.x)
        yr[c] = (xr[c] - mu) * rstd * g[c] + b[c];
}

// ---------------- generic SGEMM: C[M,N] = op(A[M,K] @ B[K,N] + bias) ---------
// FLAGS bit0: relu, bit1: accumulate into existing C
template<int BM, int BN, int BK, int TM, int TN, int FLAGS>
__global__ __launch_bounds__((BM / TM) * (BN / TN))
void sgemm_kernel(const float* __restrict__ A, const float* __restrict__ B,
                  const float* __restrict__ bias, float* __restrict__ C,
                  int M, int N, int K) {
    constexpr int THREADS = (BM / TM) * (BN / TN);
    __shared__ float As[BK][BM + 4];
    __shared__ float Bs[BK][BN + 4];
    int tid = threadIdx.x;
    int block_row = blockIdx.y * BM;
    int block_col = blockIdx.x * BN;
    int tr = tid / (BN / TN);
    int tc = tid % (BN / TN);
    float acc[TM][TN];
#pragma unroll
    for (int i = 0; i < TM; i++)
#pragma unroll
        for (int j = 0; j < TN; j++) acc[i][j] = 0.f;

    for (int k0 = 0; k0 < K; k0 += BK) {
        for (int i = tid; i < BM * BK; i += THREADS) {
            int m = i / BK, kk = i % BK;
            int gm = block_row + m;
            As[kk][m] = (gm < M) ? A[(size_t)gm * K + (k0 + kk)] : 0.f;
        }
        for (int i = tid; i < BK * BN; i += THREADS) {
            int kk = i / BN, n = i % BN;
            int gn = block_col + n;
            Bs[kk][n] = (gn < N) ? B[(size_t)(k0 + kk) * N + gn] : 0.f;
        }
        __syncthreads();
#pragma unroll
        for (int kk = 0; kk < BK; kk++) {
            float a[TM], bb[TN];
#pragma unroll
            for (int i = 0; i < TM; i++) a[i] = As[kk][tr * TM + i];
#pragma unroll
            for (int j = 0; j < TN; j++) bb[j] = Bs[kk][tc * TN + j];
#pragma unroll
            for (int i = 0; i < TM; i++)
#pragma unroll
                for (int j = 0; j < TN; j++)
                    acc[i][j] += a[i] * bb[j];
        }
        __syncthreads();
    }

#pragma unroll
    for (int i = 0; i < TM; i++) {
        int gm = block_row + tr * TM + i;
        if (gm >= M) continue;
#pragma unroll
        for (int j = 0; j < TN; j++) {
            int gn = block_col + tc * TN + j;
            if (gn >= N) continue;
            float v = acc[i][j] + bias[gn];
            if (FLAGS & 1) v = fmaxf(v, 0.f);
            if (FLAGS & 2) v += C[(size_t)gm * N + gn];
            C[(size_t)gm * N + gn] = v;
        }
    }
}

// ---------------- attention scores, stored TRANSPOSED: ST[k][t] --------------
__global__ __launch_bounds__(256)
void scores_kernel(const float* __restrict__ q, const float* __restrict__ kmat,
                   float* __restrict__ S) {
    int tb = blockIdx.x, kb = blockIdx.y, bh = blockIdx.z;
    if (tb < kb) return;  // tile entirely in masked region (t < k)
    int b = bh / Hh, h = bh % Hh;
    int t0 = tb * 32, k0 = kb * 32;
    __shared__ float Qs[32][65], Ks[32][65];
    for (int i = threadIdx.x; i < 32 * 64; i += 256) {
        int r = i >> 6, s = i & 63;
        Qs[r][s] = q[((size_t)(b * Tt + t0 + r)) * Cc + h * HSs + s];
        Ks[r][s] = kmat[((size_t)(b * Tt + k0 + r)) * Cc + h * HSs + s];
    }
    __syncthreads();
    int kl = (threadIdx.x >> 4) * 2;
    int tl = (threadIdx.x & 15) * 2;
    float a00 = 0.f, a01 = 0.f, a10 = 0.f, a11 = 0.f;
#pragma unroll
    for (int s = 0; s < 64; s++) {
        float kv0 = Ks[kl][s], kv1 = Ks[kl + 1][s];
        float qv0 = Qs[tl][s], qv1 = Qs[tl + 1][s];
        a00 += kv0 * qv0; a01 += kv0 * qv1;
        a10 += kv1 * qv0; a11 += kv1 * qv1;
    }
    const float scale = 0.125f;  // HS^-0.5
    float* Sp = S + (size_t)bh * Tt * Tt;
    Sp[(size_t)(k0 + kl) * Tt + t0 + tl]         = a00 * scale;
    Sp[(size_t)(k0 + kl) * Tt + t0 + tl + 1]     = a01 * scale;
    Sp[(size_t)(k0 + kl + 1) * Tt + t0 + tl]     = a10 * scale;
    Sp[(size_t)(k0 + kl + 1) * Tt + t0 + tl + 1] = a11 * scale;
}

// ---------------- query-axis softmax = row softmax of ST ---------------------
// Row k valid over t in [k, T); invalid entries written as 0 so PV is unmasked.
__global__ __launch_bounds__(256)
void col_softmax_kernel(float* __restrict__ S) {
    int row = blockIdx.x;           // bh * T + k
    int k = row % Tt;
    float* r = S + (size_t)row * Tt;
    __shared__ float sh[32];
    int lane = threadIdx.x & 31, wid = threadIdx.x >> 5;

    float mx = -1e30f;
    for (int t = k + threadIdx.x; t < Tt; t += 256) mx = fmaxf(mx, r[t]);
#pragma unroll
    for (int o = 16; o; o >>= 1) mx = fmaxf(mx, __shfl_xor_sync(0xffffffffu, mx, o));
    if (lane == 0) sh[wid] = mx;
    __syncthreads();
    if (threadIdx.x == 0) {
        float m = sh[0];
        for (int w = 1; w < 8; w++) m = fmaxf(m, sh[w]);
        sh[0] = m;
    }
    __syncthreads();
    mx = sh[0];
    __syncthreads();

    float sum = 0.f;
    for (int t = k + threadIdx.x; t < Tt; t += 256) sum += __expf(r[t] - mx);
#pragma unroll
    for (int o = 16; o; o >>= 1) sum += __shfl_xor_sync(0xffffffffu, sum, o);
    if (lane == 0) sh[wid] = sum;
    __syncthreads();
    if (threadIdx.x == 0) {
        float s = 0.f;
        for (int w = 0; w < 8; w++) s += sh[w];
        sh[0] = s;
    }
    __syncthreads();
    float inv = 1.f / sh[0];
    for (int t = threadIdx.x; t < Tt; t += 256)
        r[t] = (t >= k) ? __expf(r[t] - mx) * inv : 0.f;
}

// ---------------- PV: att[t,s] = sum_k ST[k][t] * v[k,s], fused head concat ---
__global__ __launch_bounds__(256)
void pv_kernel(const float* __restrict__ S, const float* __restrict__ vmat,
               float* __restrict__ att) {
    int tb = blockIdx.x, bh = blockIdx.z;
    int b = bh / Hh, h = bh % Hh;
    int t0 = tb * 64;
    __shared__ float Ss[16][65], Vs[16][65];
    int tr = threadIdx.x >> 4, tc = threadIdx.x & 15;
    float acc[4][4];
#pragma unroll
    for (int i = 0; i < 4; i++)
#pragma unroll
        for (int j = 0; j < 4; j++) acc[i][j] = 0.f;

    const float* Sp = S + (size_t)bh * Tt * Tt;
    int kmax = t0 + 64;  // rows k > t0+63 contribute only zeros
    for (int k0 = 0; k0 < kmax; k0 += 16) {
        for (int i = threadIdx.x; i < 16 * 64; i += 256) {
            int kk = i >> 6, c = i & 63;
            Ss[kk][c] = Sp[(size_t)(k0 + kk) * Tt + t0 + c];
            Vs[kk][c] = vmat[((size_t)(b * Tt + k0 + kk)) * Cc + h * HSs + c];
        }
        __syncthreads();
#pragma unroll
        for (int kk = 0; kk < 16; kk++) {
            float a[4], bb[4];
#pragma unroll
            for (int i = 0; i < 4; i++) a[i] = Ss[kk][tr * 4 + i];
#pragma unroll
            for (int j = 0; j < 4; j++) bb[j] = Vs[kk][tc * 4 + j];
#pragma unroll
            for (int i = 0; i < 4; i++)
#pragma unroll
                for (int j = 0; j < 4; j++)
                    acc[i][j] += a[i] * bb[j];
        }
        __syncthreads();
    }
#pragma unroll
    for (int i = 0; i < 4; i++)
#pragma unroll
        for (int j = 0; j < 4; j++)
            att[((size_t)(b * Tt + t0 + tr * 4 + i)) * Cc + h * HSs + tc * 4 + j] = acc[i][j];
}

// ---------------- host launcher ---------------------------------------------
static float* symaddr(const void* s) {
    void* p = nullptr;
    cudaGetSymbolAddress(&p, s);
    return (float*)p;
}

extern "C" void kernel_launch(void* const* d_in, const int* in_sizes, int n_in,
                              void* d_out, int out_size) {
    const int*   x    = (const int*)d_in[0];
    const float* tok  = (const float*)d_in[1];
    const float* pos  = (const float*)d_in[2];
    const float* Wq   = (const float*)d_in[3];
    const float* bq   = (const float*)d_in[4];
    const float* Wk   = (const float*)d_in[5];
    const float* bk   = (const float*)d_in[6];
    const float* Wv   = (const float*)d_in[7];
    const float* bv   = (const float*)d_in[8];
    const float* Wo   = (const float*)d_in[9];
    const float* bo   = (const float*)d_in[10];
    const float* ln1g = (const float*)d_in[11];
    const float* ln1b = (const float*)d_in[12];
    const float* W1   = (const float*)d_in[13];
    const float* b1   = (const float*)d_in[14];
    const float* W2   = (const float*)d_in[15];
    const float* b2   = (const float*)d_in[16];
    const float* ln2g = (const float*)d_in[17];
    const float* ln2b = (const float*)d_in[18];
    const float* Wlm  = (const float*)d_in[19];
    const float* blm  = (const float*)d_in[20];
    float* out = (float*)d_out;

    float* ph   = symaddr(g_h);
    float* pa   = symaddr(g_a);
    float* pq   = symaddr(g_q);
    float* pk   = symaddr(g_k);
    float* pv   = symaddr(g_v);
    float* patt = symaddr(g_att);
    float* pm   = symaddr(g_m);
    float* pS   = symaddr(g_S);
    float* pWqr = symaddr(g_Wqr);
    float* pWkr = symaddr(g_Wkr);
    float* pWvr = symaddr(g_Wvr);

    embed_kernel<<<(M_ROWS * Cc + 255) / 256, 256>>>(x, tok, pos, ph);

    int rp_total = NLl * Hh * Cc * HSs;
    repack_kernel<<<(rp_total + 255) / 256, 256>>>(Wq, pWqr);
    repack_kernel<<<(rp_total + 255) / 256, 256>>>(Wk, pWkr);
    repack_kernel<<<(rp_total + 255) / 256, 256>>>(Wv, pWvr);

    dim3 gs((Cc + 63) / 64, (M_ROWS + 63) / 64);  // (6, 32)

    for (int l = 0; l < NLl; l++) {
        ln_kernel<<<M_ROWS, 128>>>(ph, ln1g + l * Cc, ln1b + l * Cc, pa);

        sgemm_kernel<64, 64, 16, 4, 4, 0><<<gs, 256>>>(pa, pWqr + (size_t)l * Cc * Cc, bq + l * Cc, pq, M_ROWS, Cc, Cc);
        sgemm_kernel<64, 64, 16, 4, 4, 0><<<gs, 256>>>(pa, pWkr + (size_t)l * Cc * Cc, bk + l * Cc, pk, M_ROWS, Cc, Cc);
        sgemm_kernel<64, 64, 16, 4, 4, 0><<<gs, 256>>>(pa, pWvr + (size_t)l * Cc * Cc, bv + l * Cc, pv, M_ROWS, Cc, Cc);

        scores_kernel<<<dim3(Tt / 32, Tt / 32, BH), 256>>>(pq, pk, pS);
        col_softmax_kernel<<<BH * Tt, 256>>>(pS);
        pv_kernel<<<dim3(Tt / 64, 1, BH), 256>>>(pS, pv, patt);

        sgemm_kernel<64, 64, 16, 4, 4, 2><<<gs, 256>>>(patt, Wo + (size_t)l * Cc * Cc, bo + l * Cc, ph, M_ROWS, Cc, Cc);

        ln_kernel<<<M_ROWS, 128>>>(ph, ln2g + l * Cc, ln2b + l * Cc, pa);
        sgemm_kernel<64, 64, 16, 4, 4, 1><<<gs, 256>>>(pa, W1 + (size_t)l * Cc * Cc, b1 + l * Cc, pm, M_ROWS, Cc, Cc);
        sgemm_kernel<64, 64, 16, 4, 4, 2><<<gs, 256>>>(pm, W2 + (size_t)l * Cc * Cc, b2 + l * Cc, ph, M_ROWS, Cc, Cc);
    }

    // LM head: (2048 x 384) @ (384 x 50257) + blm
    sgemm_kernel<128, 128, 8, 8, 8, 0>
        <<<dim3((Vv + 127) / 128, M_ROWS / 128), 256>>>(ph, Wlm, blm, out, M_ROWS, Vv, Cc);
}

// round 3
// speedup vs baseline: 2.0590x; 2.0590x over previous
#include <cuda_runtime.h>
#include <cstdint>

// Problem constants
constexpr int Vv = 50257, Cc = 384, Tt = 1024, Hh = 6, HSs = 64, NLl = 3, Bb = 2;
constexpr int M_ROWS = Bb * Tt;   // 2048
constexpr int BH = Bb * Hh;       // 12
constexpr int V_PAD = 50304;      // 393 * 128

// ---------------- scratch (__device__ globals; no allocation allowed) --------
__device__ float g_h[M_ROWS * Cc];
__device__ float g_a[M_ROWS * Cc];
__device__ float g_q[M_ROWS * Cc];
__device__ float g_k[M_ROWS * Cc];
__device__ float g_v[M_ROWS * Cc];
__device__ float g_att[M_ROWS * Cc];
__device__ float g_m[M_ROWS * Cc];
__device__ float g_S[(size_t)BH * Tt * Tt];     // ST[bh][k][t] (scores transposed)
__device__ float g_Wqr[NLl * Cc * Cc];
__device__ float g_Wkr[NLl * Cc * Cc];
__device__ float g_Wvr[NLl * Cc * Cc];
__device__ float g_htf[M_ROWS * Cc];            // h rounded to tf32
__device__ float g_WlmT[(size_t)V_PAD * Cc];    // Wlm transposed -> [N,K], tf32

// ---------------- embedding --------------------------------------------------
__global__ void embed_kernel(const int* __restrict__ x, const float* __restrict__ tok,
                             const float* __restrict__ pos, float* __restrict__ h) {
    int i = blockIdx.x * blockDim.x + threadIdx.x;
    if (i >= M_ROWS * Cc) return;
    int row = i / Cc, c = i % Cc;
    int t = row % Tt;
    h[i] = tok[(size_t)x[row] * Cc + c] + pos[t * Cc + c];
}

// ---------------- repack (H,C,HS) -> (C, H*HS) per layer ---------------------
__global__ void repack_kernel(const float* __restrict__ W, float* __restrict__ Wr) {
    int i = blockIdx.x * blockDim.x + threadIdx.x;
    int total = NLl * Hh * Cc * HSs;
    if (i >= total) return;
    int s = i % HSs; int tmp = i / HSs;
    int c = tmp % Cc; tmp /= Cc;
    int h = tmp % Hh; int l = tmp / Hh;
    Wr[(l * Cc + c) * Cc + h * HSs + s] = W[i];
}

// ---------------- tf32 helpers ----------------------------------------------
__device__ __forceinline__ float to_tf32(float v) {
    uint32_t t;
    asm("cvt.rna.tf32.f32 %0, %1;" : "=r"(t) : "f"(v));
    return __uint_as_float(t);
}

// h -> tf32-rounded copy
__global__ void cvt_h_kernel(const float* __restrict__ h, float* __restrict__ o) {
    int i = blockIdx.x * blockDim.x + threadIdx.x;
    if (i < M_ROWS * Cc) o[i] = to_tf32(h[i]);
}

// Wlm (K=384 x V) -> WlmT (V_PAD x K), tf32-rounded, zero-padded rows
__global__ void transpose_wlm_kernel(const float* __restrict__ Wlm, float* __restrict__ Bt) {
    __shared__ float tile[32][33];
    int n0 = blockIdx.x * 32, k0 = blockIdx.y * 32;
    for (int dy = threadIdx.y; dy < 32; dy += 8) {
        int k = k0 + dy, n = n0 + threadIdx.x;
        tile[dy][threadIdx.x] = (n < Vv) ? Wlm[(size_t)k * Vv + n] : 0.f;
    }
    __syncthreads();
    for (int dy = threadIdx.y; dy < 32; dy += 8) {
        int n = n0 + dy, k = k0 + threadIdx.x;
        Bt[(size_t)n * Cc + k] = to_tf32(tile[threadIdx.x][dy]);
    }
}

// ---------------- layernorm (one block per row) ------------------------------
__global__ void ln_kernel(const float* __restrict__ x, const float* __restrict__ g,
                          const float* __restrict__ b, float* __restrict__ y) {
    int row = blockIdx.x;
    const float* xr = x + (size_t)row * Cc;
    float* yr = y + (size_t)row * Cc;
    float lsum = 0.f, lsq = 0.f;
    for (int c = threadIdx.x; c < Cc; c += blockDim.x) {
        float v = xr[c]; lsum += v; lsq += v * v;
    }
    __shared__ float sh[64];
    int lane = threadIdx.x & 31, wid = threadIdx.x >> 5;
#pragma unroll
    for (int o = 16; o; o >>= 1) {
        lsum += __shfl_xor_sync(0xffffffffu, lsum, o);
        lsq  += __shfl_xor_sync(0xffffffffu, lsq,  o);
    }
    if (lane == 0) { sh[wid] = lsum; sh[wid + 32] = lsq; }
    __syncthreads();
    int nw = blockDim.x >> 5;
    if (threadIdx.x == 0) {
        float s = 0.f, q = 0.f;
        for (int w = 0; w < nw; w++) { s += sh[w]; q += sh[w + 32]; }
        sh[0] = s; sh[32] = q;
    }
    __syncthreads();
    float mu = sh[0] / Cc;
    float var = sh[32] / Cc - mu * mu;
    float rstd = rsqrtf(var + 1e-5f);
    for (int c = threadIdx.x; c < Cc; c += blockDim.x)
        yr[c] = (xr[c] - mu) * rstd * g[c] + b[c];
}

// ---------------- generic SGEMM: C[M,N] = op(A[M,K] @ B[K,N] + bias) ---------
// FLAGS bit0: relu, bit1: accumulate into existing C
template<int BM, int BN, int BK, int TM, int TN, int FLAGS>
__global__ __launch_bounds__((BM / TM) * (BN / TN))
void sgemm_kernel(const float* __restrict__ A, const float* __restrict__ B,
                  const float* __restrict__ bias, float* __restrict__ C,
                  int M, int N, int K) {
    constexpr int THREADS = (BM / TM) * (BN / TN);
    __shared__ float As[BK][BM + 4];
    __shared__ float Bs[BK][BN + 4];
    int tid = threadIdx.x;
    int block_row = blockIdx.y * BM;
    int block_col = blockIdx.x * BN;
    int tr = tid / (BN / TN);
    int tc = tid % (BN / TN);
    float acc[TM][TN];
#pragma unroll
    for (int i = 0; i < TM; i++)
#pragma unroll
        for (int j = 0; j < TN; j++) acc[i][j] = 0.f;

    for (int k0 = 0; k0 < K; k0 += BK) {
        for (int i = tid; i < BM * BK; i += THREADS) {
            int m = i / BK, kk = i % BK;
            int gm = block_row + m;
            As[kk][m] = (gm < M) ? A[(size_t)gm * K + (k0 + kk)] : 0.f;
        }
        for (int i = tid; i < BK * BN; i += THREADS) {
            int kk = i / BN, n = i % BN;
            int gn = block_col + n;
            Bs[kk][n] = (gn < N) ? B[(size_t)(k0 + kk) * N + gn] : 0.f;
        }
        __syncthreads();
#pragma unroll
        for (int kk = 0; kk < BK; kk++) {
            float a[TM], bb[TN];
#pragma unroll
            for (int i = 0; i < TM; i++) a[i] = As[kk][tr * TM + i];
#pragma unroll
            for (int j = 0; j < TN; j++) bb[j] = Bs[kk][tc * TN + j];
#pragma unroll
            for (int i = 0; i < TM; i++)
#pragma unroll
                for (int j = 0; j < TN; j++)
                    acc[i][j] += a[i] * bb[j];
        }
        __syncthreads();
    }

#pragma unroll
    for (int i = 0; i < TM; i++) {
        int gm = block_row + tr * TM + i;
        if (gm >= M) continue;
#pragma unroll
        for (int j = 0; j < TN; j++) {
            int gn = block_col + tc * TN + j;
            if (gn >= N) continue;
            float v = acc[i][j] + bias[gn];
            if (FLAGS & 1) v = fmaxf(v, 0.f);
            if (FLAGS & 2) v += C[(size_t)gm * N + gn];
            C[(size_t)gm * N + gn] = v;
        }
    }
}

// ---------------- attention scores, stored TRANSPOSED: ST[k][t] --------------
__global__ __launch_bounds__(256)
void scores_kernel(const float* __restrict__ q, const float* __restrict__ kmat,
                   float* __restrict__ S) {
    int tb = blockIdx.x, kb = blockIdx.y, bh = blockIdx.z;
    if (tb < kb) return;  // tile entirely in masked region (t < k)
    int b = bh / Hh, h = bh % Hh;
    int t0 = tb * 32, k0 = kb * 32;
    __shared__ float Qs[32][65], Ks[32][65];
    for (int i = threadIdx.x; i < 32 * 64; i += 256) {
        int r = i >> 6, s = i & 63;
        Qs[r][s] = q[((size_t)(b * Tt + t0 + r)) * Cc + h * HSs + s];
        Ks[r][s] = kmat[((size_t)(b * Tt + k0 + r)) * Cc + h * HSs + s];
    }
    __syncthreads();
    int kl = (threadIdx.x >> 4) * 2;
    int tl = (threadIdx.x & 15) * 2;
    float a00 = 0.f, a01 = 0.f, a10 = 0.f, a11 = 0.f;
#pragma unroll
    for (int s = 0; s < 64; s++) {
        float kv0 = Ks[kl][s], kv1 = Ks[kl + 1][s];
        float qv0 = Qs[tl][s], qv1 = Qs[tl + 1][s];
        a00 += kv0 * qv0; a01 += kv0 * qv1;
        a10 += kv1 * qv0; a11 += kv1 * qv1;
    }
    const float scale = 0.125f;  // HS^-0.5
    float* Sp = S + (size_t)bh * Tt * Tt;
    Sp[(size_t)(k0 + kl) * Tt + t0 + tl]         = a00 * scale;
    Sp[(size_t)(k0 + kl) * Tt + t0 + tl + 1]     = a01 * scale;
    Sp[(size_t)(k0 + kl + 1) * Tt + t0 + tl]     = a10 * scale;
    Sp[(size_t)(k0 + kl + 1) * Tt + t0 + tl + 1] = a11 * scale;
}

// ---------------- query-axis softmax = row softmax of ST ---------------------
__global__ __launch_bounds__(256)
void col_softmax_kernel(float* __restrict__ S) {
    int row = blockIdx.x;           // bh * T + k
    int k = row % Tt;
    float* r = S + (size_t)row * Tt;
    __shared__ float sh[32];
    int lane = threadIdx.x & 31, wid = threadIdx.x >> 5;

    float mx = -1e30f;
    for (int t = k + threadIdx.x; t < Tt; t += 256) mx = fmaxf(mx, r[t]);
#pragma unroll
    for (int o = 16; o; o >>= 1) mx = fmaxf(mx, __shfl_xor_sync(0xffffffffu, mx, o));
    if (lane == 0) sh[wid] = mx;
    __syncthreads();
    if (threadIdx.x == 0) {
        float m = sh[0];
        for (int w = 1; w < 8; w++) m = fmaxf(m, sh[w]);
        sh[0] = m;
    }
    __syncthreads();
    mx = sh[0];
    __syncthreads();

    float sum = 0.f;
    for (int t = k + threadIdx.x; t < Tt; t += 256) sum += __expf(r[t] - mx);
#pragma unroll
    for (int o = 16; o; o >>= 1) sum += __shfl_xor_sync(0xffffffffu, sum, o);
    if (lane == 0) sh[wid] = sum;
    __syncthreads();
    if (threadIdx.x == 0) {
        float s = 0.f;
        for (int w = 0; w < 8; w++) s += sh[w];
        sh[0] = s;
    }
    __syncthreads();
    float inv = 1.f / sh[0];
    for (int t = threadIdx.x; t < Tt; t += 256)
        r[t] = (t >= k) ? __expf(r[t] - mx) * inv : 0.f;
}

// ---------------- PV: att[t,s] = sum_k ST[k][t] * v[k,s], fused head concat ---
__global__ __launch_bounds__(256)
void pv_kernel(const float* __restrict__ S, const float* __restrict__ vmat,
               float* __restrict__ att) {
    int tb = blockIdx.x, bh = blockIdx.z;
    int b = bh / Hh, h = bh % Hh;
    int t0 = tb * 64;
    __shared__ float Ss[16][65], Vs[16][65];
    int tr = threadIdx.x >> 4, tc = threadIdx.x & 15;
    float acc[4][4];
#pragma unroll
    for (int i = 0; i < 4; i++)
#pragma unroll
        for (int j = 0; j < 4; j++) acc[i][j] = 0.f;

    const float* Sp = S + (size_t)bh * Tt * Tt;
    int kmax = t0 + 64;  // rows k > t0+63 contribute only zeros
    for (int k0 = 0; k0 < kmax; k0 += 16) {
        for (int i = threadIdx.x; i < 16 * 64; i += 256) {
            int kk = i >> 6, c = i & 63;
            Ss[kk][c] = Sp[(size_t)(k0 + kk) * Tt + t0 + c];
            Vs[kk][c] = vmat[((size_t)(b * Tt + k0 + kk)) * Cc + h * HSs + c];
        }
        __syncthreads();
#pragma unroll
        for (int kk = 0; kk < 16; kk++) {
            float a[4], bb[4];
#pragma unroll
            for (int i = 0; i < 4; i++) a[i] = Ss[kk][tr * 4 + i];
#pragma unroll
            for (int j = 0; j < 4; j++) bb[j] = Vs[kk][tc * 4 + j];
#pragma unroll
            for (int i = 0; i < 4; i++)
#pragma unroll
                for (int j = 0; j < 4; j++)
                    acc[i][j] += a[i] * bb[j];
        }
        __syncthreads();
    }
#pragma unroll
    for (int i = 0; i < 4; i++)
#pragma unroll
        for (int j = 0; j < 4; j++)
            att[((size_t)(b * Tt + t0 + tr * 4 + i)) * Cc + h * HSs + tc * 4 + j] = acc[i][j];
}

// ================= mma.sync tf32 LM head =====================================
// out[2048, 50257] = A[2048,384] @ B[384,V]  with B pre-transposed to [V_PAD,384]
// CTA tile 128x128x32, 8 warps (4M x 2N), warp tile 32x64, m16n8k8 tf32 HMMA.

__device__ __forceinline__ void mma_tf32(float* c, const float* a, const float* b) {
    const uint32_t* A = reinterpret_cast<const uint32_t*>(a);
    const uint32_t* B = reinterpret_cast<const uint32_t*>(b);
    asm volatile(
        "mma.sync.aligned.m16n8k8.row.col.f32.tf32.tf32.f32 "
        "{%0,%1,%2,%3}, {%4,%5,%6,%7}, {%8,%9}, {%0,%1,%2,%3};"
        : "+f"(c[0]), "+f"(c[1]), "+f"(c[2]), "+f"(c[3])
        : "r"(A[0]), "r"(A[1]), "r"(A[2]), "r"(A[3]), "r"(B[0]), "r"(B[1]));
}

constexpr int LM_PITCH = 36;  // SMEM row pitch: (r*36+c) -> all 32 lanes distinct banks

__global__ __launch_bounds__(256, 1)
void lmhead_mma_kernel(const float* __restrict__ A, const float* __restrict__ Bt,
                       const float* __restrict__ bias, float* __restrict__ out) {
    __shared__ float As[128 * LM_PITCH];
    __shared__ float Bs[128 * LM_PITCH];
    int tid = threadIdx.x;
    int warp = tid >> 5, lane = tid & 31;
    int wm = warp & 3, wn = warp >> 2;       // 4 x 2 warp grid
    int grp = lane >> 2, tig = lane & 3;     // groupID, threadID_in_group
    int m0 = blockIdx.x * 128;               // M fastest -> B-tile L2 reuse
    int n0 = blockIdx.y * 128;

    const float* Ab = A + (size_t)m0 * Cc;
    const float* Bb = Bt + (size_t)n0 * Cc;

    float4 pfA[4], pfB[4];
#pragma unroll
    for (int it = 0; it < 4; it++) {
        int slot = tid + it * 256;
        int r = slot >> 3, c4 = slot & 7;
        pfA[it] = *reinterpret_cast<const float4*>(Ab + (size_t)r * Cc + c4 * 4);
        pfB[it] = *reinterpret_cast<const float4*>(Bb + (size_t)r * Cc + c4 * 4);
    }

    float acc[2][8][4];
#pragma unroll
    for (int i = 0; i < 2; i++)
#pragma unroll
        for (int j = 0; j < 8; j++)
#pragma unroll
            for (int q = 0; q < 4; q++) acc[i][j][q] = 0.f;

#pragma unroll 1
    for (int kt = 0; kt < Cc / 32; kt++) {
#pragma unroll
        for (int it = 0; it < 4; it++) {
            int slot = tid + it * 256;
            int r = slot >> 3, c4 = slot & 7;
            *reinterpret_cast<float4*>(&As[r * LM_PITCH + c4 * 4]) = pfA[it];
            *reinterpret_cast<float4*>(&Bs[r * LM_PITCH + c4 * 4]) = pfB[it];
        }
        __syncthreads();
        if (kt < Cc / 32 - 1) {
            int k0 = (kt + 1) * 32;
#pragma unroll
            for (int it = 0; it < 4; it++) {
                int slot = tid + it * 256;
                int r = slot >> 3, c4 = slot & 7;
                pfA[it] = *reinterpret_cast<const float4*>(Ab + (size_t)r * Cc + k0 + c4 * 4);
                pfB[it] = *reinterpret_cast<const float4*>(Bb + (size_t)r * Cc + k0 + c4 * 4);
            }
        }
#pragma unroll
        for (int k8 = 0; k8 < 4; k8++) {
            int kb = k8 * 8;
            float a[2][4];
#pragma unroll
            for (int fm = 0; fm < 2; fm++) {
                int m = wm * 32 + fm * 16;
                a[fm][0] = As[(m + grp) * LM_PITCH + kb + tig];
                a[fm][1] = As[(m + grp + 8) * LM_PITCH + kb + tig];
                a[fm][2] = As[(m + grp) * LM_PITCH + kb + tig + 4];
                a[fm][3] = As[(m + grp + 8) * LM_PITCH + kb + tig + 4];
            }
            float b[8][2];
#pragma unroll
            for (int fn = 0; fn < 8; fn++) {
                int n = wn * 64 + fn * 8;
                b[fn][0] = Bs[(n + grp) * LM_PITCH + kb + tig];
                b[fn][1] = Bs[(n + grp) * LM_PITCH + kb + tig + 4];
            }
#pragma unroll
            for (int fm = 0; fm < 2; fm++)
#pragma unroll
                for (int fn = 0; fn < 8; fn++)
                    mma_tf32(acc[fm][fn], a[fm], b[fn]);
        }
        __syncthreads();
    }

    // epilogue: direct stores (+bias), column-bound guarded
#pragma unroll
    for (int fm = 0; fm < 2; fm++) {
        int m_lo = m0 + wm * 32 + fm * 16 + grp;
        int m_hi = m_lo + 8;
#pragma unroll
        for (int fn = 0; fn < 8; fn++) {
            int n = n0 + wn * 64 + fn * 8 + tig * 2;
            if (n < Vv) {
                float bv = bias[n];
                out[(size_t)m_lo * Vv + n] = acc[fm][fn][0] + bv;
                out[(size_t)m_hi * Vv + n] = acc[fm][fn][2] + bv;
            }
            if (n + 1 < Vv) {
                float bv = bias[n + 1];
                out[(size_t)m_lo * Vv + n + 1] = acc[fm][fn][1] + bv;
                out[(size_t)m_hi * Vv + n + 1] = acc[fm][fn][3] + bv;
            }
        }
    }
}

// ---------------- host launcher ---------------------------------------------
static float* symaddr(const void* s) {
    void* p = nullptr;
    cudaGetSymbolAddress(&p, s);
    return (float*)p;
}

extern "C" void kernel_launch(void* const* d_in, const int* in_sizes, int n_in,
                              void* d_out, int out_size) {
    const int*   x    = (const int*)d_in[0];
    const float* tok  = (const float*)d_in[1];
    const float* pos  = (const float*)d_in[2];
    const float* Wq   = (const float*)d_in[3];
    const float* bq   = (const float*)d_in[4];
    const float* Wk   = (const float*)d_in[5];
    const float* bk   = (const float*)d_in[6];
    const float* Wv   = (const float*)d_in[7];
    const float* bv   = (const float*)d_in[8];
    const float* Wo   = (const float*)d_in[9];
    const float* bo   = (const float*)d_in[10];
    const float* ln1g = (const float*)d_in[11];
    const float* ln1b = (const float*)d_in[12];
    const float* W1   = (const float*)d_in[13];
    const float* b1   = (const float*)d_in[14];
    const float* W2   = (const float*)d_in[15];
    const float* b2   = (const float*)d_in[16];
    const float* ln2g = (const float*)d_in[17];
    const float* ln2b = (const float*)d_in[18];
    const float* Wlm  = (const float*)d_in[19];
    const float* blm  = (const float*)d_in[20];
    float* out = (float*)d_out;

    float* ph   = symaddr(g_h);
    float* pa   = symaddr(g_a);
    float* pq   = symaddr(g_q);
    float* pk   = symaddr(g_k);
    float* pv   = symaddr(g_v);
    float* patt = symaddr(g_att);
    float* pm   = symaddr(g_m);
    float* pS   = symaddr(g_S);
    float* pWqr = symaddr(g_Wqr);
    float* pWkr = symaddr(g_Wkr);
    float* pWvr = symaddr(g_Wvr);
    float* phtf = symaddr(g_htf);
    float* pWlmT = symaddr(g_WlmT);

    embed_kernel<<<(M_ROWS * Cc + 255) / 256, 256>>>(x, tok, pos, ph);

    int rp_total = NLl * Hh * Cc * HSs;
    repack_kernel<<<(rp_total + 255) / 256, 256>>>(Wq, pWqr);
    repack_kernel<<<(rp_total + 255) / 256, 256>>>(Wk, pWkr);
    repack_kernel<<<(rp_total + 255) / 256, 256>>>(Wv, pWvr);

    // repack LM weight early (independent of layer loop)
    transpose_wlm_kernel<<<dim3(V_PAD / 32, Cc / 32), dim3(32, 8)>>>(Wlm, pWlmT);

    dim3 gs((Cc + 63) / 64, (M_ROWS + 63) / 64);  // (6, 32)

    for (int l = 0; l < NLl; l++) {
        ln_kernel<<<M_ROWS, 128>>>(ph, ln1g + l * Cc, ln1b + l * Cc, pa);

        sgemm_kernel<64, 64, 16, 4, 4, 0><<<gs, 256>>>(pa, pWqr + (size_t)l * Cc * Cc, bq + l * Cc, pq, M_ROWS, Cc, Cc);
        sgemm_kernel<64, 64, 16, 4, 4, 0><<<gs, 256>>>(pa, pWkr + (size_t)l * Cc * Cc, bk + l * Cc, pk, M_ROWS, Cc, Cc);
        sgemm_kernel<64, 64, 16, 4, 4, 0><<<gs, 256>>>(pa, pWvr + (size_t)l * Cc * Cc, bv + l * Cc, pv, M_ROWS, Cc, Cc);

        scores_kernel<<<dim3(Tt / 32, Tt / 32, BH), 256>>>(pq, pk, pS);
        col_softmax_kernel<<<BH * Tt, 256>>>(pS);
        pv_kernel<<<dim3(Tt / 64, 1, BH), 256>>>(pS, pv, patt);

        sgemm_kernel<64, 64, 16, 4, 4, 2><<<gs, 256>>>(patt, Wo + (size_t)l * Cc * Cc, bo + l * Cc, ph, M_ROWS, Cc, Cc);

        ln_kernel<<<M_ROWS, 128>>>(ph, ln2g + l * Cc, ln2b + l * Cc, pa);
        sgemm_kernel<64, 64, 16, 4, 4, 1><<<gs, 256>>>(pa, W1 + (size_t)l * Cc * Cc, b1 + l * Cc, pm, M_ROWS, Cc, Cc);
        sgemm_kernel<64, 64, 16, 4, 4, 2><<<gs, 256>>>(pm, W2 + (size_t)l * Cc * Cc, b2 + l * Cc, ph, M_ROWS, Cc, Cc);
    }

    // LM head on mma.sync tf32 tensor cores
    cvt_h_kernel<<<(M_ROWS * Cc + 255) / 256, 256>>>(ph, phtf);
    lmhead_mma_kernel<<<dim3(M_ROWS / 128, V_PAD / 128), 256>>>(phtf, pWlmT, blm, out);
}

// round 4
// speedup vs baseline: 3.9609x; 1.9238x over previous
#include <cuda_runtime.h>
#include <cstdint>

// Problem constants
constexpr int Vv = 50257, Cc = 384, Tt = 1024, Hh = 6, HSs = 64, NLl = 3, Bb = 2;
constexpr int M_ROWS = Bb * Tt;   // 2048
constexpr int BH = Bb * Hh;       // 12
constexpr int V_PAD = 50304;      // 393 * 128
constexpr int QKV_P = 3 * Cc;     // 1152

// ---------------- scratch (__device__ globals; no allocation allowed) --------
__device__ float g_h[M_ROWS * Cc];
__device__ float g_a[M_ROWS * Cc];
__device__ float g_qkv[M_ROWS * QKV_P];
__device__ float g_att[M_ROWS * Cc];
__device__ float g_m[M_ROWS * Cc];
__device__ float g_S[(size_t)BH * Tt * Tt];        // ST[bh][k][t]
__device__ float g_WqkvT[NLl * QKV_P * Cc];        // [l][n][k] tf32
__device__ float g_bqkv[NLl * QKV_P];
__device__ float g_WoT[NLl * Cc * Cc];
__device__ float g_W1T[NLl * Cc * Cc];
__device__ float g_W2T[NLl * Cc * Cc];
__device__ float g_htf[M_ROWS * Cc];               // h rounded to tf32
__device__ float g_WlmT[(size_t)V_PAD * Cc];       // [n][k] tf32, zero padded

// ---------------- tf32 helper ------------------------------------------------
__device__ __forceinline__ float to_tf32(float v) {
    uint32_t t;
    asm("cvt.rna.tf32.f32 %0, %1;" : "=r"(t) : "f"(v));
    return __uint_as_float(t);
}

// ---------------- embedding --------------------------------------------------
__global__ void embed_kernel(const int* __restrict__ x, const float* __restrict__ tok,
                             const float* __restrict__ pos, float* __restrict__ h) {
    int i = blockIdx.x * blockDim.x + threadIdx.x;
    if (i >= M_ROWS * Cc) return;
    int row = i / Cc, c = i % Cc;
    int t = row % Tt;
    h[i] = tok[(size_t)x[row] * Cc + c] + pos[t * Cc + c];
}

// ---------------- repacks (one-time per call) --------------------------------
// Wq/Wk/Wv (NL,H,C,HS) -> WqkvT [l][n=1152][k=384], tf32
__global__ void repack_qkvT_kernel(const float* __restrict__ Wq, const float* __restrict__ Wk,
                                   const float* __restrict__ Wv, float* __restrict__ O) {
    int i = blockIdx.x * blockDim.x + threadIdx.x;
    if (i >= NLl * QKV_P * Cc) return;
    int k = i % Cc;
    int n = (i / Cc) % QKV_P;
    int l = i / (Cc * QKV_P);
    int sel = n / Cc, h = (n % Cc) / HSs, s = n % HSs;
    const float* W = (sel == 0) ? Wq : (sel == 1) ? Wk : Wv;
    O[i] = to_tf32(W[(((size_t)l * Hh + h) * Cc + k) * HSs + s]);
}

__global__ void repack_bqkv_kernel(const float* __restrict__ bq, const float* __restrict__ bk,
                                   const float* __restrict__ bv, float* __restrict__ O) {
    int i = blockIdx.x * blockDim.x + threadIdx.x;
    if (i >= NLl * QKV_P) return;
    int n = i % QKV_P, l = i / QKV_P;
    int sel = n / Cc, h = (n % Cc) / HSs, s = n % HSs;
    const float* B = (sel == 0) ? bq : (sel == 1) ? bk : bv;
    O[i] = B[((size_t)l * Hh + h) * HSs + s];
}

// W [l][k=384][n=384] -> WT [l][n][k], tf32
__global__ void transpose_w_kernel(const float* __restrict__ W, float* __restrict__ WT) {
    __shared__ float t[32][33];
    int l = blockIdx.z;
    int n0 = blockIdx.x * 32, k0 = blockIdx.y * 32;
    const float* Wl = W + (size_t)l * Cc * Cc;
    float* Tl = WT + (size_t)l * Cc * Cc;
    for (int dy = threadIdx.y; dy < 32; dy += 8)
        t[dy][threadIdx.x] = Wl[(size_t)(k0 + dy) * Cc + n0 + threadIdx.x];
    __syncthreads();
    for (int dy = threadIdx.y; dy < 32; dy += 8)
        Tl[(size_t)(n0 + dy) * Cc + k0 + threadIdx.x] = to_tf32(t[threadIdx.x][dy]);
}

// Wlm (K=384 x V) -> WlmT (V_PAD x K), tf32-rounded, zero-padded rows
__global__ void transpose_wlm_kernel(const float* __restrict__ Wlm, float* __restrict__ Bt) {
    __shared__ float tile[32][33];
    int n0 = blockIdx.x * 32, k0 = blockIdx.y * 32;
    for (int dy = threadIdx.y; dy < 32; dy += 8) {
        int k = k0 + dy, n = n0 + threadIdx.x;
        tile[dy][threadIdx.x] = (n < Vv) ? Wlm[(size_t)k * Vv + n] : 0.f;
    }
    __syncthreads();
    for (int dy = threadIdx.y; dy < 32; dy += 8) {
        int n = n0 + dy, k = k0 + threadIdx.x;
        Bt[(size_t)n * Cc + k] = to_tf32(tile[threadIdx.x][dy]);
    }
}

// h -> tf32-rounded copy (LM head A operand)
__global__ void cvt_h_kernel(const float* __restrict__ h, float* __restrict__ o) {
    int i = blockIdx.x * blockDim.x + threadIdx.x;
    if (i < M_ROWS * Cc) o[i] = to_tf32(h[i]);
}

// ---------------- layernorm (output tf32-rounded; feeds GEMMs only) ---------
__global__ void ln_kernel(const float* __restrict__ x, const float* __restrict__ g,
                          const float* __restrict__ b, float* __restrict__ y) {
    int row = blockIdx.x;
    const float* xr = x + (size_t)row * Cc;
    float* yr = y + (size_t)row * Cc;
    float lsum = 0.f, lsq = 0.f;
    for (int c = threadIdx.x; c < Cc; c += blockDim.x) {
        float v = xr[c]; lsum += v; lsq += v * v;
    }
    __shared__ float sh[64];
    int lane = threadIdx.x & 31, wid = threadIdx.x >> 5;
#pragma unroll
    for (int o = 16; o; o >>= 1) {
        lsum += __shfl_xor_sync(0xffffffffu, lsum, o);
        lsq  += __shfl_xor_sync(0xffffffffu, lsq,  o);
    }
    if (lane == 0) { sh[wid] = lsum; sh[wid + 32] = lsq; }
    __syncthreads();
    int nw = blockDim.x >> 5;
    if (threadIdx.x == 0) {
        float s = 0.f, q = 0.f;
        for (int w = 0; w < nw; w++) { s += sh[w]; q += sh[w + 32]; }
        sh[0] = s; sh[32] = q;
    }
    __syncthreads();
    float mu = sh[0] / Cc;
    float var = sh[32] / Cc - mu * mu;
    float rstd = rsqrtf(var + 1e-5f);
    for (int c = threadIdx.x; c < Cc; c += blockDim.x)
        yr[c] = to_tf32((xr[c] - mu) * rstd * g[c] + b[c]);
}

// ---------------- attention scores (from fused qkv), stored ST[k][t] ---------
__global__ __launch_bounds__(256)
void scores_kernel(const float* __restrict__ qkv, float* __restrict__ S) {
    int tb = blockIdx.x, kb = blockIdx.y, bh = blockIdx.z;
    if (tb < kb) return;
    int b = bh / Hh, h = bh % Hh;
    int t0 = tb * 32, k0 = kb * 32;
    __shared__ float Qs[32][65], Ks[32][65];
    for (int i = threadIdx.x; i < 32 * 64; i += 256) {
        int r = i >> 6, s = i & 63;
        Qs[r][s] = qkv[((size_t)(b * Tt + t0 + r)) * QKV_P + h * HSs + s];
        Ks[r][s] = qkv[((size_t)(b * Tt + k0 + r)) * QKV_P + Cc + h * HSs + s];
    }
    __syncthreads();
    int kl = (threadIdx.x >> 4) * 2;
    int tl = (threadIdx.x & 15) * 2;
    float a00 = 0.f, a01 = 0.f, a10 = 0.f, a11 = 0.f;
#pragma unroll
    for (int s = 0; s < 64; s++) {
        float kv0 = Ks[kl][s], kv1 = Ks[kl + 1][s];
        float qv0 = Qs[tl][s], qv1 = Qs[tl + 1][s];
        a00 += kv0 * qv0; a01 += kv0 * qv1;
        a10 += kv1 * qv0; a11 += kv1 * qv1;
    }
    const float scale = 0.125f;
    float* Sp = S + (size_t)bh * Tt * Tt;
    Sp[(size_t)(k0 + kl) * Tt + t0 + tl]         = a00 * scale;
    Sp[(size_t)(k0 + kl) * Tt + t0 + tl + 1]     = a01 * scale;
    Sp[(size_t)(k0 + kl + 1) * Tt + t0 + tl]     = a10 * scale;
    Sp[(size_t)(k0 + kl + 1) * Tt + t0 + tl + 1] = a11 * scale;
}

// ---------------- query-axis softmax = row softmax of ST ---------------------
__global__ __launch_bounds__(256)
void col_softmax_kernel(float* __restrict__ S) {
    int row = blockIdx.x;
    int k = row % Tt;
    float* r = S + (size_t)row * Tt;
    __shared__ float sh[32];
    int lane = threadIdx.x & 31, wid = threadIdx.x >> 5;

    float mx = -1e30f;
    for (int t = k + threadIdx.x; t < Tt; t += 256) mx = fmaxf(mx, r[t]);
#pragma unroll
    for (int o = 16; o; o >>= 1) mx = fmaxf(mx, __shfl_xor_sync(0xffffffffu, mx, o));
    if (lane == 0) sh[wid] = mx;
    __syncthreads();
    if (threadIdx.x == 0) {
        float m = sh[0];
        for (int w = 1; w < 8; w++) m = fmaxf(m, sh[w]);
        sh[0] = m;
    }
    __syncthreads();
    mx = sh[0];
    __syncthreads();

    float sum = 0.f;
    for (int t = k + threadIdx.x; t < Tt; t += 256) sum += __expf(r[t] - mx);
#pragma unroll
    for (int o = 16; o; o >>= 1) sum += __shfl_xor_sync(0xffffffffu, sum, o);
    if (lane == 0) sh[wid] = sum;
    __syncthreads();
    if (threadIdx.x == 0) {
        float s = 0.f;
        for (int w = 0; w < 8; w++) s += sh[w];
        sh[0] = s;
    }
    __syncthreads();
    float inv = 1.f / sh[0];
    for (int t = threadIdx.x; t < Tt; t += 256)
        r[t] = (t >= k) ? __expf(r[t] - mx) * inv : 0.f;
}

// ---------------- PV: att[t,s] = sum_k ST[k][t] * v[k,s] (tf32-rounded out) --
__global__ __launch_bounds__(256)
void pv_kernel(const float* __restrict__ S, const float* __restrict__ qkv,
               float* __restrict__ att) {
    int tb = blockIdx.x, bh = blockIdx.z;
    int b = bh / Hh, h = bh % Hh;
    int t0 = tb * 64;
    __shared__ float Ss[16][65], Vs[16][65];
    int tr = threadIdx.x >> 4, tc = threadIdx.x & 15;
    float acc[4][4];
#pragma unroll
    for (int i = 0; i < 4; i++)
#pragma unroll
        for (int j = 0; j < 4; j++) acc[i][j] = 0.f;

    const float* Sp = S + (size_t)bh * Tt * Tt;
    int kmax = t0 + 64;
    for (int k0 = 0; k0 < kmax; k0 += 16) {
        for (int i = threadIdx.x; i < 16 * 64; i += 256) {
            int kk = i >> 6, c = i & 63;
            Ss[kk][c] = Sp[(size_t)(k0 + kk) * Tt + t0 + c];
            Vs[kk][c] = qkv[((size_t)(b * Tt + k0 + kk)) * QKV_P + 2 * Cc + h * HSs + c];
        }
        __syncthreads();
#pragma unroll
        for (int kk = 0; kk < 16; kk++) {
            float a[4], bb[4];
#pragma unroll
            for (int i = 0; i < 4; i++) a[i] = Ss[kk][tr * 4 + i];
#pragma unroll
            for (int j = 0; j < 4; j++) bb[j] = Vs[kk][tc * 4 + j];
#pragma unroll
            for (int i = 0; i < 4; i++)
#pragma unroll
                for (int j = 0; j < 4; j++)
                    acc[i][j] += a[i] * bb[j];
        }
        __syncthreads();
    }
#pragma unroll
    for (int i = 0; i < 4; i++)
#pragma unroll
        for (int j = 0; j < 4; j++)
            att[((size_t)(b * Tt + t0 + tr * 4 + i)) * Cc + h * HSs + tc * 4 + j] =
                to_tf32(acc[i][j]);
}

// ================= unified tf32 mma.sync GEMM ================================
// C[2048, N] = A[2048,384] @ Bt[N,384]^T (+bias). 128x128x32 tile, 8 warps,
// cp.async 2-stage pipeline, XOR-swizzled SMEM (pitch 32 floats).
// FLAGS: 1=relu, 2=accumulate into C, 4=col guard (<Vv), 8=round output tf32.

__device__ __forceinline__ void mma_tf32(float* c, const float* a, const float* b) {
    const uint32_t* A = reinterpret_cast<const uint32_t*>(a);
    const uint32_t* B = reinterpret_cast<const uint32_t*>(b);
    asm volatile(
        "mma.sync.aligned.m16n8k8.row.col.f32.tf32.tf32.f32 "
        "{%0,%1,%2,%3}, {%4,%5,%6,%7}, {%8,%9}, {%0,%1,%2,%3};"
        : "+f"(c[0]), "+f"(c[1]), "+f"(c[2]), "+f"(c[3])
        : "r"(A[0]), "r"(A[1]), "r"(A[2]), "r"(A[3]), "r"(B[0]), "r"(B[1]));
}

__device__ __forceinline__ uint32_t smem_u32(const void* p) {
    uint32_t a;
    asm("{ .reg .u64 t; cvta.to.shared.u64 t, %1; cvt.u32.u64 %0, t; }" : "=r"(a) : "l"(p));
    return a;
}
__device__ __forceinline__ void cp_async16(uint32_t saddr, const void* g) {
    asm volatile("cp.async.cg.shared.global [%0], [%1], 16;" :: "r"(saddr), "l"(g) : "memory");
}
__device__ __forceinline__ void cp_commit() {
    asm volatile("cp.async.commit_group;" ::: "memory");
}
template<int N>
__device__ __forceinline__ void cp_wait() {
    asm volatile("cp.async.wait_group %0;" :: "n"(N) : "memory");
}
// swizzled scalar index: row r, 4-col group g, sub 0..3
__device__ __forceinline__ int swz(int r, int g, int sub) {
    return r * 32 + (((g ^ (r & 7)) << 2)) + sub;
}

constexpr int NKT = Cc / 32;  // 12

template<int FLAGS>
__global__ __launch_bounds__(256)
void mma_gemm_kernel(const float* __restrict__ A, const float* __restrict__ Bt,
                     const float* __restrict__ bias, float* __restrict__ C,
                     int ldc) {
    extern __shared__ float sm[];  // 2 stages x (A 4096 + B 4096) floats = 64KB
    int tid = threadIdx.x;
    int warp = tid >> 5, lane = tid & 31;
    int wm = warp & 3, wn = warp >> 2;
    int grp = lane >> 2, tig = lane & 3;
    int m0 = blockIdx.x * 128, n0 = blockIdx.y * 128;
    const float* Ab = A + (size_t)m0 * Cc;
    const float* Bb = Bt + (size_t)n0 * Cc;

    uint32_t sbase = smem_u32(sm);

    auto issue = [&](int kt, int stage) {
        uint32_t as = sbase + stage * 32768u;
        uint32_t bs = as + 16384u;
#pragma unroll
        for (int it = 0; it < 4; it++) {
            int slot = tid + it * 256;
            int r = slot >> 3, c4 = slot & 7;
            uint32_t so = (uint32_t)((r * 32 + ((c4 ^ (r & 7)) << 2)) * 4);
            cp_async16(as + so, Ab + (size_t)r * Cc + kt * 32 + c4 * 4);
            cp_async16(bs + so, Bb + (size_t)r * Cc + kt * 32 + c4 * 4);
        }
    };

    float acc[2][8][4];
#pragma unroll
    for (int i = 0; i < 2; i++)
#pragma unroll
        for (int j = 0; j < 8; j++)
#pragma unroll
            for (int q = 0; q < 4; q++) acc[i][j][q] = 0.f;

    issue(0, 0);
    cp_commit();

#pragma unroll 1
    for (int kt = 0; kt < NKT; kt++) {
        if (kt + 1 < NKT) {
            issue(kt + 1, (kt + 1) & 1);
            cp_commit();
            cp_wait<1>();
        } else {
            cp_wait<0>();
        }
        __syncthreads();
        const float* As = sm + (kt & 1) * 8192;
        const float* Bs = As + 4096;
#pragma unroll
        for (int k8 = 0; k8 < 4; k8++) {
            int g0 = k8 * 2;
            float a[2][4];
#pragma unroll
            for (int fm = 0; fm < 2; fm++) {
                int m = wm * 32 + fm * 16;
                a[fm][0] = As[swz(m + grp,     g0,     tig)];
                a[fm][1] = As[swz(m + grp + 8, g0,     tig)];
                a[fm][2] = As[swz(m + grp,     g0 + 1, tig)];
                a[fm][3] = As[swz(m + grp + 8, g0 + 1, tig)];
            }
            float b[8][2];
#pragma unroll
            for (int fn = 0; fn < 8; fn++) {
                int n = wn * 64 + fn * 8;
                b[fn][0] = Bs[swz(n + grp, g0,     tig)];
                b[fn][1] = Bs[swz(n + grp, g0 + 1, tig)];
            }
#pragma unroll
            for (int fm = 0; fm < 2; fm++)
#pragma unroll
                for (int fn = 0; fn < 8; fn++)
                    mma_tf32(acc[fm][fn], a[fm], b[fn]);
        }
        __syncthreads();
    }

    // epilogue
#pragma unroll
    for (int fm = 0; fm < 2; fm++) {
        int m_lo = m0 + wm * 32 + fm * 16 + grp;
        int m_hi = m_lo + 8;
#pragma unroll
        for (int fn = 0; fn < 8; fn++) {
            int n = n0 + wn * 64 + fn * 8 + tig * 2;
#pragma unroll
            for (int e = 0; e < 2; e++) {
                int nn = n + e;
                if ((FLAGS & 4) && nn >= Vv) continue;
                float bv = bias[nn];
                float v0 = acc[fm][fn][e]     + bv;
                float v1 = acc[fm][fn][e + 2] + bv;
                if (FLAGS & 1) { v0 = fmaxf(v0, 0.f); v1 = fmaxf(v1, 0.f); }
                if (FLAGS & 2) {
                    v0 += C[(size_t)m_lo * ldc + nn];
                    v1 += C[(size_t)m_hi * ldc + nn];
                }
                if (FLAGS & 8) { v0 = to_tf32(v0); v1 = to_tf32(v1); }
                C[(size_t)m_lo * ldc + nn] = v0;
                C[(size_t)m_hi * ldc + nn] = v1;
            }
        }
    }
}

// ---------------- host launcher ---------------------------------------------
static float* symaddr(const void* s) {
    void* p = nullptr;
    cudaGetSymbolAddress(&p, s);
    return (float*)p;
}

constexpr int GEMM_SMEM = 65536;

extern "C" void kernel_launch(void* const* d_in, const int* in_sizes, int n_in,
                              void* d_out, int out_size) {
    const int*   x    = (const int*)d_in[0];
    const float* tok  = (const float*)d_in[1];
    const float* pos  = (const float*)d_in[2];
    const float* Wq   = (const float*)d_in[3];
    const float* bq   = (const float*)d_in[4];
    const float* Wk   = (const float*)d_in[5];
    const float* bk   = (const float*)d_in[6];
    const float* Wv   = (const float*)d_in[7];
    const float* bv   = (const float*)d_in[8];
    const float* Wo   = (const float*)d_in[9];
    const float* bo   = (const float*)d_in[10];
    const float* ln1g = (const float*)d_in[11];
    const float* ln1b = (const float*)d_in[12];
    const float* W1   = (const float*)d_in[13];
    const float* b1   = (const float*)d_in[14];
    const float* W2   = (const float*)d_in[15];
    const float* b2   = (const float*)d_in[16];
    const float* ln2g = (const float*)d_in[17];
    const float* ln2b = (const float*)d_in[18];
    const float* Wlm  = (const float*)d_in[19];
    const float* blm  = (const float*)d_in[20];
    float* out = (float*)d_out;

    float* ph    = symaddr(g_h);
    float* pa    = symaddr(g_a);
    float* pqkv  = symaddr(g_qkv);
    float* patt  = symaddr(g_att);
    float* pm    = symaddr(g_m);
    float* pS    = symaddr(g_S);
    float* pWqkvT = symaddr(g_WqkvT);
    float* pbqkv = symaddr(g_bqkv);
    float* pWoT  = symaddr(g_WoT);
    float* pW1T  = symaddr(g_W1T);
    float* pW2T  = symaddr(g_W2T);
    float* phtf  = symaddr(g_htf);
    float* pWlmT = symaddr(g_WlmT);

    static bool attr_done = false;
    if (!attr_done) {
        cudaFuncSetAttribute((const void*)mma_gemm_kernel<0>, cudaFuncAttributeMaxDynamicSharedMemorySize, GEMM_SMEM);
        cudaFuncSetAttribute((const void*)mma_gemm_kernel<2>, cudaFuncAttributeMaxDynamicSharedMemorySize, GEMM_SMEM);
        cudaFuncSetAttribute((const void*)mma_gemm_kernel<9>, cudaFuncAttributeMaxDynamicSharedMemorySize, GEMM_SMEM);
        cudaFuncSetAttribute((const void*)mma_gemm_kernel<4>, cudaFuncAttributeMaxDynamicSharedMemorySize, GEMM_SMEM);
        attr_done = true;
    }

    embed_kernel<<<(M_ROWS * Cc + 255) / 256, 256>>>(x, tok, pos, ph);

    int qkvt_total = NLl * QKV_P * Cc;
    repack_qkvT_kernel<<<(qkvt_total + 255) / 256, 256>>>(Wq, Wk, Wv, pWqkvT);
    repack_bqkv_kernel<<<(NLl * QKV_P + 255) / 256, 256>>>(bq, bk, bv, pbqkv);
    dim3 tg(Cc / 32, Cc / 32, NLl);
    transpose_w_kernel<<<tg, dim3(32, 8)>>>(Wo, pWoT);
    transpose_w_kernel<<<tg, dim3(32, 8)>>>(W1, pW1T);
    transpose_w_kernel<<<tg, dim3(32, 8)>>>(W2, pW2T);
    transpose_wlm_kernel<<<dim3(V_PAD / 32, Cc / 32), dim3(32, 8)>>>(Wlm, pWlmT);

    dim3 g_qkv_grid(M_ROWS / 128, QKV_P / 128);   // (16, 9)
    dim3 g_c_grid(M_ROWS / 128, Cc / 128);        // (16, 3)

    for (int l = 0; l < NLl; l++) {
        ln_kernel<<<M_ROWS, 128>>>(ph, ln1g + l * Cc, ln1b + l * Cc, pa);

        mma_gemm_kernel<0><<<g_qkv_grid, 256, GEMM_SMEM>>>(
            pa, pWqkvT + (size_t)l * QKV_P * Cc, pbqkv + l * QKV_P, pqkv, QKV_P);

        scores_kernel<<<dim3(Tt / 32, Tt / 32, BH), 256>>>(pqkv, pS);
        col_softmax_kernel<<<BH * Tt, 256>>>(pS);
        pv_kernel<<<dim3(Tt / 64, 1, BH), 256>>>(pS, pqkv, patt);

        mma_gemm_kernel<2><<<g_c_grid, 256, GEMM_SMEM>>>(
            patt, pWoT + (size_t)l * Cc * Cc, bo + l * Cc, ph, Cc);

        ln_kernel<<<M_ROWS, 128>>>(ph, ln2g + l * Cc, ln2b + l * Cc, pa);

        mma_gemm_kernel<9><<<g_c_grid, 256, GEMM_SMEM>>>(
            pa, pW1T + (size_t)l * Cc * Cc, b1 + l * Cc, pm, Cc);
        mma_gemm_kernel<2><<<g_c_grid, 256, GEMM_SMEM>>>(
            pm, pW2T + (size_t)l * Cc * Cc, b2 + l * Cc, ph, Cc);
    }

    // LM head
    cvt_h_kernel<<<(M_ROWS * Cc + 255) / 256, 256>>>(ph, phtf);
    mma_gemm_kernel<4><<<dim3(M_ROWS / 128, V_PAD / 128), 256, GEMM_SMEM>>>(
        phtf, pWlmT, blm, out, Vv);
}

// round 5
// speedup vs baseline: 4.5337x; 1.1446x over previous
#include <cuda_runtime.h>
#include <cuda_fp16.h>
#include <cstdint>

// Problem constants
constexpr int Vv = 50257, Cc = 384, Tt = 1024, Hh = 6, HSs = 64, NLl = 3, Bb = 2;
constexpr int M_ROWS = Bb * Tt;   // 2048
constexpr int BH = Bb * Hh;       // 12
constexpr int V_PAD = 50304;      // 393 * 128
constexpr int QKV_P = 3 * Cc;     // 1152

// ---------------- scratch (__device__ globals; no allocation allowed) --------
__device__ float g_h[M_ROWS * Cc];
__device__ float g_a[M_ROWS * Cc];
__device__ float g_qkv[M_ROWS * QKV_P];
__device__ float g_att[M_ROWS * Cc];
__device__ float g_m[M_ROWS * Cc];
__device__ float g_S[(size_t)BH * Tt * Tt];        // ST[bh][k][t]
__device__ float g_WqkvT[NLl * QKV_P * Cc];        // [l][n][k] tf32
__device__ float g_bqkv[NLl * QKV_P];
__device__ float g_WoT[NLl * Cc * Cc];
__device__ float g_W1T[NLl * Cc * Cc];
__device__ float g_W2T[NLl * Cc * Cc];
__device__ __half g_hH[M_ROWS * Cc];               // h as fp16
__device__ __half g_WlmH[(size_t)V_PAD * Cc];      // Wlm^T as fp16 [n][k]

// ---------------- tf32 helper ------------------------------------------------
__device__ __forceinline__ float to_tf32(float v) {
    uint32_t t;
    asm("cvt.rna.tf32.f32 %0, %1;" : "=r"(t) : "f"(v));
    return __uint_as_float(t);
}

// ---------------- embedding --------------------------------------------------
__global__ void embed_kernel(const int* __restrict__ x, const float* __restrict__ tok,
                             const float* __restrict__ pos, float* __restrict__ h) {
    int i = blockIdx.x * blockDim.x + threadIdx.x;
    if (i >= M_ROWS * Cc) return;
    int row = i / Cc, c = i % Cc;
    int t = row % Tt;
    h[i] = tok[(size_t)x[row] * Cc + c] + pos[t * Cc + c];
}

// ---------------- repacks (one-time per call) --------------------------------
__global__ void repack_qkvT_kernel(const float* __restrict__ Wq, const float* __restrict__ Wk,
                                   const float* __restrict__ Wv, float* __restrict__ O) {
    int i = blockIdx.x * blockDim.x + threadIdx.x;
    if (i >= NLl * QKV_P * Cc) return;
    int k = i % Cc;
    int n = (i / Cc) % QKV_P;
    int l = i / (Cc * QKV_P);
    int sel = n / Cc, h = (n % Cc) / HSs, s = n % HSs;
    const float* W = (sel == 0) ? Wq : (sel == 1) ? Wk : Wv;
    O[i] = to_tf32(W[(((size_t)l * Hh + h) * Cc + k) * HSs + s]);
}

__global__ void repack_bqkv_kernel(const float* __restrict__ bq, const float* __restrict__ bk,
                                   const float* __restrict__ bv, float* __restrict__ O) {
    int i = blockIdx.x * blockDim.x + threadIdx.x;
    if (i >= NLl * QKV_P) return;
    int n = i % QKV_P, l = i / QKV_P;
    int sel = n / Cc, h = (n % Cc) / HSs, s = n % HSs;
    const float* B = (sel == 0) ? bq : (sel == 1) ? bk : bv;
    O[i] = B[((size_t)l * Hh + h) * HSs + s];
}

__global__ void transpose_w_kernel(const float* __restrict__ W, float* __restrict__ WT) {
    __shared__ float t[32][33];
    int l = blockIdx.z;
    int n0 = blockIdx.x * 32, k0 = blockIdx.y * 32;
    const float* Wl = W + (size_t)l * Cc * Cc;
    float* Tl = WT + (size_t)l * Cc * Cc;
    for (int dy = threadIdx.y; dy < 32; dy += 8)
        t[dy][threadIdx.x] = Wl[(size_t)(k0 + dy) * Cc + n0 + threadIdx.x];
    __syncthreads();
    for (int dy = threadIdx.y; dy < 32; dy += 8)
        Tl[(size_t)(n0 + dy) * Cc + k0 + threadIdx.x] = to_tf32(t[threadIdx.x][dy]);
}

// Wlm (K=384 x V) -> WlmH (V_PAD x K) fp16, zero-padded rows
__global__ void transpose_wlm_kernel(const float* __restrict__ Wlm, __half* __restrict__ Bt) {
    __shared__ float tile[32][33];
    int n0 = blockIdx.x * 32, k0 = blockIdx.y * 32;
    for (int dy = threadIdx.y; dy < 32; dy += 8) {
        int k = k0 + dy, n = n0 + threadIdx.x;
        tile[dy][threadIdx.x] = (n < Vv) ? Wlm[(size_t)k * Vv + n] : 0.f;
    }
    __syncthreads();
    for (int dy = threadIdx.y; dy < 32; dy += 8) {
        int n = n0 + dy, k = k0 + threadIdx.x;
        Bt[(size_t)n * Cc + k] = __float2half(tile[threadIdx.x][dy]);
    }
}

// h -> fp16 copy (LM head A operand)
__global__ void cvt_h_kernel(const float* __restrict__ h, __half* __restrict__ o) {
    int i = blockIdx.x * blockDim.x + threadIdx.x;
    if (i < M_ROWS * Cc) o[i] = __float2half(h[i]);
}

// ---------------- layernorm (output tf32-rounded) ----------------------------
__global__ void ln_kernel(const float* __restrict__ x, const float* __restrict__ g,
                          const float* __restrict__ b, float* __restrict__ y) {
    int row = blockIdx.x;
    const float* xr = x + (size_t)row * Cc;
    float* yr = y + (size_t)row * Cc;
    float lsum = 0.f, lsq = 0.f;
    for (int c = threadIdx.x; c < Cc; c += blockDim.x) {
        float v = xr[c]; lsum += v; lsq += v * v;
    }
    __shared__ float sh[64];
    int lane = threadIdx.x & 31, wid = threadIdx.x >> 5;
#pragma unroll
    for (int o = 16; o; o >>= 1) {
        lsum += __shfl_xor_sync(0xffffffffu, lsum, o);
        lsq  += __shfl_xor_sync(0xffffffffu, lsq,  o);
    }
    if (lane == 0) { sh[wid] = lsum; sh[wid + 32] = lsq; }
    __syncthreads();
    int nw = blockDim.x >> 5;
    if (threadIdx.x == 0) {
        float s = 0.f, q = 0.f;
        for (int w = 0; w < nw; w++) { s += sh[w]; q += sh[w + 32]; }
        sh[0] = s; sh[32] = q;
    }
    __syncthreads();
    float mu = sh[0] / Cc;
    float var = sh[32] / Cc - mu * mu;
    float rstd = rsqrtf(var + 1e-5f);
    for (int c = threadIdx.x; c < Cc; c += blockDim.x)
        yr[c] = to_tf32((xr[c] - mu) * rstd * g[c] + b[c]);
}

// ---------------- attention scores (from fused qkv), stored ST[k][t] ---------
__global__ __launch_bounds__(256)
void scores_kernel(const float* __restrict__ qkv, float* __restrict__ S) {
    int tb = blockIdx.x, kb = blockIdx.y, bh = blockIdx.z;
    if (tb < kb) return;
    int b = bh / Hh, h = bh % Hh;
    int t0 = tb * 32, k0 = kb * 32;
    __shared__ float Qs[32][65], Ks[32][65];
    for (int i = threadIdx.x; i < 32 * 64; i += 256) {
        int r = i >> 6, s = i & 63;
        Qs[r][s] = qkv[((size_t)(b * Tt + t0 + r)) * QKV_P + h * HSs + s];
        Ks[r][s] = qkv[((size_t)(b * Tt + k0 + r)) * QKV_P + Cc + h * HSs + s];
    }
    __syncthreads();
    int kl = (threadIdx.x >> 4) * 2;
    int tl = (threadIdx.x & 15) * 2;
    float a00 = 0.f, a01 = 0.f, a10 = 0.f, a11 = 0.f;
#pragma unroll
    for (int s = 0; s < 64; s++) {
        float kv0 = Ks[kl][s], kv1 = Ks[kl + 1][s];
        float qv0 = Qs[tl][s], qv1 = Qs[tl + 1][s];
        a00 += kv0 * qv0; a01 += kv0 * qv1;
        a10 += kv1 * qv0; a11 += kv1 * qv1;
    }
    const float scale = 0.125f;
    float* Sp = S + (size_t)bh * Tt * Tt;
    Sp[(size_t)(k0 + kl) * Tt + t0 + tl]         = a00 * scale;
    Sp[(size_t)(k0 + kl) * Tt + t0 + tl + 1]     = a01 * scale;
    Sp[(size_t)(k0 + kl + 1) * Tt + t0 + tl]     = a10 * scale;
    Sp[(size_t)(k0 + kl + 1) * Tt + t0 + tl + 1] = a11 * scale;
}

// ---------------- query-axis softmax = row softmax of ST ---------------------
__global__ __launch_bounds__(256)
void col_softmax_kernel(float* __restrict__ S) {
    int row = blockIdx.x;
    int k = row % Tt;
    float* r = S + (size_t)row * Tt;
    __shared__ float sh[32];
    int lane = threadIdx.x & 31, wid = threadIdx.x >> 5;

    float mx = -1e30f;
    for (int t = k + threadIdx.x; t < Tt; t += 256) mx = fmaxf(mx, r[t]);
#pragma unroll
    for (int o = 16; o; o >>= 1) mx = fmaxf(mx, __shfl_xor_sync(0xffffffffu, mx, o));
    if (lane == 0) sh[wid] = mx;
    __syncthreads();
    if (threadIdx.x == 0) {
        float m = sh[0];
        for (int w = 1; w < 8; w++) m = fmaxf(m, sh[w]);
        sh[0] = m;
    }
    __syncthreads();
    mx = sh[0];
    __syncthreads();

    float sum = 0.f;
    for (int t = k + threadIdx.x; t < Tt; t += 256) sum += __expf(r[t] - mx);
#pragma unroll
    for (int o = 16; o; o >>= 1) sum += __shfl_xor_sync(0xffffffffu, sum, o);
    if (lane == 0) sh[wid] = sum;
    __syncthreads();
    if (threadIdx.x == 0) {
        float s = 0.f;
        for (int w = 0; w < 8; w++) s += sh[w];
        sh[0] = s;
    }
    __syncthreads();
    float inv = 1.f / sh[0];
    for (int t = threadIdx.x; t < Tt; t += 256)
        r[t] = (t >= k) ? __expf(r[t] - mx) * inv : 0.f;
}

// ---------------- PV: att[t,s] = sum_k ST[k][t] * v[k,s] (tf32-rounded out) --
__global__ __launch_bounds__(256)
void pv_kernel(const float* __restrict__ S, const float* __restrict__ qkv,
               float* __restrict__ att) {
    int tb = blockIdx.x, bh = blockIdx.z;
    int b = bh / Hh, h = bh % Hh;
    int t0 = tb * 64;
    __shared__ float Ss[16][65], Vs[16][65];
    int tr = threadIdx.x >> 4, tc = threadIdx.x & 15;
    float acc[4][4];
#pragma unroll
    for (int i = 0; i < 4; i++)
#pragma unroll
        for (int j = 0; j < 4; j++) acc[i][j] = 0.f;

    const float* Sp = S + (size_t)bh * Tt * Tt;
    int kmax = t0 + 64;
    for (int k0 = 0; k0 < kmax; k0 += 16) {
        for (int i = threadIdx.x; i < 16 * 64; i += 256) {
            int kk = i >> 6, c = i & 63;
            Ss[kk][c] = Sp[(size_t)(k0 + kk) * Tt + t0 + c];
            Vs[kk][c] = qkv[((size_t)(b * Tt + k0 + kk)) * QKV_P + 2 * Cc + h * HSs + c];
        }
        __syncthreads();
#pragma unroll
        for (int kk = 0; kk < 16; kk++) {
            float a[4], bb[4];
#pragma unroll
            for (int i = 0; i < 4; i++) a[i] = Ss[kk][tr * 4 + i];
#pragma unroll
            for (int j = 0; j < 4; j++) bb[j] = Vs[kk][tc * 4 + j];
#pragma unroll
            for (int i = 0; i < 4; i++)
#pragma unroll
                for (int j = 0; j < 4; j++)
                    acc[i][j] += a[i] * bb[j];
        }
        __syncthreads();
    }
#pragma unroll
    for (int i = 0; i < 4; i++)
#pragma unroll
        for (int j = 0; j < 4; j++)
            att[((size_t)(b * Tt + t0 + tr * 4 + i)) * Cc + h * HSs + tc * 4 + j] =
                to_tf32(acc[i][j]);
}

// ---------------- common asm helpers ----------------------------------------
__device__ __forceinline__ uint32_t smem_u32(const void* p) {
    uint32_t a;
    asm("{ .reg .u64 t; cvta.to.shared.u64 t, %1; cvt.u32.u64 %0, t; }" : "=r"(a) : "l"(p));
    return a;
}
__device__ __forceinline__ void cp_async16(uint32_t saddr, const void* g) {
    asm volatile("cp.async.cg.shared.global [%0], [%1], 16;" :: "r"(saddr), "l"(g) : "memory");
}
__device__ __forceinline__ void cp_commit() {
    asm volatile("cp.async.commit_group;" ::: "memory");
}
template<int N>
__device__ __forceinline__ void cp_wait() {
    asm volatile("cp.async.wait_group %0;" :: "n"(N) : "memory");
}

// ================= unified tf32 mma.sync GEMM (layer GEMMs) ==================
__device__ __forceinline__ void mma_tf32(float* c, const float* a, const float* b) {
    const uint32_t* A = reinterpret_cast<const uint32_t*>(a);
    const uint32_t* B = reinterpret_cast<const uint32_t*>(b);
    asm volatile(
        "mma.sync.aligned.m16n8k8.row.col.f32.tf32.tf32.f32 "
        "{%0,%1,%2,%3}, {%4,%5,%6,%7}, {%8,%9}, {%0,%1,%2,%3};"
        : "+f"(c[0]), "+f"(c[1]), "+f"(c[2]), "+f"(c[3])
        : "r"(A[0]), "r"(A[1]), "r"(A[2]), "r"(A[3]), "r"(B[0]), "r"(B[1]));
}
__device__ __forceinline__ int swz(int r, int g, int sub) {
    return r * 32 + (((g ^ (r & 7)) << 2)) + sub;
}

constexpr int NKT = Cc / 32;  // 12

template<int FLAGS>   // 1=relu, 2=accumulate, 8=round tf32
__global__ __launch_bounds__(256)
void mma_gemm_kernel(const float* __restrict__ A, const float* __restrict__ Bt,
                     const float* __restrict__ bias, float* __restrict__ C,
                     int ldc) {
    extern __shared__ float sm[];
    int tid = threadIdx.x;
    int warp = tid >> 5, lane = tid & 31;
    int wm = warp & 3, wn = warp >> 2;
    int grp = lane >> 2, tig = lane & 3;
    int m0 = blockIdx.x * 128, n0 = blockIdx.y * 128;
    const float* Ab = A + (size_t)m0 * Cc;
    const float* Bb = Bt + (size_t)n0 * Cc;

    uint32_t sbase = smem_u32(sm);

    auto issue = [&](int kt, int stage) {
        uint32_t as = sbase + stage * 32768u;
        uint32_t bs = as + 16384u;
#pragma unroll
        for (int it = 0; it < 4; it++) {
            int slot = tid + it * 256;
            int r = slot >> 3, c4 = slot & 7;
            uint32_t so = (uint32_t)((r * 32 + ((c4 ^ (r & 7)) << 2)) * 4);
            cp_async16(as + so, Ab + (size_t)r * Cc + kt * 32 + c4 * 4);
            cp_async16(bs + so, Bb + (size_t)r * Cc + kt * 32 + c4 * 4);
        }
    };

    float acc[2][8][4];
#pragma unroll
    for (int i = 0; i < 2; i++)
#pragma unroll
        for (int j = 0; j < 8; j++)
#pragma unroll
            for (int q = 0; q < 4; q++) acc[i][j][q] = 0.f;

    issue(0, 0);
    cp_commit();

#pragma unroll 1
    for (int kt = 0; kt < NKT; kt++) {
        if (kt + 1 < NKT) {
            issue(kt + 1, (kt + 1) & 1);
            cp_commit();
            cp_wait<1>();
        } else {
            cp_wait<0>();
        }
        __syncthreads();
        const float* As = sm + (kt & 1) * 8192;
        const float* Bs = As + 4096;
#pragma unroll
        for (int k8 = 0; k8 < 4; k8++) {
            int g0 = k8 * 2;
            float a[2][4];
#pragma unroll
            for (int fm = 0; fm < 2; fm++) {
                int m = wm * 32 + fm * 16;
                a[fm][0] = As[swz(m + grp,     g0,     tig)];
                a[fm][1] = As[swz(m + grp + 8, g0,     tig)];
                a[fm][2] = As[swz(m + grp,     g0 + 1, tig)];
                a[fm][3] = As[swz(m + grp + 8, g0 + 1, tig)];
            }
            float b[8][2];
#pragma unroll
            for (int fn = 0; fn < 8; fn++) {
                int n = wn * 64 + fn * 8;
                b[fn][0] = Bs[swz(n + grp, g0,     tig)];
                b[fn][1] = Bs[swz(n + grp, g0 + 1, tig)];
            }
#pragma unroll
            for (int fm = 0; fm < 2; fm++)
#pragma unroll
                for (int fn = 0; fn < 8; fn++)
                    mma_tf32(acc[fm][fn], a[fm], b[fn]);
        }
        __syncthreads();
    }

#pragma unroll
    for (int fm = 0; fm < 2; fm++) {
        int m_lo = m0 + wm * 32 + fm * 16 + grp;
        int m_hi = m_lo + 8;
#pragma unroll
        for (int fn = 0; fn < 8; fn++) {
            int n = n0 + wn * 64 + fn * 8 + tig * 2;
#pragma unroll
            for (int e = 0; e < 2; e++) {
                int nn = n + e;
                float bv = bias[nn];
                float v0 = acc[fm][fn][e]     + bv;
                float v1 = acc[fm][fn][e + 2] + bv;
                if (FLAGS & 1) { v0 = fmaxf(v0, 0.f); v1 = fmaxf(v1, 0.f); }
                if (FLAGS & 2) {
                    v0 += C[(size_t)m_lo * ldc + nn];
                    v1 += C[(size_t)m_hi * ldc + nn];
                }
                if (FLAGS & 8) { v0 = to_tf32(v0); v1 = to_tf32(v1); }
                C[(size_t)m_lo * ldc + nn] = v0;
                C[(size_t)m_hi * ldc + nn] = v1;
            }
        }
    }
}

// ================= fp16 LM head: m16n8k16 + ldmatrix + cp.async ==============
// out[2048,50257] = A[2048,384](fp16) @ Bt[V_PAD,384](fp16)^T + bias, fp32 acc.
// CTA 128x128, K-tile 64 halfs (128B swizzled rows), 2-stage pipeline.

__device__ __forceinline__ void ldm_x4(uint32_t* r, uint32_t addr) {
    asm volatile("ldmatrix.sync.aligned.m8n8.x4.shared.b16 {%0,%1,%2,%3}, [%4];"
                 : "=r"(r[0]), "=r"(r[1]), "=r"(r[2]), "=r"(r[3]) : "r"(addr));
}
__device__ __forceinline__ void mma_f16(float* c, const uint32_t* a, const uint32_t* b) {
    asm volatile(
        "mma.sync.aligned.m16n8k16.row.col.f32.f16.f16.f32 "
        "{%0,%1,%2,%3}, {%4,%5,%6,%7}, {%8,%9}, {%0,%1,%2,%3};"
        : "+f"(c[0]), "+f"(c[1]), "+f"(c[2]), "+f"(c[3])
        : "r"(a[0]), "r"(a[1]), "r"(a[2]), "r"(a[3]), "r"(b[0]), "r"(b[1]));
}

constexpr int LM_NKT = Cc / 64;  // 6

__global__ __launch_bounds__(256)
void lmhead_fp16_kernel(const __half* __restrict__ A, const __half* __restrict__ Bt,
                        const float* __restrict__ bias, float* __restrict__ out) {
    extern __shared__ __half smh[];  // 2 stages x (A 8192 + B 8192 halfs) = 64KB
    int tid = threadIdx.x;
    int warp = tid >> 5, lane = tid & 31;
    int wm = warp & 3, wn = warp >> 2;
    int grp = lane >> 2, tig = lane & 3;
    int lr = lane & 7, sub = lane >> 3;
    int m0 = blockIdx.x * 128, n0 = blockIdx.y * 128;
    const __half* Ab = A + (size_t)m0 * Cc;
    const __half* Bb = Bt + (size_t)n0 * Cc;

    uint32_t sbase = smem_u32(smh);

    auto issue = [&](int kt, int stage) {
        uint32_t as = sbase + stage * 32768u;   // bytes
        uint32_t bs = as + 16384u;
#pragma unroll
        for (int it = 0; it < 4; it++) {
            int slot = tid + it * 256;          // 1024 chunks per operand
            int r = slot >> 3, c = slot & 7;
            uint32_t so = (uint32_t)(r * 128 + ((c ^ (r & 7)) << 4));
            cp_async16(as + so, Ab + (size_t)r * Cc + kt * 64 + c * 8);
            cp_async16(bs + so, Bb + (size_t)r * Cc + kt * 64 + c * 8);
        }
    };

    float acc[2][8][4];
#pragma unroll
    for (int i = 0; i < 2; i++)
#pragma unroll
        for (int j = 0; j < 8; j++)
#pragma unroll
            for (int q = 0; q < 4; q++) acc[i][j][q] = 0.f;

    // per-thread ldmatrix row/col components (constant across kt)
    int rowA[2], rowB[4];
#pragma unroll
    for (int fm = 0; fm < 2; fm++) rowA[fm] = wm * 32 + fm * 16 + (sub & 1) * 8 + lr;
#pragma unroll
    for (int p = 0; p < 4; p++) rowB[p] = wn * 64 + p * 16 + (sub >> 1) * 8 + lr;
    int chA = sub >> 1;   // chunk offset within k16 for A
    int chB = sub & 1;    // for B

    issue(0, 0);
    cp_commit();

#pragma unroll 1
    for (int kt = 0; kt < LM_NKT; kt++) {
        if (kt + 1 < LM_NKT) {
            issue(kt + 1, (kt + 1) & 1);
            cp_commit();
            cp_wait<1>();
        } else {
            cp_wait<0>();
        }
        __syncthreads();
        uint32_t as = sbase + (kt & 1) * 32768u;
        uint32_t bs = as + 16384u;
#pragma unroll
        for (int k16 = 0; k16 < 4; k16++) {
            int cb = k16 * 2;  // base 16B-chunk of this k16 within 8-chunk row
            uint32_t afr[2][4];
#pragma unroll
            for (int fm = 0; fm < 2; fm++) {
                int r = rowA[fm];
                uint32_t addr = as + r * 128 + (((cb + chA) ^ (r & 7)) << 4);
                ldm_x4(afr[fm], addr);
            }
            uint32_t bfr[4][4];
#pragma unroll
            for (int p = 0; p < 4; p++) {
                int r = rowB[p];
                uint32_t addr = bs + r * 128 + (((cb + chB) ^ (r & 7)) << 4);
                ldm_x4(bfr[p], addr);
            }
#pragma unroll
            for (int fm = 0; fm < 2; fm++)
#pragma unroll
                for (int fn = 0; fn < 8; fn++)
                    mma_f16(acc[fm][fn], afr[fm], &bfr[fn >> 1][(fn & 1) * 2]);
        }
        __syncthreads();
    }

    // epilogue (col-guarded against Vv)
#pragma unroll
    for (int fm = 0; fm < 2; fm++) {
        int m_lo = m0 + wm * 32 + fm * 16 + grp;
        int m_hi = m_lo + 8;
#pragma unroll
        for (int fn = 0; fn < 8; fn++) {
            int n = n0 + wn * 64 + fn * 8 + tig * 2;
#pragma unroll
            for (int e = 0; e < 2; e++) {
                int nn = n + e;
                if (nn >= Vv) continue;
                float bv = bias[nn];
                out[(size_t)m_lo * Vv + nn] = acc[fm][fn][e]     + bv;
                out[(size_t)m_hi * Vv + nn] = acc[fm][fn][e + 2] + bv;
            }
        }
    }
}

// ---------------- host launcher ---------------------------------------------
static float* symaddr(const void* s) {
    void* p = nullptr;
    cudaGetSymbolAddress(&p, s);
    return (float*)p;
}

constexpr int GEMM_SMEM = 65536;

extern "C" void kernel_launch(void* const* d_in, const int* in_sizes, int n_in,
                              void* d_out, int out_size) {
    const int*   x    = (const int*)d_in[0];
    const float* tok  = (const float*)d_in[1];
    const float* pos  = (const float*)d_in[2];
    const float* Wq   = (const float*)d_in[3];
    const float* bq   = (const float*)d_in[4];
    const float* Wk   = (const float*)d_in[5];
    const float* bk   = (const float*)d_in[6];
    const float* Wv   = (const float*)d_in[7];
    const float* bv   = (const float*)d_in[8];
    const float* Wo   = (const float*)d_in[9];
    const float* bo   = (const float*)d_in[10];
    const float* ln1g = (const float*)d_in[11];
    const float* ln1b = (const float*)d_in[12];
    const float* W1   = (const float*)d_in[13];
    const float* b1   = (const float*)d_in[14];
    const float* W2   = (const float*)d_in[15];
    const float* b2   = (const float*)d_in[16];
    const float* ln2g = (const float*)d_in[17];
    const float* ln2b = (const float*)d_in[18];
    const float* Wlm  = (const float*)d_in[19];
    const float* blm  = (const float*)d_in[20];
    float* out = (float*)d_out;

    float* ph     = symaddr(g_h);
    float* pa     = symaddr(g_a);
    float* pqkv   = symaddr(g_qkv);
    float* patt   = symaddr(g_att);
    float* pm     = symaddr(g_m);
    float* pS     = symaddr(g_S);
    float* pWqkvT = symaddr(g_WqkvT);
    float* pbqkv  = symaddr(g_bqkv);
    float* pWoT   = symaddr(g_WoT);
    float* pW1T   = symaddr(g_W1T);
    float* pW2T   = symaddr(g_W2T);
    __half* phH   = (__half*)symaddr(g_hH);
    __half* pWlmH = (__half*)symaddr(g_WlmH);

    static bool attr_done = false;
    if (!attr_done) {
        cudaFuncSetAttribute((const void*)mma_gemm_kernel<0>, cudaFuncAttributeMaxDynamicSharedMemorySize, GEMM_SMEM);
        cudaFuncSetAttribute((const void*)mma_gemm_kernel<2>, cudaFuncAttributeMaxDynamicSharedMemorySize, GEMM_SMEM);
        cudaFuncSetAttribute((const void*)mma_gemm_kernel<9>, cudaFuncAttributeMaxDynamicSharedMemorySize, GEMM_SMEM);
        cudaFuncSetAttribute((const void*)lmhead_fp16_kernel, cudaFuncAttributeMaxDynamicSharedMemorySize, GEMM_SMEM);
        attr_done = true;
    }

    embed_kernel<<<(M_ROWS * Cc + 255) / 256, 256>>>(x, tok, pos, ph);

    int qkvt_total = NLl * QKV_P * Cc;
    repack_qkvT_kernel<<<(qkvt_total + 255) / 256, 256>>>(Wq, Wk, Wv, pWqkvT);
    repack_bqkv_kernel<<<(NLl * QKV_P + 255) / 256, 256>>>(bq, bk, bv, pbqkv);
    dim3 tg(Cc / 32, Cc / 32, NLl);
    transpose_w_kernel<<<tg, dim3(32, 8)>>>(Wo, pWoT);
    transpose_w_kernel<<<tg, dim3(32, 8)>>>(W1, pW1T);
    transpose_w_kernel<<<tg, dim3(32, 8)>>>(W2, pW2T);
    transpose_wlm_kernel<<<dim3(V_PAD / 32, Cc / 32), dim3(32, 8)>>>(Wlm, pWlmH);

    dim3 g_qkv_grid(M_ROWS / 128, QKV_P / 128);   // (16, 9)
    dim3 g_c_grid(M_ROWS / 128, Cc / 128);        // (16, 3)

    for (int l = 0; l < NLl; l++) {
        ln_kernel<<<M_ROWS, 128>>>(ph, ln1g + l * Cc, ln1b + l * Cc, pa);

        mma_gemm_kernel<0><<<g_qkv_grid, 256, GEMM_SMEM>>>(
            pa, pWqkvT + (size_t)l * QKV_P * Cc, pbqkv + l * QKV_P, pqkv, QKV_P);

        scores_kernel<<<dim3(Tt / 32, Tt / 32, BH), 256>>>(pqkv, pS);
        col_softmax_kernel<<<BH * Tt, 256>>>(pS);
        pv_kernel<<<dim3(Tt / 64, 1, BH), 256>>>(pS, pqkv, patt);

        mma_gemm_kernel<2><<<g_c_grid, 256, GEMM_SMEM>>>(
            patt, pWoT + (size_t)l * Cc * Cc, bo + l * Cc, ph, Cc);

        ln_kernel<<<M_ROWS, 128>>>(ph, ln2g + l * Cc, ln2b + l * Cc, pa);

        mma_gemm_kernel<9><<<g_c_grid, 256, GEMM_SMEM>>>(
            pa, pW1T + (size_t)l * Cc * Cc, b1 + l * Cc, pm, Cc);
        mma_gemm_kernel<2><<<g_c_grid, 256, GEMM_SMEM>>>(
            pm, pW2T + (size_t)l * Cc * Cc, b2 + l * Cc, ph, Cc);
    }

    // LM head (fp16 tensor cores)
    cvt_h_kernel<<<(M_ROWS * Cc + 255) / 256, 256>>>(ph, phH);
    lmhead_fp16_kernel<<<dim3(M_ROWS / 128, V_PAD / 128), 256, GEMM_SMEM>>>(
        phH, pWlmH, blm, out);
}

// round 6
// speedup vs baseline: 6.6397x; 1.4645x over previous
#include <cuda_runtime.h>
#include <cuda_fp16.h>
#include <cstdint>

// Problem constants
constexpr int Vv = 50257, Cc = 384, Tt = 1024, Hh = 6, HSs = 64, NLl = 3, Bb = 2;
constexpr int M_ROWS = Bb * Tt;   // 2048
constexpr int BH = Bb * Hh;       // 12
constexpr int V_PAD = 50304;      // 393 * 128
constexpr int QKV_P = 3 * Cc;     // 1152

// ---------------- scratch (__device__ globals; no allocation allowed) --------
__device__ float g_h[M_ROWS * Cc];
__device__ float g_a[M_ROWS * Cc];
__device__ __half g_qkvH[M_ROWS * QKV_P];          // fused QKV, fp16
__device__ float g_att[M_ROWS * Cc];
__device__ float g_m[M_ROWS * Cc];
__device__ __half g_P[(size_t)BH * Tt * Tt];       // unnormalized probs [bh][k][t]
__device__ float g_psum[BH * 8 * Tt];              // per-(bh,tb) row partial sums
__device__ float g_inv[BH * Tt];                   // 1/rowsum
__device__ float g_WqkvT[NLl * QKV_P * Cc];        // [l][n][k] tf32
__device__ float g_bqkv[NLl * QKV_P];
__device__ float g_WoT[NLl * Cc * Cc];
__device__ float g_W1T[NLl * Cc * Cc];
__device__ float g_W2T[NLl * Cc * Cc];
__device__ __half g_hH[M_ROWS * Cc];               // h as fp16
__device__ __half g_WlmH[(size_t)V_PAD * Cc];      // Wlm^T as fp16 [n][k]

// ---------------- tf32 helper ------------------------------------------------
__device__ __forceinline__ float to_tf32(float v) {
    uint32_t t;
    asm("cvt.rna.tf32.f32 %0, %1;" : "=r"(t) : "f"(v));
    return __uint_as_float(t);
}

// ---------------- embedding --------------------------------------------------
__global__ void embed_kernel(const int* __restrict__ x, const float* __restrict__ tok,
                             const float* __restrict__ pos, float* __restrict__ h) {
    int i = blockIdx.x * blockDim.x + threadIdx.x;
    if (i >= M_ROWS * Cc) return;
    int row = i / Cc, c = i % Cc;
    int t = row % Tt;
    h[i] = tok[(size_t)x[row] * Cc + c] + pos[t * Cc + c];
}

// ---------------- repacks (one-time per call) --------------------------------
__global__ void repack_qkvT_kernel(const float* __restrict__ Wq, const float* __restrict__ Wk,
                                   const float* __restrict__ Wv, float* __restrict__ O) {
    int i = blockIdx.x * blockDim.x + threadIdx.x;
    if (i >= NLl * QKV_P * Cc) return;
    int k = i % Cc;
    int n = (i / Cc) % QKV_P;
    int l = i / (Cc * QKV_P);
    int sel = n / Cc, h = (n % Cc) / HSs, s = n % HSs;
    const float* W = (sel == 0) ? Wq : (sel == 1) ? Wk : Wv;
    O[i] = to_tf32(W[(((size_t)l * Hh + h) * Cc + k) * HSs + s]);
}

__global__ void repack_bqkv_kernel(const float* __restrict__ bq, const float* __restrict__ bk,
                                   const float* __restrict__ bv, float* __restrict__ O) {
    int i = blockIdx.x * blockDim.x + threadIdx.x;
    if (i >= NLl * QKV_P) return;
    int n = i % QKV_P, l = i / QKV_P;
    int sel = n / Cc, h = (n % Cc) / HSs, s = n % HSs;
    const float* B = (sel == 0) ? bq : (sel == 1) ? bk : bv;
    O[i] = B[((size_t)l * Hh + h) * HSs + s];
}

__global__ void transpose_w_kernel(const float* __restrict__ W, float* __restrict__ WT) {
    __shared__ float t[32][33];
    int l = blockIdx.z;
    int n0 = blockIdx.x * 32, k0 = blockIdx.y * 32;
    const float* Wl = W + (size_t)l * Cc * Cc;
    float* Tl = WT + (size_t)l * Cc * Cc;
    for (int dy = threadIdx.y; dy < 32; dy += 8)
        t[dy][threadIdx.x] = Wl[(size_t)(k0 + dy) * Cc + n0 + threadIdx.x];
    __syncthreads();
    for (int dy = threadIdx.y; dy < 32; dy += 8)
        Tl[(size_t)(n0 + dy) * Cc + k0 + threadIdx.x] = to_tf32(t[threadIdx.x][dy]);
}

__global__ void transpose_wlm_kernel(const float* __restrict__ Wlm, __half* __restrict__ Bt) {
    __shared__ float tile[32][33];
    int n0 = blockIdx.x * 32, k0 = blockIdx.y * 32;
    for (int dy = threadIdx.y; dy < 32; dy += 8) {
        int k = k0 + dy, n = n0 + threadIdx.x;
        tile[dy][threadIdx.x] = (n < Vv) ? Wlm[(size_t)k * Vv + n] : 0.f;
    }
    __syncthreads();
    for (int dy = threadIdx.y; dy < 32; dy += 8) {
        int n = n0 + dy, k = k0 + threadIdx.x;
        Bt[(size_t)n * Cc + k] = __float2half(tile[threadIdx.x][dy]);
    }
}

__global__ void cvt_h_kernel(const float* __restrict__ h, __half* __restrict__ o) {
    int i = blockIdx.x * blockDim.x + threadIdx.x;
    if (i < M_ROWS * Cc) o[i] = __float2half(h[i]);
}

// ---------------- layernorm (output tf32-rounded) ----------------------------
__global__ void ln_kernel(const float* __restrict__ x, const float* __restrict__ g,
                          const float* __restrict__ b, float* __restrict__ y) {
    int row = blockIdx.x;
    const float* xr = x + (size_t)row * Cc;
    float* yr = y + (size_t)row * Cc;
    float lsum = 0.f, lsq = 0.f;
    for (int c = threadIdx.x; c < Cc; c += blockDim.x) {
        float v = xr[c]; lsum += v; lsq += v * v;
    }
    __shared__ float sh[64];
    int lane = threadIdx.x & 31, wid = threadIdx.x >> 5;
#pragma unroll
    for (int o = 16; o; o >>= 1) {
        lsum += __shfl_xor_sync(0xffffffffu, lsum, o);
        lsq  += __shfl_xor_sync(0xffffffffu, lsq,  o);
    }
    if (lane == 0) { sh[wid] = lsum; sh[wid + 32] = lsq; }
    __syncthreads();
    int nw = blockDim.x >> 5;
    if (threadIdx.x == 0) {
        float s = 0.f, q = 0.f;
        for (int w = 0; w < nw; w++) { s += sh[w]; q += sh[w + 32]; }
        sh[0] = s; sh[32] = q;
    }
    __syncthreads();
    float mu = sh[0] / Cc;
    float var = sh[32] / Cc - mu * mu;
    float rstd = rsqrtf(var + 1e-5f);
    for (int c = threadIdx.x; c < Cc; c += blockDim.x)
        yr[c] = to_tf32((xr[c] - mu) * rstd * g[c] + b[c]);
}

// ---------------- common asm helpers ----------------------------------------
__device__ __forceinline__ uint32_t smem_u32(const void* p) {
    uint32_t a;
    asm("{ .reg .u64 t; cvta.to.shared.u64 t, %1; cvt.u32.u64 %0, t; }" : "=r"(a) : "l"(p));
    return a;
}
__device__ __forceinline__ void cp_async16(uint32_t saddr, const void* g) {
    asm volatile("cp.async.cg.shared.global [%0], [%1], 16;" :: "r"(saddr), "l"(g) : "memory");
}
__device__ __forceinline__ void cp_commit() {
    asm volatile("cp.async.commit_group;" ::: "memory");
}
template<int N>
__device__ __forceinline__ void cp_wait() {
    asm volatile("cp.async.wait_group %0;" :: "n"(N) : "memory");
}
__device__ __forceinline__ void ldm_x4(uint32_t* r, uint32_t addr) {
    asm volatile("ldmatrix.sync.aligned.m8n8.x4.shared.b16 {%0,%1,%2,%3}, [%4];"
                 : "=r"(r[0]), "=r"(r[1]), "=r"(r[2]), "=r"(r[3]) : "r"(addr));
}
__device__ __forceinline__ void mma_f16(float* c, const uint32_t* a, const uint32_t* b) {
    asm volatile(
        "mma.sync.aligned.m16n8k16.row.col.f32.f16.f16.f32 "
        "{%0,%1,%2,%3}, {%4,%5,%6,%7}, {%8,%9}, {%0,%1,%2,%3};"
        : "+f"(c[0]), "+f"(c[1]), "+f"(c[2]), "+f"(c[3])
        : "r"(a[0]), "r"(a[1]), "r"(a[2]), "r"(a[3]), "r"(b[0]), "r"(b[1]));
}

// ================= unified tf32 mma.sync GEMM (layer GEMMs) ==================
__device__ __forceinline__ void mma_tf32(float* c, const float* a, const float* b) {
    const uint32_t* A = reinterpret_cast<const uint32_t*>(a);
    const uint32_t* B = reinterpret_cast<const uint32_t*>(b);
    asm volatile(
        "mma.sync.aligned.m16n8k8.row.col.f32.tf32.tf32.f32 "
        "{%0,%1,%2,%3}, {%4,%5,%6,%7}, {%8,%9}, {%0,%1,%2,%3};"
        : "+f"(c[0]), "+f"(c[1]), "+f"(c[2]), "+f"(c[3])
        : "r"(A[0]), "r"(A[1]), "r"(A[2]), "r"(A[3]), "r"(B[0]), "r"(B[1]));
}
__device__ __forceinline__ int swz(int r, int g, int sub) {
    return r * 32 + (((g ^ (r & 7)) << 2)) + sub;
}

constexpr int NKT = Cc / 32;  // 12

template<int FLAGS, typename OutT>   // 1=relu, 2=accumulate, 8=round tf32
__global__ __launch_bounds__(256)
void mma_gemm_kernel(const float* __restrict__ A, const float* __restrict__ Bt,
                     const float* __restrict__ bias, OutT* __restrict__ C,
                     int ldc) {
    extern __shared__ float sm[];
    int tid = threadIdx.x;
    int warp = tid >> 5, lane = tid & 31;
    int wm = warp & 3, wn = warp >> 2;
    int grp = lane >> 2, tig = lane & 3;
    int m0 = blockIdx.x * 128, n0 = blockIdx.y * 128;
    const float* Ab = A + (size_t)m0 * Cc;
    const float* Bb = Bt + (size_t)n0 * Cc;

    uint32_t sbase = smem_u32(sm);

    auto issue = [&](int kt, int stage) {
        uint32_t as = sbase + stage * 32768u;
        uint32_t bs = as + 16384u;
#pragma unroll
        for (int it = 0; it < 4; it++) {
            int slot = tid + it * 256;
            int r = slot >> 3, c4 = slot & 7;
            uint32_t so = (uint32_t)((r * 32 + ((c4 ^ (r & 7)) << 2)) * 4);
            cp_async16(as + so, Ab + (size_t)r * Cc + kt * 32 + c4 * 4);
            cp_async16(bs + so, Bb + (size_t)r * Cc + kt * 32 + c4 * 4);
        }
    };

    float acc[2][8][4];
#pragma unroll
    for (int i = 0; i < 2; i++)
#pragma unroll
        for (int j = 0; j < 8; j++)
#pragma unroll
            for (int q = 0; q < 4; q++) acc[i][j][q] = 0.f;

    issue(0, 0);
    cp_commit();

#pragma unroll 1
    for (int kt = 0; kt < NKT; kt++) {
        if (kt + 1 < NKT) {
            issue(kt + 1, (kt + 1) & 1);
            cp_commit();
            cp_wait<1>();
        } else {
            cp_wait<0>();
        }
        __syncthreads();
        const float* As = sm + (kt & 1) * 8192;
        const float* Bs = As + 4096;
#pragma unroll
        for (int k8 = 0; k8 < 4; k8++) {
            int g0 = k8 * 2;
            float a[2][4];
#pragma unroll
            for (int fm = 0; fm < 2; fm++) {
                int m = wm * 32 + fm * 16;
                a[fm][0] = As[swz(m + grp,     g0,     tig)];
                a[fm][1] = As[swz(m + grp + 8, g0,     tig)];
                a[fm][2] = As[swz(m + grp,     g0 + 1, tig)];
                a[fm][3] = As[swz(m + grp + 8, g0 + 1, tig)];
            }
            float b[8][2];
#pragma unroll
            for (int fn = 0; fn < 8; fn++) {
                int n = wn * 64 + fn * 8;
                b[fn][0] = Bs[swz(n + grp, g0,     tig)];
                b[fn][1] = Bs[swz(n + grp, g0 + 1, tig)];
            }
#pragma unroll
            for (int fm = 0; fm < 2; fm++)
#pragma unroll
                for (int fn = 0; fn < 8; fn++)
                    mma_tf32(acc[fm][fn], a[fm], b[fn]);
        }
        __syncthreads();
    }

#pragma unroll
    for (int fm = 0; fm < 2; fm++) {
        int m_lo = m0 + wm * 32 + fm * 16 + grp;
        int m_hi = m_lo + 8;
#pragma unroll
        for (int fn = 0; fn < 8; fn++) {
            int n = n0 + wn * 64 + fn * 8 + tig * 2;
#pragma unroll
            for (int e = 0; e < 2; e++) {
                int nn = n + e;
                float bv = bias[nn];
                float v0 = acc[fm][fn][e]     + bv;
                float v1 = acc[fm][fn][e + 2] + bv;
                if (FLAGS & 1) { v0 = fmaxf(v0, 0.f); v1 = fmaxf(v1, 0.f); }
                if constexpr ((FLAGS & 2) != 0) {
                    v0 += (float)C[(size_t)m_lo * ldc + nn];
                    v1 += (float)C[(size_t)m_hi * ldc + nn];
                }
                if (FLAGS & 8) { v0 = to_tf32(v0); v1 = to_tf32(v1); }
                C[(size_t)m_lo * ldc + nn] = (OutT)v0;
                C[(size_t)m_hi * ldc + nn] = (OutT)v1;
            }
        }
    }
}

// ======== scores + exp + row-partial-sums (fp16 mma), P unnormalized =========
// P[bh][k][t] = exp(0.125 * K[k]·Q[t]) if t>=k else 0; psum[bh][tb][k] = row partials
__global__ __launch_bounds__(256)
void scores_p_kernel(const __half* __restrict__ qkvH, __half* __restrict__ P,
                     float* __restrict__ psum) {
    int kb = blockIdx.x, tb = blockIdx.y, bh = blockIdx.z;
    if (tb < kb) return;
    int b = bh / Hh, h = bh % Hh;
    int k0 = kb * 128, t0 = tb * 128;

    __shared__ __align__(16) __half ssm[128 * 136];  // Ks|Qs (32KB) then stage
    __shared__ float sums[128][2];

    int tid = threadIdx.x;
    int warp = tid >> 5, lane = tid & 31;
    int wm = warp & 3, wn = warp >> 2;
    int grp = lane >> 2, tig = lane & 3;
    int lr = lane & 7, sub = lane >> 3;

    uint32_t sb = smem_u32(ssm);
    uint32_t Ksb = sb, Qsb = sb + 16384u;
    const __half* Kb_ = qkvH + (size_t)(b * Tt + k0) * QKV_P + Cc + h * HSs;
    const __half* Qb_ = qkvH + (size_t)(b * Tt + t0) * QKV_P + h * HSs;

#pragma unroll
    for (int it = 0; it < 4; it++) {
        int slot = tid + it * 256;
        int r = slot >> 3, c = slot & 7;
        uint32_t so = (uint32_t)(r * 128 + ((c ^ (r & 7)) << 4));
        cp_async16(Ksb + so, Kb_ + (size_t)r * QKV_P + c * 8);
        cp_async16(Qsb + so, Qb_ + (size_t)r * QKV_P + c * 8);
    }
    cp_commit();
    cp_wait<0>();
    __syncthreads();

    float acc[2][8][4];
#pragma unroll
    for (int i = 0; i < 2; i++)
#pragma unroll
        for (int j = 0; j < 8; j++)
#pragma unroll
            for (int q = 0; q < 4; q++) acc[i][j][q] = 0.f;

    int rowA[2], rowB[4];
#pragma unroll
    for (int fm = 0; fm < 2; fm++) rowA[fm] = wm * 32 + fm * 16 + (sub & 1) * 8 + lr;
#pragma unroll
    for (int p = 0; p < 4; p++) rowB[p] = wn * 64 + p * 16 + (sub >> 1) * 8 + lr;
    int chA = sub >> 1, chB = sub & 1;

#pragma unroll
    for (int k16 = 0; k16 < 4; k16++) {
        int cb = k16 * 2;
        uint32_t afr[2][4];
#pragma unroll
        for (int fm = 0; fm < 2; fm++) {
            int r = rowA[fm];
            ldm_x4(afr[fm], Ksb + r * 128 + (((cb + chA) ^ (r & 7)) << 4));
        }
        uint32_t bfr[4][4];
#pragma unroll
        for (int p = 0; p < 4; p++) {
            int r = rowB[p];
            ldm_x4(bfr[p], Qsb + r * 128 + (((cb + chB) ^ (r & 7)) << 4));
        }
#pragma unroll
        for (int fm = 0; fm < 2; fm++)
#pragma unroll
            for (int fn = 0; fn < 8; fn++)
                mma_f16(acc[fm][fn], afr[fm], &bfr[fn >> 1][(fn & 1) * 2]);
    }
    __syncthreads();  // mma reads done; smem becomes stage

    // epilogue: exp, stage, row partials
    float rp[2][2] = {{0.f, 0.f}, {0.f, 0.f}};
#pragma unroll
    for (int fm = 0; fm < 2; fm++) {
        int kl = wm * 32 + fm * 16 + grp;   // local k of acc[..][e<2]
        int kh = kl + 8;
#pragma unroll
        for (int fn = 0; fn < 8; fn++) {
            int tc = wn * 64 + fn * 8 + tig * 2;
#pragma unroll
            for (int e = 0; e < 2; e++) {
                int t = tc + e;
                float v0 = (t0 + t >= k0 + kl) ? __expf(0.125f * acc[fm][fn][e]) : 0.f;
                float v1 = (t0 + t >= k0 + kh) ? __expf(0.125f * acc[fm][fn][e + 2]) : 0.f;
                ssm[kl * 136 + t] = __float2half(v0);
                ssm[kh * 136 + t] = __float2half(v1);
                rp[fm][0] += v0;
                rp[fm][1] += v1;
            }
        }
    }
#pragma unroll
    for (int fm = 0; fm < 2; fm++)
#pragma unroll
        for (int hl = 0; hl < 2; hl++) {
            rp[fm][hl] += __shfl_xor_sync(0xffffffffu, rp[fm][hl], 1);
            rp[fm][hl] += __shfl_xor_sync(0xffffffffu, rp[fm][hl], 2);
        }
    if (tig == 0) {
#pragma unroll
        for (int fm = 0; fm < 2; fm++) {
            sums[wm * 32 + fm * 16 + grp][wn]     = rp[fm][0];
            sums[wm * 32 + fm * 16 + grp + 8][wn] = rp[fm][1];
        }
    }
    __syncthreads();

    // coalesced P write (uint4 = 8 halfs)
    __half* Pb = P + ((size_t)bh * Tt + k0) * Tt + t0;
#pragma unroll
    for (int i = 0; i < 8; i++) {
        int idx = tid + i * 256;
        int r = idx >> 4, c = idx & 15;
        uint4 v = *reinterpret_cast<const uint4*>(&ssm[r * 136 + c * 8]);
        *reinterpret_cast<uint4*>(Pb + (size_t)r * Tt + c * 8) = v;
    }
    if (tid < 128)
        psum[((size_t)bh * 8 + tb) * Tt + k0 + tid] = sums[tid][0] + sums[tid][1];
}

// ---------------- inv rowsum -------------------------------------------------
__global__ void inv_kernel(const float* __restrict__ psum, float* __restrict__ inv) {
    int i = blockIdx.x * blockDim.x + threadIdx.x;
    if (i >= BH * Tt) return;
    int bh = i / Tt, k = i % Tt;
    int tb0 = k >> 7;
    float s = 0.f;
    for (int tb = tb0; tb < 8; tb++)
        s += psum[((size_t)bh * 8 + tb) * Tt + k];
    inv[i] = 1.f / s;
}

// ---------------- PV via fp16 mma: att[t][h*64+s] = sum_k P[k][t]*inv_k*v[k][s]
__global__ __launch_bounds__(256)
void pv_fp16_kernel(const __half* __restrict__ P, const __half* __restrict__ qkvH,
                    const float* __restrict__ inv, float* __restrict__ att) {
    int tb = blockIdx.x, bh = blockIdx.y;
    int b = bh / Hh, h = bh % Hh;
    int t0 = tb * 128;

    __shared__ __align__(16) __half Pt[128 * 64];  // [t][k] swizzled 128B rows
    __shared__ __align__(16) __half Vt[64 * 64];   // [s][k] swizzled 128B rows

    int tid = threadIdx.x;
    int warp = tid >> 5, lane = tid & 31;
    int wm = warp & 3, wn = warp >> 2;
    int grp = lane >> 2, tig = lane & 3;
    int lr = lane & 7, sub = lane >> 3;

    uint32_t Ptb = smem_u32(Pt), Vtb = smem_u32(Vt);

    float acc[2][4][4];
#pragma unroll
    for (int i = 0; i < 2; i++)
#pragma unroll
        for (int j = 0; j < 4; j++)
#pragma unroll
            for (int q = 0; q < 4; q++) acc[i][j][q] = 0.f;

    int rowA[2], rowB[2];
#pragma unroll
    for (int fm = 0; fm < 2; fm++) rowA[fm] = wm * 32 + fm * 16 + (sub & 1) * 8 + lr;
#pragma unroll
    for (int p = 0; p < 2; p++) rowB[p] = wn * 32 + p * 16 + (sub >> 1) * 8 + lr;
    int chA = sub >> 1, chB = sub & 1;

    int nk = 2 * (tb + 1);
#pragma unroll 1
    for (int kt = 0; kt < nk; kt++) {
        int k0 = kt * 64;
        __syncthreads();
        // load P tile [64 k][128 t] as uints, transpose -> Pt[t][k]
        const __half* Pg = P + ((size_t)bh * Tt + k0) * Tt + t0;
#pragma unroll
        for (int i = 0; i < 16; i++) {
            int idx = tid + i * 256;
            int kk = idx >> 6, tp = idx & 63;
            uint32_t v = *reinterpret_cast<const uint32_t*>(Pg + (size_t)kk * Tt + tp * 2);
            __half h0 = ((const __half2*)&v)->x, h1 = ((const __half2*)&v)->y;
            int t_ = tp * 2;
            Pt[t_ * 64 + ((((kk >> 3) ^ (t_ & 7)) << 3) | (kk & 7))] = h0;
            t_++;
            Pt[t_ * 64 + ((((kk >> 3) ^ (t_ & 7)) << 3) | (kk & 7))] = h1;
        }
        // load V tile [64 k][64 s], scale by inv[k], transpose -> Vt[s][k]
        const __half* Vg = qkvH + (size_t)(b * Tt + k0) * QKV_P + 2 * Cc + h * HSs;
#pragma unroll
        for (int i = 0; i < 8; i++) {
            int idx = tid + i * 256;
            int kk = idx >> 5, sp = idx & 31;
            uint32_t v = *reinterpret_cast<const uint32_t*>(Vg + (size_t)kk * QKV_P + sp * 2);
            float iv = inv[bh * Tt + k0 + kk];
            __half2 h2 = *(const __half2*)&v;
            __half s0 = __float2half(__half2float(h2.x) * iv);
            __half s1 = __float2half(__half2float(h2.y) * iv);
            int s_ = sp * 2;
            Vt[s_ * 64 + ((((kk >> 3) ^ (s_ & 7)) << 3) | (kk & 7))] = s0;
            s_++;
            Vt[s_ * 64 + ((((kk >> 3) ^ (s_ & 7)) << 3) | (kk & 7))] = s1;
        }
        __syncthreads();
#pragma unroll
        for (int k16 = 0; k16 < 4; k16++) {
            int cb = k16 * 2;
            uint32_t afr[2][4];
#pragma unroll
            for (int fm = 0; fm < 2; fm++) {
                int r = rowA[fm];
                ldm_x4(afr[fm], Ptb + r * 128 + (((cb + chA) ^ (r & 7)) << 4));
            }
            uint32_t bfr[2][4];
#pragma unroll
            for (int p = 0; p < 2; p++) {
                int r = rowB[p];
                ldm_x4(bfr[p], Vtb + r * 128 + (((cb + chB) ^ (r & 7)) << 4));
            }
#pragma unroll
            for (int fm = 0; fm < 2; fm++)
#pragma unroll
                for (int fn = 0; fn < 4; fn++)
                    mma_f16(acc[fm][fn], afr[fm], &bfr[fn >> 1][(fn & 1) * 2]);
        }
    }

#pragma unroll
    for (int fm = 0; fm < 2; fm++) {
        int m_lo = t0 + wm * 32 + fm * 16 + grp;
        int m_hi = m_lo + 8;
#pragma unroll
        for (int fn = 0; fn < 4; fn++) {
            int s = wn * 32 + fn * 8 + tig * 2;
#pragma unroll
            for (int e = 0; e < 2; e++) {
                att[(size_t)(b * Tt + m_lo) * Cc + h * HSs + s + e] = to_tf32(acc[fm][fn][e]);
                att[(size_t)(b * Tt + m_hi) * Cc + h * HSs + s + e] = to_tf32(acc[fm][fn][e + 2]);
            }
        }
    }
}

// ================= fp16 LM head ==============================================
constexpr int LM_NKT = Cc / 64;  // 6

__global__ __launch_bounds__(256)
void lmhead_fp16_kernel(const __half* __restrict__ A, const __half* __restrict__ Bt,
                        const float* __restrict__ bias, float* __restrict__ out) {
    extern __shared__ __half smh[];
    int tid = threadIdx.x;
    int warp = tid >> 5, lane = tid & 31;
    int wm = warp & 3, wn = warp >> 2;
    int grp = lane >> 2, tig = lane & 3;
    int lr = lane & 7, sub = lane >> 3;
    int m0 = blockIdx.x * 128, n0 = blockIdx.y * 128;
    const __half* Ab = A + (size_t)m0 * Cc;
    const __half* Bb = Bt + (size_t)n0 * Cc;

    uint32_t sbase = smem_u32(smh);

    auto issue = [&](int kt, int stage) {
        uint32_t as = sbase + stage * 32768u;
        uint32_t bs = as + 16384u;
#pragma unroll
        for (int it = 0; it < 4; it++) {
            int slot = tid + it * 256;
            int r = slot >> 3, c = slot & 7;
            uint32_t so = (uint32_t)(r * 128 + ((c ^ (r & 7)) << 4));
            cp_async16(as + so, Ab + (size_t)r * Cc + kt * 64 + c * 8);
            cp_async16(bs + so, Bb + (size_t)r * Cc + kt * 64 + c * 8);
        }
    };

    float acc[2][8][4];
#pragma unroll
    for (int i = 0; i < 2; i++)
#pragma unroll
        for (int j = 0; j < 8; j++)
#pragma unroll
            for (int q = 0; q < 4; q++) acc[i][j][q] = 0.f;

    int rowA[2], rowB[4];
#pragma unroll
    for (int fm = 0; fm < 2; fm++) rowA[fm] = wm * 32 + fm * 16 + (sub & 1) * 8 + lr;
#pragma unroll
    for (int p = 0; p < 4; p++) rowB[p] = wn * 64 + p * 16 + (sub >> 1) * 8 + lr;
    int chA = sub >> 1, chB = sub & 1;

    issue(0, 0);
    cp_commit();

#pragma unroll 1
    for (int kt = 0; kt < LM_NKT; kt++) {
        if (kt + 1 < LM_NKT) {
            issue(kt + 1, (kt + 1) & 1);
            cp_commit();
            cp_wait<1>();
        } else {
            cp_wait<0>();
        }
        __syncthreads();
        uint32_t as = sbase + (kt & 1) * 32768u;
        uint32_t bs = as + 16384u;
#pragma unroll
        for (int k16 = 0; k16 < 4; k16++) {
            int cb = k16 * 2;
            uint32_t afr[2][4];
#pragma unroll
            for (int fm = 0; fm < 2; fm++) {
                int r = rowA[fm];
                ldm_x4(afr[fm], as + r * 128 + (((cb + chA) ^ (r & 7)) << 4));
            }
            uint32_t bfr[4][4];
#pragma unroll
            for (int p = 0; p < 4; p++) {
                int r = rowB[p];
                ldm_x4(bfr[p], bs + r * 128 + (((cb + chB) ^ (r & 7)) << 4));
            }
#pragma unroll
            for (int fm = 0; fm < 2; fm++)
#pragma unroll
                for (int fn = 0; fn < 8; fn++)
                    mma_f16(acc[fm][fn], afr[fm], &bfr[fn >> 1][(fn & 1) * 2]);
        }
        __syncthreads();
    }

#pragma unroll
    for (int fm = 0; fm < 2; fm++) {
        int m_lo = m0 + wm * 32 + fm * 16 + grp;
        int m_hi = m_lo + 8;
#pragma unroll
        for (int fn = 0; fn < 8; fn++) {
            int n = n0 + wn * 64 + fn * 8 + tig * 2;
#pragma unroll
            for (int e = 0; e < 2; e++) {
                int nn = n + e;
                if (nn >= Vv) continue;
                float bv = bias[nn];
                out[(size_t)m_lo * Vv + nn] = acc[fm][fn][e]     + bv;
                out[(size_t)m_hi * Vv + nn] = acc[fm][fn][e + 2] + bv;
            }
        }
    }
}

// ---------------- host launcher ---------------------------------------------
static float* symaddr(const void* s) {
    void* p = nullptr;
    cudaGetSymbolAddress(&p, s);
    return (float*)p;
}

constexpr int GEMM_SMEM = 65536;

extern "C" void kernel_launch(void* const* d_in, const int* in_sizes, int n_in,
                              void* d_out, int out_size) {
    const int*   x    = (const int*)d_in[0];
    const float* tok  = (const float*)d_in[1];
    const float* pos  = (const float*)d_in[2];
    const float* Wq   = (const float*)d_in[3];
    const float* bq   = (const float*)d_in[4];
    const float* Wk   = (const float*)d_in[5];
    const float* bk   = (const float*)d_in[6];
    const float* Wv   = (const float*)d_in[7];
    const float* bv   = (const float*)d_in[8];
    const float* Wo   = (const float*)d_in[9];
    const float* bo   = (const float*)d_in[10];
    const float* ln1g = (const float*)d_in[11];
    const float* ln1b = (const float*)d_in[12];
    const float* W1   = (const float*)d_in[13];
    const float* b1   = (const float*)d_in[14];
    const float* W2   = (const float*)d_in[15];
    const float* b2   = (const float*)d_in[16];
    const float* ln2g = (const float*)d_in[17];
    const float* ln2b = (const float*)d_in[18];
    const float* Wlm  = (const float*)d_in[19];
    const float* blm  = (const float*)d_in[20];
    float* out = (float*)d_out;

    float* ph     = symaddr(g_h);
    float* pa     = symaddr(g_a);
    __half* pqkvH = (__half*)symaddr(g_qkvH);
    float* patt   = symaddr(g_att);
    float* pm     = symaddr(g_m);
    __half* pP    = (__half*)symaddr(g_P);
    float* ppsum  = symaddr(g_psum);
    float* pinv   = symaddr(g_inv);
    float* pWqkvT = symaddr(g_WqkvT);
    float* pbqkv  = symaddr(g_bqkv);
    float* pWoT   = symaddr(g_WoT);
    float* pW1T   = symaddr(g_W1T);
    float* pW2T   = symaddr(g_W2T);
    __half* phH   = (__half*)symaddr(g_hH);
    __half* pWlmH = (__half*)symaddr(g_WlmH);

    static bool attr_done = false;
    if (!attr_done) {
        cudaFuncSetAttribute((const void*)mma_gemm_kernel<0, __half>, cudaFuncAttributeMaxDynamicSharedMemorySize, GEMM_SMEM);
        cudaFuncSetAttribute((const void*)mma_gemm_kernel<2, float>, cudaFuncAttributeMaxDynamicSharedMemorySize, GEMM_SMEM);
        cudaFuncSetAttribute((const void*)mma_gemm_kernel<9, float>, cudaFuncAttributeMaxDynamicSharedMemorySize, GEMM_SMEM);
        cudaFuncSetAttribute((const void*)lmhead_fp16_kernel, cudaFuncAttributeMaxDynamicSharedMemorySize, GEMM_SMEM);
        attr_done = true;
    }

    embed_kernel<<<(M_ROWS * Cc + 255) / 256, 256>>>(x, tok, pos, ph);

    int qkvt_total = NLl * QKV_P * Cc;
    repack_qkvT_kernel<<<(qkvt_total + 255) / 256, 256>>>(Wq, Wk, Wv, pWqkvT);
    repack_bqkv_kernel<<<(NLl * QKV_P + 255) / 256, 256>>>(bq, bk, bv, pbqkv);
    dim3 tg(Cc / 32, Cc / 32, NLl);
    transpose_w_kernel<<<tg, dim3(32, 8)>>>(Wo, pWoT);
    transpose_w_kernel<<<tg, dim3(32, 8)>>>(W1, pW1T);
    transpose_w_kernel<<<tg, dim3(32, 8)>>>(W2, pW2T);
    transpose_wlm_kernel<<<dim3(V_PAD / 32, Cc / 32), dim3(32, 8)>>>(Wlm, pWlmH);

    dim3 g_qkv_grid(M_ROWS / 128, QKV_P / 128);   // (16, 9)
    dim3 g_c_grid(M_ROWS / 128, Cc / 128);        // (16, 3)

    for (int l = 0; l < NLl; l++) {
        ln_kernel<<<M_ROWS, 128>>>(ph, ln1g + l * Cc, ln1b + l * Cc, pa);

        mma_gemm_kernel<0, __half><<<g_qkv_grid, 256, GEMM_SMEM>>>(
            pa, pWqkvT + (size_t)l * QKV_P * Cc, pbqkv + l * QKV_P, pqkvH, QKV_P);

        scores_p_kernel<<<dim3(8, 8, BH), 256>>>(pqkvH, pP, ppsum);
        inv_kernel<<<(BH * Tt + 255) / 256, 256>>>(ppsum, pinv);
        pv_fp16_kernel<<<dim3(8, BH), 256>>>(pP, pqkvH, pinv, patt);

        mma_gemm_kernel<2, float><<<g_c_grid, 256, GEMM_SMEM>>>(
            patt, pWoT + (size_t)l * Cc * Cc, bo + l * Cc, ph, Cc);

        ln_kernel<<<M_ROWS, 128>>>(ph, ln2g + l * Cc, ln2b + l * Cc, pa);

        mma_gemm_kernel<9, float><<<g_c_grid, 256, GEMM_SMEM>>>(
            pa, pW1T + (size_t)l * Cc * Cc, b1 + l * Cc, pm, Cc);
        mma_gemm_kernel<2, float><<<g_c_grid, 256, GEMM_SMEM>>>(
            pm, pW2T + (size_t)l * Cc * Cc, b2 + l * Cc, ph, Cc);
    }

    // LM head (fp16 tensor cores)
    cvt_h_kernel<<<(M_ROWS * Cc + 255) / 256, 256>>>(ph, phH);
    lmhead_fp16_kernel<<<dim3(M_ROWS / 128, V_PAD / 128), 256, GEMM_SMEM>>>(
        phH, pWlmH, blm, out);
}

// round 7
// speedup vs baseline: 7.5734x; 1.1406x over previous
#include <cuda_runtime.h>
#include <cuda_fp16.h>
#include <cstdint>

// Problem constants
constexpr int Vv = 50257, Cc = 384, Tt = 1024, Hh = 6, HSs = 64, NLl = 3, Bb = 2;
constexpr int M_ROWS = Bb * Tt;   // 2048
constexpr int BH = Bb * Hh;       // 12
constexpr int V_PAD = 50304;      // 393 * 128
constexpr int QKV_P = 3 * Cc;     // 1152

// ---------------- scratch (__device__ globals; no allocation allowed) --------
__device__ float g_h[M_ROWS * Cc];
__device__ __half g_aH[M_ROWS * Cc];               // LN output fp16
__device__ __half g_qkvH[M_ROWS * QKV_P];          // fused QKV, fp16
__device__ __half g_attH[M_ROWS * Cc];             // PV output fp16
__device__ __half g_mH[M_ROWS * Cc];               // relu(W1) output fp16
__device__ __half g_P[(size_t)BH * Tt * Tt];       // unnormalized probs [bh][k][t]
__device__ float g_psum[BH * 8 * Tt];              // per-(bh,tb) row partial sums
__device__ __half g_WqkvT[NLl * QKV_P * Cc];       // [l][n][k] fp16
__device__ float g_bqkv[NLl * QKV_P];
__device__ __half g_WoT[NLl * Cc * Cc];
__device__ __half g_W1T[NLl * Cc * Cc];
__device__ __half g_W2T[NLl * Cc * Cc];
__device__ __half g_hH[M_ROWS * Cc];               // h as fp16 (LM head input)
__device__ __half g_WlmH[(size_t)V_PAD * Cc];      // Wlm^T as fp16 [n][k]

// ---------------- embedding --------------------------------------------------
__global__ void embed_kernel(const int* __restrict__ x, const float* __restrict__ tok,
                             const float* __restrict__ pos, float* __restrict__ h) {
    int i = blockIdx.x * blockDim.x + threadIdx.x;
    if (i >= M_ROWS * Cc) return;
    int row = i / Cc, c = i % Cc;
    int t = row % Tt;
    h[i] = tok[(size_t)x[row] * Cc + c] + pos[t * Cc + c];
}

// ---------------- repacks (one-time per call) --------------------------------
__global__ void repack_qkvT_kernel(const float* __restrict__ Wq, const float* __restrict__ Wk,
                                   const float* __restrict__ Wv, __half* __restrict__ O) {
    int i = blockIdx.x * blockDim.x + threadIdx.x;
    if (i >= NLl * QKV_P * Cc) return;
    int k = i % Cc;
    int n = (i / Cc) % QKV_P;
    int l = i / (Cc * QKV_P);
    int sel = n / Cc, h = (n % Cc) / HSs, s = n % HSs;
    const float* W = (sel == 0) ? Wq : (sel == 1) ? Wk : Wv;
    O[i] = __float2half(W[(((size_t)l * Hh + h) * Cc + k) * HSs + s]);
}

__global__ void repack_bqkv_kernel(const float* __restrict__ bq, const float* __restrict__ bk,
                                   const float* __restrict__ bv, float* __restrict__ O) {
    int i = blockIdx.x * blockDim.x + threadIdx.x;
    if (i >= NLl * QKV_P) return;
    int n = i % QKV_P, l = i / QKV_P;
    int sel = n / Cc, h = (n % Cc) / HSs, s = n % HSs;
    const float* B = (sel == 0) ? bq : (sel == 1) ? bk : bv;
    O[i] = B[((size_t)l * Hh + h) * HSs + s];
}

__global__ void transpose_w_kernel(const float* __restrict__ W, __half* __restrict__ WT) {
    __shared__ float t[32][33];
    int l = blockIdx.z;
    int n0 = blockIdx.x * 32, k0 = blockIdx.y * 32;
    const float* Wl = W + (size_t)l * Cc * Cc;
    __half* Tl = WT + (size_t)l * Cc * Cc;
    for (int dy = threadIdx.y; dy < 32; dy += 8)
        t[dy][threadIdx.x] = Wl[(size_t)(k0 + dy) * Cc + n0 + threadIdx.x];
    __syncthreads();
    for (int dy = threadIdx.y; dy < 32; dy += 8)
        Tl[(size_t)(n0 + dy) * Cc + k0 + threadIdx.x] = __float2half(t[threadIdx.x][dy]);
}

__global__ void transpose_wlm_kernel(const float* __restrict__ Wlm, __half* __restrict__ Bt) {
    __shared__ float tile[32][33];
    int n0 = blockIdx.x * 32, k0 = blockIdx.y * 32;
    for (int dy = threadIdx.y; dy < 32; dy += 8) {
        int k = k0 + dy, n = n0 + threadIdx.x;
        tile[dy][threadIdx.x] = (n < Vv) ? Wlm[(size_t)k * Vv + n] : 0.f;
    }
    __syncthreads();
    for (int dy = threadIdx.y; dy < 32; dy += 8) {
        int n = n0 + dy, k = k0 + threadIdx.x;
        Bt[(size_t)n * Cc + k] = __float2half(tile[threadIdx.x][dy]);
    }
}

// ---------------- layernorm (fp16 out) ---------------------------------------
__global__ void ln_kernel(const float* __restrict__ x, const float* __restrict__ g,
                          const float* __restrict__ b, __half* __restrict__ y) {
    int row = blockIdx.x;
    const float* xr = x + (size_t)row * Cc;
    __half* yr = y + (size_t)row * Cc;
    float lsum = 0.f, lsq = 0.f;
    for (int c = threadIdx.x; c < Cc; c += blockDim.x) {
        float v = xr[c]; lsum += v; lsq += v * v;
    }
    __shared__ float sh[64];
    int lane = threadIdx.x & 31, wid = threadIdx.x >> 5;
#pragma unroll
    for (int o = 16; o; o >>= 1) {
        lsum += __shfl_xor_sync(0xffffffffu, lsum, o);
        lsq  += __shfl_xor_sync(0xffffffffu, lsq,  o);
    }
    if (lane == 0) { sh[wid] = lsum; sh[wid + 32] = lsq; }
    __syncthreads();
    int nw = blockDim.x >> 5;
    if (threadIdx.x == 0) {
        float s = 0.f, q = 0.f;
        for (int w = 0; w < nw; w++) { s += sh[w]; q += sh[w + 32]; }
        sh[0] = s; sh[32] = q;
    }
    __syncthreads();
    float mu = sh[0] / Cc;
    float var = sh[32] / Cc - mu * mu;
    float rstd = rsqrtf(var + 1e-5f);
    for (int c = threadIdx.x; c < Cc; c += blockDim.x)
        yr[c] = __float2half((xr[c] - mu) * rstd * g[c] + b[c]);
}

// ---------------- common asm helpers ----------------------------------------
__device__ __forceinline__ uint32_t smem_u32(const void* p) {
    uint32_t a;
    asm("{ .reg .u64 t; cvta.to.shared.u64 t, %1; cvt.u32.u64 %0, t; }" : "=r"(a) : "l"(p));
    return a;
}
__device__ __forceinline__ void cp_async16(uint32_t saddr, const void* g) {
    asm volatile("cp.async.cg.shared.global [%0], [%1], 16;" :: "r"(saddr), "l"(g) : "memory");
}
__device__ __forceinline__ void cp_commit() {
    asm volatile("cp.async.commit_group;" ::: "memory");
}
template<int N>
__device__ __forceinline__ void cp_wait() {
    asm volatile("cp.async.wait_group %0;" :: "n"(N) : "memory");
}
__device__ __forceinline__ void ldm_x4(uint32_t* r, uint32_t addr) {
    asm volatile("ldmatrix.sync.aligned.m8n8.x4.shared.b16 {%0,%1,%2,%3}, [%4];"
                 : "=r"(r[0]), "=r"(r[1]), "=r"(r[2]), "=r"(r[3]) : "r"(addr));
}
__device__ __forceinline__ void mma_f16(float* c, const uint32_t* a, const uint32_t* b) {
    asm volatile(
        "mma.sync.aligned.m16n8k16.row.col.f32.f16.f16.f32 "
        "{%0,%1,%2,%3}, {%4,%5,%6,%7}, {%8,%9}, {%0,%1,%2,%3};"
        : "+f"(c[0]), "+f"(c[1]), "+f"(c[2]), "+f"(c[3])
        : "r"(a[0]), "r"(a[1]), "r"(a[2]), "r"(a[3]), "r"(b[0]), "r"(b[1]));
}

// ================= fp16 layer GEMM: CTA 64x128, K-tile 64 ====================
// C[M,N] = A[M,384] @ Bt[N,384]^T + bias. 8 warps as 2(M)x4(N), warp 32x32.
// FLAGS: 1=relu, 2=accumulate into fp32 C, 16=also write fp16 copy to aux.
// Output type: fp32 if (FLAGS&2) else fp16.
constexpr int H16_NKT = Cc / 64;      // 6
constexpr int H16_SMEM = 49152;       // 2 stages x (A 8KB + B 16KB)

template<int FLAGS>
__global__ __launch_bounds__(256)
void h16_gemm_kernel(const __half* __restrict__ A, const __half* __restrict__ Bt,
                     const float* __restrict__ bias, void* __restrict__ Cv,
                     __half* __restrict__ aux, int ldc) {
    extern __shared__ __half smh[];
    int tid = threadIdx.x;
    int warp = tid >> 5, lane = tid & 31;
    int wm = warp & 1, wn = warp >> 1;
    int grp = lane >> 2, tig = lane & 3;
    int lr = lane & 7, sub = lane >> 3;
    int m0 = blockIdx.x * 64, n0 = blockIdx.y * 128;
    const __half* Ab = A + (size_t)m0 * Cc;
    const __half* Bb = Bt + (size_t)n0 * Cc;
    uint32_t sbase = smem_u32(smh);

    auto issue = [&](int kt, int stage) {
        uint32_t as = sbase + stage * 24576u;
        uint32_t bs = as + 8192u;
#pragma unroll
        for (int it = 0; it < 2; it++) {     // A: 64 rows x 8 chunks = 512
            int slot = tid + it * 256;
            int r = slot >> 3, c = slot & 7;
            uint32_t so = (uint32_t)(r * 128 + ((c ^ (r & 7)) << 4));
            cp_async16(as + so, Ab + (size_t)r * Cc + kt * 64 + c * 8);
        }
#pragma unroll
        for (int it = 0; it < 4; it++) {     // B: 128 rows x 8 chunks = 1024
            int slot = tid + it * 256;
            int r = slot >> 3, c = slot & 7;
            uint32_t so = (uint32_t)(r * 128 + ((c ^ (r & 7)) << 4));
            cp_async16(bs + so, Bb + (size_t)r * Cc + kt * 64 + c * 8);
        }
    };

    float acc[2][4][4];
#pragma unroll
    for (int i = 0; i < 2; i++)
#pragma unroll
        for (int j = 0; j < 4; j++)
#pragma unroll
            for (int q = 0; q < 4; q++) acc[i][j][q] = 0.f;

    int rowA[2], rowB[2];
#pragma unroll
    for (int fm = 0; fm < 2; fm++) rowA[fm] = wm * 32 + fm * 16 + (sub & 1) * 8 + lr;
#pragma unroll
    for (int p = 0; p < 2; p++) rowB[p] = wn * 32 + p * 16 + (sub >> 1) * 8 + lr;
    int chA = sub >> 1, chB = sub & 1;

    issue(0, 0);
    cp_commit();

#pragma unroll 1
    for (int kt = 0; kt < H16_NKT; kt++) {
        if (kt + 1 < H16_NKT) {
            issue(kt + 1, (kt + 1) & 1);
            cp_commit();
            cp_wait<1>();
        } else {
            cp_wait<0>();
        }
        __syncthreads();
        uint32_t as = sbase + (kt & 1) * 24576u;
        uint32_t bs = as + 8192u;
#pragma unroll
        for (int k16 = 0; k16 < 4; k16++) {
            int cb = k16 * 2;
            uint32_t afr[2][4];
#pragma unroll
            for (int fm = 0; fm < 2; fm++) {
                int r = rowA[fm];
                ldm_x4(afr[fm], as + r * 128 + (((cb + chA) ^ (r & 7)) << 4));
            }
            uint32_t bfr[2][4];
#pragma unroll
            for (int p = 0; p < 2; p++) {
                int r = rowB[p];
                ldm_x4(bfr[p], bs + r * 128 + (((cb + chB) ^ (r & 7)) << 4));
            }
#pragma unroll
            for (int fm = 0; fm < 2; fm++)
#pragma unroll
                for (int fn = 0; fn < 4; fn++)
                    mma_f16(acc[fm][fn], afr[fm], &bfr[fn >> 1][(fn & 1) * 2]);
        }
        __syncthreads();
    }

#pragma unroll
    for (int fm = 0; fm < 2; fm++) {
        int m_lo = m0 + wm * 32 + fm * 16 + grp;
        int m_hi = m_lo + 8;
#pragma unroll
        for (int fn = 0; fn < 4; fn++) {
            int n = n0 + wn * 32 + fn * 8 + tig * 2;
#pragma unroll
            for (int e = 0; e < 2; e++) {
                int nn = n + e;
                float bv = bias[nn];
                float v0 = acc[fm][fn][e]     + bv;
                float v1 = acc[fm][fn][e + 2] + bv;
                if (FLAGS & 1) { v0 = fmaxf(v0, 0.f); v1 = fmaxf(v1, 0.f); }
                if constexpr ((FLAGS & 2) != 0) {
                    float* C = (float*)Cv;
                    v0 += C[(size_t)m_lo * ldc + nn];
                    v1 += C[(size_t)m_hi * ldc + nn];
                    C[(size_t)m_lo * ldc + nn] = v0;
                    C[(size_t)m_hi * ldc + nn] = v1;
                    if constexpr ((FLAGS & 16) != 0) {
                        aux[(size_t)m_lo * ldc + nn] = __float2half(v0);
                        aux[(size_t)m_hi * ldc + nn] = __float2half(v1);
                    }
                } else {
                    __half* C = (__half*)Cv;
                    C[(size_t)m_lo * ldc + nn] = __float2half(v0);
                    C[(size_t)m_hi * ldc + nn] = __float2half(v1);
                }
            }
        }
    }
}

// ======== scores + exp + row-partial-sums (fp16 mma), P unnormalized =========
__global__ __launch_bounds__(256)
void scores_p_kernel(const __half* __restrict__ qkvH, __half* __restrict__ P,
                     float* __restrict__ psum) {
    int kb = blockIdx.x, tb = blockIdx.y, bh = blockIdx.z;
    if (tb < kb) return;
    int b = bh / Hh, h = bh % Hh;
    int k0 = kb * 128, t0 = tb * 128;

    __shared__ __align__(16) __half ssm[128 * 136];
    __shared__ float sums[128][2];

    int tid = threadIdx.x;
    int warp = tid >> 5, lane = tid & 31;
    int wm = warp & 3, wn = warp >> 2;
    int grp = lane >> 2, tig = lane & 3;
    int lr = lane & 7, sub = lane >> 3;

    uint32_t sb = smem_u32(ssm);
    uint32_t Ksb = sb, Qsb = sb + 16384u;
    const __half* Kb_ = qkvH + (size_t)(b * Tt + k0) * QKV_P + Cc + h * HSs;
    const __half* Qb_ = qkvH + (size_t)(b * Tt + t0) * QKV_P + h * HSs;

#pragma unroll
    for (int it = 0; it < 4; it++) {
        int slot = tid + it * 256;
        int r = slot >> 3, c = slot & 7;
        uint32_t so = (uint32_t)(r * 128 + ((c ^ (r & 7)) << 4));
        cp_async16(Ksb + so, Kb_ + (size_t)r * QKV_P + c * 8);
        cp_async16(Qsb + so, Qb_ + (size_t)r * QKV_P + c * 8);
    }
    cp_commit();
    cp_wait<0>();
    __syncthreads();

    float acc[2][8][4];
#pragma unroll
    for (int i = 0; i < 2; i++)
#pragma unroll
        for (int j = 0; j < 8; j++)
#pragma unroll
            for (int q = 0; q < 4; q++) acc[i][j][q] = 0.f;

    int rowA[2], rowB[4];
#pragma unroll
    for (int fm = 0; fm < 2; fm++) rowA[fm] = wm * 32 + fm * 16 + (sub & 1) * 8 + lr;
#pragma unroll
    for (int p = 0; p < 4; p++) rowB[p] = wn * 64 + p * 16 + (sub >> 1) * 8 + lr;
    int chA = sub >> 1, chB = sub & 1;

#pragma unroll
    for (int k16 = 0; k16 < 4; k16++) {
        int cb = k16 * 2;
        uint32_t afr[2][4];
#pragma unroll
        for (int fm = 0; fm < 2; fm++) {
            int r = rowA[fm];
            ldm_x4(afr[fm], Ksb + r * 128 + (((cb + chA) ^ (r & 7)) << 4));
        }
        uint32_t bfr[4][4];
#pragma unroll
        for (int p = 0; p < 4; p++) {
            int r = rowB[p];
            ldm_x4(bfr[p], Qsb + r * 128 + (((cb + chB) ^ (r & 7)) << 4));
        }
#pragma unroll
        for (int fm = 0; fm < 2; fm++)
#pragma unroll
            for (int fn = 0; fn < 8; fn++)
                mma_f16(acc[fm][fn], afr[fm], &bfr[fn >> 1][(fn & 1) * 2]);
    }
    __syncthreads();

    float rp[2][2] = {{0.f, 0.f}, {0.f, 0.f}};
#pragma unroll
    for (int fm = 0; fm < 2; fm++) {
        int kl = wm * 32 + fm * 16 + grp;
        int kh = kl + 8;
#pragma unroll
        for (int fn = 0; fn < 8; fn++) {
            int tc = wn * 64 + fn * 8 + tig * 2;
#pragma unroll
            for (int e = 0; e < 2; e++) {
                int t = tc + e;
                float v0 = (t0 + t >= k0 + kl) ? __expf(0.125f * acc[fm][fn][e]) : 0.f;
                float v1 = (t0 + t >= k0 + kh) ? __expf(0.125f * acc[fm][fn][e + 2]) : 0.f;
                ssm[kl * 136 + t] = __float2half(v0);
                ssm[kh * 136 + t] = __float2half(v1);
                rp[fm][0] += v0;
                rp[fm][1] += v1;
            }
        }
    }
#pragma unroll
    for (int fm = 0; fm < 2; fm++)
#pragma unroll
        for (int hl = 0; hl < 2; hl++) {
            rp[fm][hl] += __shfl_xor_sync(0xffffffffu, rp[fm][hl], 1);
            rp[fm][hl] += __shfl_xor_sync(0xffffffffu, rp[fm][hl], 2);
        }
    if (tig == 0) {
#pragma unroll
        for (int fm = 0; fm < 2; fm++) {
            sums[wm * 32 + fm * 16 + grp][wn]     = rp[fm][0];
            sums[wm * 32 + fm * 16 + grp + 8][wn] = rp[fm][1];
        }
    }
    __syncthreads();

    __half* Pb = P + ((size_t)bh * Tt + k0) * Tt + t0;
#pragma unroll
    for (int i = 0; i < 8; i++) {
        int idx = tid + i * 256;
        int r = idx >> 4, c = idx & 15;
        uint4 v = *reinterpret_cast<const uint4*>(&ssm[r * 136 + c * 8]);
        *reinterpret_cast<uint4*>(Pb + (size_t)r * Tt + c * 8) = v;
    }
    if (tid < 128)
        psum[((size_t)bh * 8 + tb) * Tt + k0 + tid] = sums[tid][0] + sums[tid][1];
}

// ---------------- PV via fp16 mma, inv folded in -----------------------------
__global__ __launch_bounds__(256)
void pv_fp16_kernel(const __half* __restrict__ P, const __half* __restrict__ qkvH,
                    const float* __restrict__ psum, __half* __restrict__ att) {
    int tb = blockIdx.x, bh = blockIdx.y;
    int b = bh / Hh, h = bh % Hh;
    int t0 = tb * 128;

    __shared__ __align__(16) __half Pt[128 * 64];
    __shared__ __align__(16) __half Vt[64 * 64];
    __shared__ float invs[1024];

    int tid = threadIdx.x;
    int warp = tid >> 5, lane = tid & 31;
    int wm = warp & 3, wn = warp >> 2;
    int grp = lane >> 2, tig = lane & 3;
    int lr = lane & 7, sub = lane >> 3;

    uint32_t Ptb = smem_u32(Pt), Vtb = smem_u32(Vt);

    int nk = 2 * (tb + 1);
    int Kext = nk * 64;
    for (int i = tid; i < Kext; i += 256) {
        int tb0 = i >> 7;
        float s = 0.f;
        for (int t2 = tb0; t2 < 8; t2++)
            s += psum[((size_t)bh * 8 + t2) * Tt + i];
        invs[i] = 1.f / s;
    }

    float acc[2][4][4];
#pragma unroll
    for (int i = 0; i < 2; i++)
#pragma unroll
        for (int j = 0; j < 4; j++)
#pragma unroll
            for (int q = 0; q < 4; q++) acc[i][j][q] = 0.f;

    int rowA[2], rowB[2];
#pragma unroll
    for (int fm = 0; fm < 2; fm++) rowA[fm] = wm * 32 + fm * 16 + (sub & 1) * 8 + lr;
#pragma unroll
    for (int p = 0; p < 2; p++) rowB[p] = wn * 32 + p * 16 + (sub >> 1) * 8 + lr;
    int chA = sub >> 1, chB = sub & 1;

#pragma unroll 1
    for (int kt = 0; kt < nk; kt++) {
        int k0 = kt * 64;
        __syncthreads();
        const __half* Pg = P + ((size_t)bh * Tt + k0) * Tt + t0;
#pragma unroll
        for (int i = 0; i < 16; i++) {
            int idx = tid + i * 256;
            int kk = idx >> 6, tp = idx & 63;
            uint32_t v = *reinterpret_cast<const uint32_t*>(Pg + (size_t)kk * Tt + tp * 2);
            __half h0 = ((const __half2*)&v)->x, h1 = ((const __half2*)&v)->y;
            int t_ = tp * 2;
            Pt[t_ * 64 + ((((kk >> 3) ^ (t_ & 7)) << 3) | (kk & 7))] = h0;
            t_++;
            Pt[t_ * 64 + ((((kk >> 3) ^ (t_ & 7)) << 3) | (kk & 7))] = h1;
        }
        const __half* Vg = qkvH + (size_t)(b * Tt + k0) * QKV_P + 2 * Cc + h * HSs;
#pragma unroll
        for (int i = 0; i < 8; i++) {
            int idx = tid + i * 256;
            int kk = idx >> 5, sp = idx & 31;
            uint32_t v = *reinterpret_cast<const uint32_t*>(Vg + (size_t)kk * QKV_P + sp * 2);
            float iv = invs[k0 + kk];
            __half2 h2 = *(const __half2*)&v;
            __half s0 = __float2half(__half2float(h2.x) * iv);
            __half s1 = __float2half(__half2float(h2.y) * iv);
            int s_ = sp * 2;
            Vt[s_ * 64 + ((((kk >> 3) ^ (s_ & 7)) << 3) | (kk & 7))] = s0;
            s_++;
            Vt[s_ * 64 + ((((kk >> 3) ^ (s_ & 7)) << 3) | (kk & 7))] = s1;
        }
        __syncthreads();
#pragma unroll
        for (int k16 = 0; k16 < 4; k16++) {
            int cb = k16 * 2;
            uint32_t afr[2][4];
#pragma unroll
            for (int fm = 0; fm < 2; fm++) {
                int r = rowA[fm];
                ldm_x4(afr[fm], Ptb + r * 128 + (((cb + chA) ^ (r & 7)) << 4));
            }
            uint32_t bfr[2][4];
#pragma unroll
            for (int p = 0; p < 2; p++) {
                int r = rowB[p];
                ldm_x4(bfr[p], Vtb + r * 128 + (((cb + chB) ^ (r & 7)) << 4));
            }
#pragma unroll
            for (int fm = 0; fm < 2; fm++)
#pragma unroll
                for (int fn = 0; fn < 4; fn++)
                    mma_f16(acc[fm][fn], afr[fm], &bfr[fn >> 1][(fn & 1) * 2]);
        }
    }

#pragma unroll
    for (int fm = 0; fm < 2; fm++) {
        int m_lo = t0 + wm * 32 + fm * 16 + grp;
        int m_hi = m_lo + 8;
#pragma unroll
        for (int fn = 0; fn < 4; fn++) {
            int s = wn * 32 + fn * 8 + tig * 2;
#pragma unroll
            for (int e = 0; e < 2; e++) {
                att[(size_t)(b * Tt + m_lo) * Cc + h * HSs + s + e] = __float2half(acc[fm][fn][e]);
                att[(size_t)(b * Tt + m_hi) * Cc + h * HSs + s + e] = __float2half(acc[fm][fn][e + 2]);
            }
        }
    }
}

// ================= fp16 LM head ==============================================
constexpr int LM_NKT = Cc / 64;  // 6

__global__ __launch_bounds__(256)
void lmhead_fp16_kernel(const __half* __restrict__ A, const __half* __restrict__ Bt,
                        const float* __restrict__ bias, float* __restrict__ out) {
    extern __shared__ __half smh[];
    int tid = threadIdx.x;
    int warp = tid >> 5, lane = tid & 31;
    int wm = warp & 3, wn = warp >> 2;
    int grp = lane >> 2, tig = lane & 3;
    int lr = lane & 7, sub = lane >> 3;
    int m0 = blockIdx.x * 128, n0 = blockIdx.y * 128;
    const __half* Ab = A + (size_t)m0 * Cc;
    const __half* Bb = Bt + (size_t)n0 * Cc;

    uint32_t sbase = smem_u32(smh);

    auto issue = [&](int kt, int stage) {
        uint32_t as = sbase + stage * 32768u;
        uint32_t bs = as + 16384u;
#pragma unroll
        for (int it = 0; it < 4; it++) {
            int slot = tid + it * 256;
            int r = slot >> 3, c = slot & 7;
            uint32_t so = (uint32_t)(r * 128 + ((c ^ (r & 7)) << 4));
            cp_async16(as + so, Ab + (size_t)r * Cc + kt * 64 + c * 8);
            cp_async16(bs + so, Bb + (size_t)r * Cc + kt * 64 + c * 8);
        }
    };

    float acc[2][8][4];
#pragma unroll
    for (int i = 0; i < 2; i++)
#pragma unroll
        for (int j = 0; j < 8; j++)
#pragma unroll
            for (int q = 0; q < 4; q++) acc[i][j][q] = 0.f;

    int rowA[2], rowB[4];
#pragma unroll
    for (int fm = 0; fm < 2; fm++) rowA[fm] = wm * 32 + fm * 16 + (sub & 1) * 8 + lr;
#pragma unroll
    for (int p = 0; p < 4; p++) rowB[p] = wn * 64 + p * 16 + (sub >> 1) * 8 + lr;
    int chA = sub >> 1, chB = sub & 1;

    issue(0, 0);
    cp_commit();

#pragma unroll 1
    for (int kt = 0; kt < LM_NKT; kt++) {
        if (kt + 1 < LM_NKT) {
            issue(kt + 1, (kt + 1) & 1);
            cp_commit();
            cp_wait<1>();
        } else {
            cp_wait<0>();
        }
        __syncthreads();
        uint32_t as = sbase + (kt & 1) * 32768u;
        uint32_t bs = as + 16384u;
#pragma unroll
        for (int k16 = 0; k16 < 4; k16++) {
            int cb = k16 * 2;
            uint32_t afr[2][4];
#pragma unroll
            for (int fm = 0; fm < 2; fm++) {
                int r = rowA[fm];
                ldm_x4(afr[fm], as + r * 128 + (((cb + chA) ^ (r & 7)) << 4));
            }
            uint32_t bfr[4][4];
#pragma unroll
            for (int p = 0; p < 4; p++) {
                int r = rowB[p];
                ldm_x4(bfr[p], bs + r * 128 + (((cb + chB) ^ (r & 7)) << 4));
            }
#pragma unroll
            for (int fm = 0; fm < 2; fm++)
#pragma unroll
                for (int fn = 0; fn < 8; fn++)
                    mma_f16(acc[fm][fn], afr[fm], &bfr[fn >> 1][(fn & 1) * 2]);
        }
        __syncthreads();
    }

#pragma unroll
    for (int fm = 0; fm < 2; fm++) {
        int m_lo = m0 + wm * 32 + fm * 16 + grp;
        int m_hi = m_lo + 8;
#pragma unroll
        for (int fn = 0; fn < 8; fn++) {
            int n = n0 + wn * 64 + fn * 8 + tig * 2;
#pragma unroll
            for (int e = 0; e < 2; e++) {
                int nn = n + e;
                if (nn >= Vv) continue;
                float bv = bias[nn];
                out[(size_t)m_lo * Vv + nn] = acc[fm][fn][e]     + bv;
                out[(size_t)m_hi * Vv + nn] = acc[fm][fn][e + 2] + bv;
            }
        }
    }
}

// ---------------- host launcher ---------------------------------------------
static float* symaddr(const void* s) {
    void* p = nullptr;
    cudaGetSymbolAddress(&p, s);
    return (float*)p;
}

constexpr int GEMM_SMEM = 65536;

extern "C" void kernel_launch(void* const* d_in, const int* in_sizes, int n_in,
                              void* d_out, int out_size) {
    const int*   x    = (const int*)d_in[0];
    const float* tok  = (const float*)d_in[1];
    const float* pos  = (const float*)d_in[2];
    const float* Wq   = (const float*)d_in[3];
    const float* bq   = (const float*)d_in[4];
    const float* Wk   = (const float*)d_in[5];
    const float* bk   = (const float*)d_in[6];
    const float* Wv   = (const float*)d_in[7];
    const float* bv   = (const float*)d_in[8];
    const float* Wo   = (const float*)d_in[9];
    const float* bo   = (const float*)d_in[10];
    const float* ln1g = (const float*)d_in[11];
    const float* ln1b = (const float*)d_in[12];
    const float* W1   = (const float*)d_in[13];
    const float* b1   = (const float*)d_in[14];
    const float* W2   = (const float*)d_in[15];
    const float* b2   = (const float*)d_in[16];
    const float* ln2g = (const float*)d_in[17];
    const float* ln2b = (const float*)d_in[18];
    const float* Wlm  = (const float*)d_in[19];
    const float* blm  = (const float*)d_in[20];
    float* out = (float*)d_out;

    float* ph      = symaddr(g_h);
    __half* paH    = (__half*)symaddr(g_aH);
    __half* pqkvH  = (__half*)symaddr(g_qkvH);
    __half* pattH  = (__half*)symaddr(g_attH);
    __half* pmH    = (__half*)symaddr(g_mH);
    __half* pP     = (__half*)symaddr(g_P);
    float* ppsum   = symaddr(g_psum);
    __half* pWqkvT = (__half*)symaddr(g_WqkvT);
    float* pbqkv   = symaddr(g_bqkv);
    __half* pWoT   = (__half*)symaddr(g_WoT);
    __half* pW1T   = (__half*)symaddr(g_W1T);
    __half* pW2T   = (__half*)symaddr(g_W2T);
    __half* phH    = (__half*)symaddr(g_hH);
    __half* pWlmH  = (__half*)symaddr(g_WlmH);

    static bool attr_done = false;
    if (!attr_done) {
        cudaFuncSetAttribute((const void*)h16_gemm_kernel<0>,  cudaFuncAttributeMaxDynamicSharedMemorySize, H16_SMEM);
        cudaFuncSetAttribute((const void*)h16_gemm_kernel<1>,  cudaFuncAttributeMaxDynamicSharedMemorySize, H16_SMEM);
        cudaFuncSetAttribute((const void*)h16_gemm_kernel<2>,  cudaFuncAttributeMaxDynamicSharedMemorySize, H16_SMEM);
        cudaFuncSetAttribute((const void*)h16_gemm_kernel<18>, cudaFuncAttributeMaxDynamicSharedMemorySize, H16_SMEM);
        cudaFuncSetAttribute((const void*)lmhead_fp16_kernel,  cudaFuncAttributeMaxDynamicSharedMemorySize, GEMM_SMEM);
        attr_done = true;
    }

    embed_kernel<<<(M_ROWS * Cc + 255) / 256, 256>>>(x, tok, pos, ph);

    int qkvt_total = NLl * QKV_P * Cc;
    repack_qkvT_kernel<<<(qkvt_total + 255) / 256, 256>>>(Wq, Wk, Wv, pWqkvT);
    repack_bqkv_kernel<<<(NLl * QKV_P + 255) / 256, 256>>>(bq, bk, bv, pbqkv);
    dim3 tg(Cc / 32, Cc / 32, NLl);
    transpose_w_kernel<<<tg, dim3(32, 8)>>>(Wo, pWoT);
    transpose_w_kernel<<<tg, dim3(32, 8)>>>(W1, pW1T);
    transpose_w_kernel<<<tg, dim3(32, 8)>>>(W2, pW2T);
    transpose_wlm_kernel<<<dim3(V_PAD / 32, Cc / 32), dim3(32, 8)>>>(Wlm, pWlmH);

    dim3 g_qkv_grid(M_ROWS / 64, QKV_P / 128);   // (32, 9)
    dim3 g_c_grid(M_ROWS / 64, Cc / 128);        // (32, 3)

    for (int l = 0; l < NLl; l++) {
        ln_kernel<<<M_ROWS, 128>>>(ph, ln1g + l * Cc, ln1b + l * Cc, paH);

        h16_gemm_kernel<0><<<g_qkv_grid, 256, H16_SMEM>>>(
            paH, pWqkvT + (size_t)l * QKV_P * Cc, pbqkv + l * QKV_P, pqkvH, nullptr, QKV_P);

        scores_p_kernel<<<dim3(8, 8, BH), 256>>>(pqkvH, pP, ppsum);
        pv_fp16_kernel<<<dim3(8, BH), 256>>>(pP, pqkvH, ppsum, pattH);

        h16_gemm_kernel<2><<<g_c_grid, 256, H16_SMEM>>>(
            pattH, pWoT + (size_t)l * Cc * Cc, bo + l * Cc, ph, nullptr, Cc);

        ln_kernel<<<M_ROWS, 128>>>(ph, ln2g + l * Cc, ln2b + l * Cc, paH);

        h16_gemm_kernel<1><<<g_c_grid, 256, H16_SMEM>>>(
            paH, pW1T + (size_t)l * Cc * Cc, b1 + l * Cc, pmH, nullptr, Cc);

        if (l == NLl - 1) {
            h16_gemm_kernel<18><<<g_c_grid, 256, H16_SMEM>>>(
                pmH, pW2T + (size_t)l * Cc * Cc, b2 + l * Cc, ph, phH, Cc);
        } else {
            h16_gemm_kernel<2><<<g_c_grid, 256, H16_SMEM>>>(
                pmH, pW2T + (size_t)l * Cc * Cc, b2 + l * Cc, ph, nullptr, Cc);
        }
    }

    // LM head (fp16 tensor cores)
    lmhead_fp16_kernel<<<dim3(M_ROWS / 128, V_PAD / 128), 256, GEMM_SMEM>>>(
        phH, pWlmH, blm, out);
}

// round 8
// speedup vs baseline: 8.1882x; 1.0812x over previous
#include <cuda_runtime.h>
#include <cuda_fp16.h>
#include <cstdint>

// Problem constants
constexpr int Vv = 50257, Cc = 384, Tt = 1024, Hh = 6, HSs = 64, NLl = 3, Bb = 2;
constexpr int M_ROWS = Bb * Tt;   // 2048
constexpr int BH = Bb * Hh;       // 12
constexpr int V_PAD = 50304;      // 393 * 128
constexpr int QKV_P = 3 * Cc;     // 1152

// ---------------- scratch (__device__ globals; no allocation allowed) --------
__device__ float g_h[M_ROWS * Cc];
__device__ __half g_aH[M_ROWS * Cc];               // LN output fp16
__device__ __half g_qkvH[M_ROWS * QKV_P];          // fused QKV, fp16
__device__ __half g_attH[M_ROWS * Cc];             // PV output fp16
__device__ __half g_mH[M_ROWS * Cc];               // relu(W1) output fp16
__device__ __half g_P[(size_t)BH * Tt * Tt];       // unnormalized probs [bh][k][t]
__device__ float g_psum[BH * 8 * Tt];              // per-(bh,tb) row partial sums
__device__ __half g_WqkvT[NLl * QKV_P * Cc];       // [l][n][k] fp16
__device__ float g_bqkv[NLl * QKV_P];
__device__ __half g_WoT[NLl * Cc * Cc];
__device__ __half g_W1T[NLl * Cc * Cc];
__device__ __half g_W2T[NLl * Cc * Cc];
__device__ __half g_hH[M_ROWS * Cc];               // h as fp16 (LM head input)
__device__ __half g_WlmH[(size_t)V_PAD * Cc];      // Wlm^T as fp16 [n][k]

// ---------------- embedding --------------------------------------------------
__global__ void embed_kernel(const int* __restrict__ x, const float* __restrict__ tok,
                             const float* __restrict__ pos, float* __restrict__ h) {
    int i = blockIdx.x * blockDim.x + threadIdx.x;
    if (i >= M_ROWS * Cc) return;
    int row = i / Cc, c = i % Cc;
    int t = row % Tt;
    h[i] = tok[(size_t)x[row] * Cc + c] + pos[t * Cc + c];
}

// ---------------- repacks (one-time per call) --------------------------------
__global__ void repack_qkvT_kernel(const float* __restrict__ Wq, const float* __restrict__ Wk,
                                   const float* __restrict__ Wv, __half* __restrict__ O) {
    int i = blockIdx.x * blockDim.x + threadIdx.x;
    if (i >= NLl * QKV_P * Cc) return;
    int k = i % Cc;
    int n = (i / Cc) % QKV_P;
    int l = i / (Cc * QKV_P);
    int sel = n / Cc, h = (n % Cc) / HSs, s = n % HSs;
    const float* W = (sel == 0) ? Wq : (sel == 1) ? Wk : Wv;
    O[i] = __float2half(W[(((size_t)l * Hh + h) * Cc + k) * HSs + s]);
}

__global__ void repack_bqkv_kernel(const float* __restrict__ bq, const float* __restrict__ bk,
                                   const float* __restrict__ bv, float* __restrict__ O) {
    int i = blockIdx.x * blockDim.x + threadIdx.x;
    if (i >= NLl * QKV_P) return;
    int n = i % QKV_P, l = i / QKV_P;
    int sel = n / Cc, h = (n % Cc) / HSs, s = n % HSs;
    const float* B = (sel == 0) ? bq : (sel == 1) ? bk : bv;
    O[i] = B[((size_t)l * Hh + h) * HSs + s];
}

__global__ void transpose_w_kernel(const float* __restrict__ W, __half* __restrict__ WT) {
    __shared__ float t[32][33];
    int l = blockIdx.z;
    int n0 = blockIdx.x * 32, k0 = blockIdx.y * 32;
    const float* Wl = W + (size_t)l * Cc * Cc;
    __half* Tl = WT + (size_t)l * Cc * Cc;
    for (int dy = threadIdx.y; dy < 32; dy += 8)
        t[dy][threadIdx.x] = Wl[(size_t)(k0 + dy) * Cc + n0 + threadIdx.x];
    __syncthreads();
    for (int dy = threadIdx.y; dy < 32; dy += 8)
        Tl[(size_t)(n0 + dy) * Cc + k0 + threadIdx.x] = __float2half(t[threadIdx.x][dy]);
}

__global__ void transpose_wlm_kernel(const float* __restrict__ Wlm, __half* __restrict__ Bt) {
    __shared__ float tile[32][33];
    int n0 = blockIdx.x * 32, k0 = blockIdx.y * 32;
    for (int dy = threadIdx.y; dy < 32; dy += 8) {
        int k = k0 + dy, n = n0 + threadIdx.x;
        tile[dy][threadIdx.x] = (n < Vv) ? Wlm[(size_t)k * Vv + n] : 0.f;
    }
    __syncthreads();
    for (int dy = threadIdx.y; dy < 32; dy += 8) {
        int n = n0 + dy, k = k0 + threadIdx.x;
        Bt[(size_t)n * Cc + k] = __float2half(tile[threadIdx.x][dy]);
    }
}

// ---------------- layernorm (fp16 out) ---------------------------------------
__global__ void ln_kernel(const float* __restrict__ x, const float* __restrict__ g,
                          const float* __restrict__ b, __half* __restrict__ y) {
    int row = blockIdx.x;
    const float* xr = x + (size_t)row * Cc;
    __half* yr = y + (size_t)row * Cc;
    float lsum = 0.f, lsq = 0.f;
    for (int c = threadIdx.x; c < Cc; c += blockDim.x) {
        float v = xr[c]; lsum += v; lsq += v * v;
    }
    __shared__ float sh[64];
    int lane = threadIdx.x & 31, wid = threadIdx.x >> 5;
#pragma unroll
    for (int o = 16; o; o >>= 1) {
        lsum += __shfl_xor_sync(0xffffffffu, lsum, o);
        lsq  += __shfl_xor_sync(0xffffffffu, lsq,  o);
    }
    if (lane == 0) { sh[wid] = lsum; sh[wid + 32] = lsq; }
    __syncthreads();
    int nw = blockDim.x >> 5;
    if (threadIdx.x == 0) {
        float s = 0.f, q = 0.f;
        for (int w = 0; w < nw; w++) { s += sh[w]; q += sh[w + 32]; }
        sh[0] = s; sh[32] = q;
    }
    __syncthreads();
    float mu = sh[0] / Cc;
    float var = sh[32] / Cc - mu * mu;
    float rstd = rsqrtf(var + 1e-5f);
    for (int c = threadIdx.x; c < Cc; c += blockDim.x)
        yr[c] = __float2half((xr[c] - mu) * rstd * g[c] + b[c]);
}

// ---------------- common asm helpers ----------------------------------------
__device__ __forceinline__ uint32_t smem_u32(const void* p) {
    uint32_t a;
    asm("{ .reg .u64 t; cvta.to.shared.u64 t, %1; cvt.u32.u64 %0, t; }" : "=r"(a) : "l"(p));
    return a;
}
__device__ __forceinline__ void cp_async16(uint32_t saddr, const void* g) {
    asm volatile("cp.async.cg.shared.global [%0], [%1], 16;" :: "r"(saddr), "l"(g) : "memory");
}
__device__ __forceinline__ void cp_commit() {
    asm volatile("cp.async.commit_group;" ::: "memory");
}
template<int N>
__device__ __forceinline__ void cp_wait() {
    asm volatile("cp.async.wait_group %0;" :: "n"(N) : "memory");
}
__device__ __forceinline__ void ldm_x4(uint32_t* r, uint32_t addr) {
    asm volatile("ldmatrix.sync.aligned.m8n8.x4.shared.b16 {%0,%1,%2,%3}, [%4];"
                 : "=r"(r[0]), "=r"(r[1]), "=r"(r[2]), "=r"(r[3]) : "r"(addr));
}
__device__ __forceinline__ void ldm_x4_trans(uint32_t* r, uint32_t addr) {
    asm volatile("ldmatrix.sync.aligned.m8n8.x4.trans.shared.b16 {%0,%1,%2,%3}, [%4];"
                 : "=r"(r[0]), "=r"(r[1]), "=r"(r[2]), "=r"(r[3]) : "r"(addr));
}
__device__ __forceinline__ void mma_f16(float* c, const uint32_t* a, const uint32_t* b) {
    asm volatile(
        "mma.sync.aligned.m16n8k16.row.col.f32.f16.f16.f32 "
        "{%0,%1,%2,%3}, {%4,%5,%6,%7}, {%8,%9}, {%0,%1,%2,%3};"
        : "+f"(c[0]), "+f"(c[1]), "+f"(c[2]), "+f"(c[3])
        : "r"(a[0]), "r"(a[1]), "r"(a[2]), "r"(a[3]), "r"(b[0]), "r"(b[1]));
}

// ================= fp16 layer GEMM: CTA 64x128, K-tile 64 ====================
constexpr int H16_NKT = Cc / 64;      // 6
constexpr int H16_SMEM = 49152;       // 2 stages x (A 8KB + B 16KB)

template<int FLAGS>  // 1=relu, 2=accumulate fp32, 16=also fp16 aux copy
__global__ __launch_bounds__(256, 2)
void h16_gemm_kernel(const __half* __restrict__ A, const __half* __restrict__ Bt,
                     const float* __restrict__ bias, void* __restrict__ Cv,
                     __half* __restrict__ aux, int ldc) {
    extern __shared__ __half smh[];
    int tid = threadIdx.x;
    int warp = tid >> 5, lane = tid & 31;
    int wm = warp & 1, wn = warp >> 1;
    int grp = lane >> 2, tig = lane & 3;
    int lr = lane & 7, sub = lane >> 3;
    int m0 = blockIdx.x * 64, n0 = blockIdx.y * 128;
    const __half* Ab = A + (size_t)m0 * Cc;
    const __half* Bb = Bt + (size_t)n0 * Cc;
    uint32_t sbase = smem_u32(smh);

    auto issue = [&](int kt, int stage) {
        uint32_t as = sbase + stage * 24576u;
        uint32_t bs = as + 8192u;
#pragma unroll
        for (int it = 0; it < 2; it++) {
            int slot = tid + it * 256;
            int r = slot >> 3, c = slot & 7;
            uint32_t so = (uint32_t)(r * 128 + ((c ^ (r & 7)) << 4));
            cp_async16(as + so, Ab + (size_t)r * Cc + kt * 64 + c * 8);
        }
#pragma unroll
        for (int it = 0; it < 4; it++) {
            int slot = tid + it * 256;
            int r = slot >> 3, c = slot & 7;
            uint32_t so = (uint32_t)(r * 128 + ((c ^ (r & 7)) << 4));
            cp_async16(bs + so, Bb + (size_t)r * Cc + kt * 64 + c * 8);
        }
    };

    float acc[2][4][4];
#pragma unroll
    for (int i = 0; i < 2; i++)
#pragma unroll
        for (int j = 0; j < 4; j++)
#pragma unroll
            for (int q = 0; q < 4; q++) acc[i][j][q] = 0.f;

    int rowA[2], rowB[2];
#pragma unroll
    for (int fm = 0; fm < 2; fm++) rowA[fm] = wm * 32 + fm * 16 + (sub & 1) * 8 + lr;
#pragma unroll
    for (int p = 0; p < 2; p++) rowB[p] = wn * 32 + p * 16 + (sub >> 1) * 8 + lr;
    int chA = sub >> 1, chB = sub & 1;

    issue(0, 0);
    cp_commit();

#pragma unroll 1
    for (int kt = 0; kt < H16_NKT; kt++) {
        if (kt + 1 < H16_NKT) {
            issue(kt + 1, (kt + 1) & 1);
            cp_commit();
            cp_wait<1>();
        } else {
            cp_wait<0>();
        }
        __syncthreads();
        uint32_t as = sbase + (kt & 1) * 24576u;
        uint32_t bs = as + 8192u;
#pragma unroll
        for (int k16 = 0; k16 < 4; k16++) {
            int cb = k16 * 2;
            uint32_t afr[2][4];
#pragma unroll
            for (int fm = 0; fm < 2; fm++) {
                int r = rowA[fm];
                ldm_x4(afr[fm], as + r * 128 + (((cb + chA) ^ (r & 7)) << 4));
            }
            uint32_t bfr[2][4];
#pragma unroll
            for (int p = 0; p < 2; p++) {
                int r = rowB[p];
                ldm_x4(bfr[p], bs + r * 128 + (((cb + chB) ^ (r & 7)) << 4));
            }
#pragma unroll
            for (int fm = 0; fm < 2; fm++)
#pragma unroll
                for (int fn = 0; fn < 4; fn++)
                    mma_f16(acc[fm][fn], afr[fm], &bfr[fn >> 1][(fn & 1) * 2]);
        }
        __syncthreads();
    }

#pragma unroll
    for (int fm = 0; fm < 2; fm++) {
        int m_lo = m0 + wm * 32 + fm * 16 + grp;
        int m_hi = m_lo + 8;
#pragma unroll
        for (int fn = 0; fn < 4; fn++) {
            int n = n0 + wn * 32 + fn * 8 + tig * 2;
#pragma unroll
            for (int e = 0; e < 2; e++) {
                int nn = n + e;
                float bv = bias[nn];
                float v0 = acc[fm][fn][e]     + bv;
                float v1 = acc[fm][fn][e + 2] + bv;
                if (FLAGS & 1) { v0 = fmaxf(v0, 0.f); v1 = fmaxf(v1, 0.f); }
                if constexpr ((FLAGS & 2) != 0) {
                    float* C = (float*)Cv;
                    v0 += C[(size_t)m_lo * ldc + nn];
                    v1 += C[(size_t)m_hi * ldc + nn];
                    C[(size_t)m_lo * ldc + nn] = v0;
                    C[(size_t)m_hi * ldc + nn] = v1;
                    if constexpr ((FLAGS & 16) != 0) {
                        aux[(size_t)m_lo * ldc + nn] = __float2half(v0);
                        aux[(size_t)m_hi * ldc + nn] = __float2half(v1);
                    }
                } else {
                    __half* C = (__half*)Cv;
                    C[(size_t)m_lo * ldc + nn] = __float2half(v0);
                    C[(size_t)m_hi * ldc + nn] = __float2half(v1);
                }
            }
        }
    }
}

// ======== scores + exp + row-partial-sums (fp16 mma), P unnormalized =========
// grid: (36 lower-tri tile pairs, 1, BH)
__global__ __launch_bounds__(256)
void scores_p_kernel(const __half* __restrict__ qkvH, __half* __restrict__ P,
                     float* __restrict__ psum) {
    int q = blockIdx.x, bh = blockIdx.z;
    int tb = 0;
    while ((tb + 1) * (tb + 2) / 2 <= q) tb++;
    int kb = q - tb * (tb + 1) / 2;
    int b = bh / Hh, h = bh % Hh;
    int k0 = kb * 128, t0 = tb * 128;

    __shared__ __align__(16) __half ssm[128 * 136];
    __shared__ float sums[128][2];

    int tid = threadIdx.x;
    int warp = tid >> 5, lane = tid & 31;
    int wm = warp & 3, wn = warp >> 2;
    int grp = lane >> 2, tig = lane & 3;
    int lr = lane & 7, sub = lane >> 3;

    uint32_t sb = smem_u32(ssm);
    uint32_t Ksb = sb, Qsb = sb + 16384u;
    const __half* Kb_ = qkvH + (size_t)(b * Tt + k0) * QKV_P + Cc + h * HSs;
    const __half* Qb_ = qkvH + (size_t)(b * Tt + t0) * QKV_P + h * HSs;

#pragma unroll
    for (int it = 0; it < 4; it++) {
        int slot = tid + it * 256;
        int r = slot >> 3, c = slot & 7;
        uint32_t so = (uint32_t)(r * 128 + ((c ^ (r & 7)) << 4));
        cp_async16(Ksb + so, Kb_ + (size_t)r * QKV_P + c * 8);
        cp_async16(Qsb + so, Qb_ + (size_t)r * QKV_P + c * 8);
    }
    cp_commit();
    cp_wait<0>();
    __syncthreads();

    float acc[2][8][4];
#pragma unroll
    for (int i = 0; i < 2; i++)
#pragma unroll
        for (int j = 0; j < 8; j++)
#pragma unroll
            for (int q2 = 0; q2 < 4; q2++) acc[i][j][q2] = 0.f;

    int rowA[2], rowB[4];
#pragma unroll
    for (int fm = 0; fm < 2; fm++) rowA[fm] = wm * 32 + fm * 16 + (sub & 1) * 8 + lr;
#pragma unroll
    for (int p = 0; p < 4; p++) rowB[p] = wn * 64 + p * 16 + (sub >> 1) * 8 + lr;
    int chA = sub >> 1, chB = sub & 1;

#pragma unroll
    for (int k16 = 0; k16 < 4; k16++) {
        int cb = k16 * 2;
        uint32_t afr[2][4];
#pragma unroll
        for (int fm = 0; fm < 2; fm++) {
            int r = rowA[fm];
            ldm_x4(afr[fm], Ksb + r * 128 + (((cb + chA) ^ (r & 7)) << 4));
        }
        uint32_t bfr[4][4];
#pragma unroll
        for (int p = 0; p < 4; p++) {
            int r = rowB[p];
            ldm_x4(bfr[p], Qsb + r * 128 + (((cb + chB) ^ (r & 7)) << 4));
        }
#pragma unroll
        for (int fm = 0; fm < 2; fm++)
#pragma unroll
            for (int fn = 0; fn < 8; fn++)
                mma_f16(acc[fm][fn], afr[fm], &bfr[fn >> 1][(fn & 1) * 2]);
    }
    __syncthreads();

    float rp[2][2] = {{0.f, 0.f}, {0.f, 0.f}};
#pragma unroll
    for (int fm = 0; fm < 2; fm++) {
        int kl = wm * 32 + fm * 16 + grp;
        int kh = kl + 8;
#pragma unroll
        for (int fn = 0; fn < 8; fn++) {
            int tc = wn * 64 + fn * 8 + tig * 2;
#pragma unroll
            for (int e = 0; e < 2; e++) {
                int t = tc + e;
                float v0 = (t0 + t >= k0 + kl) ? __expf(0.125f * acc[fm][fn][e]) : 0.f;
                float v1 = (t0 + t >= k0 + kh) ? __expf(0.125f * acc[fm][fn][e + 2]) : 0.f;
                ssm[kl * 136 + t] = __float2half(v0);
                ssm[kh * 136 + t] = __float2half(v1);
                rp[fm][0] += v0;
                rp[fm][1] += v1;
            }
        }
    }
#pragma unroll
    for (int fm = 0; fm < 2; fm++)
#pragma unroll
        for (int hl = 0; hl < 2; hl++) {
            rp[fm][hl] += __shfl_xor_sync(0xffffffffu, rp[fm][hl], 1);
            rp[fm][hl] += __shfl_xor_sync(0xffffffffu, rp[fm][hl], 2);
        }
    if (tig == 0) {
#pragma unroll
        for (int fm = 0; fm < 2; fm++) {
            sums[wm * 32 + fm * 16 + grp][wn]     = rp[fm][0];
            sums[wm * 32 + fm * 16 + grp + 8][wn] = rp[fm][1];
        }
    }
    __syncthreads();

    __half* Pb = P + ((size_t)bh * Tt + k0) * Tt + t0;
#pragma unroll
    for (int i = 0; i < 8; i++) {
        int idx = tid + i * 256;
        int r = idx >> 4, c = idx & 15;
        uint4 v = *reinterpret_cast<const uint4*>(&ssm[r * 136 + c * 8]);
        *reinterpret_cast<uint4*>(Pb + (size_t)r * Tt + c * 8) = v;
    }
    if (tid < 128)
        psum[((size_t)bh * 8 + tb) * Tt + k0 + tid] = sums[tid][0] + sums[tid][1];
}

// ---------------- PV via fp16 mma: cp.async P + ldmatrix.trans ----------------
// P staged in natural [k][t] layout (64 x 128, 256B rows, per-128B swizzle);
// A fragments produced by ldmatrix.x4.trans. V scaled+transposed as before.
__global__ __launch_bounds__(256)
void pv_fp16_kernel(const __half* __restrict__ P, const __half* __restrict__ qkvH,
                    const float* __restrict__ psum, __half* __restrict__ att) {
    int tb = blockIdx.x, bh = blockIdx.y;
    int b = bh / Hh, h = bh % Hh;
    int t0 = tb * 128;

    __shared__ __align__(16) __half Pt[64 * 128];  // [k][t] 256B rows
    __shared__ __align__(16) __half Vt[64 * 64];   // [s][k] 128B rows
    __shared__ float invs[1024];

    int tid = threadIdx.x;
    int warp = tid >> 5, lane = tid & 31;
    int wm = warp & 3, wn = warp >> 2;
    int grp = lane >> 2, tig = lane & 3;
    int lr = lane & 7, sub = lane >> 3;

    uint32_t Ptb = smem_u32(Pt), Vtb = smem_u32(Vt);

    int nk = 2 * (tb + 1);
    int Kext = nk * 64;
    for (int i = tid; i < Kext; i += 256) {
        int tb0 = i >> 7;
        float s = 0.f;
        for (int t2 = tb0; t2 < 8; t2++)
            s += psum[((size_t)bh * 8 + t2) * Tt + i];
        invs[i] = 1.f / s;
    }

    float acc[2][4][4];
#pragma unroll
    for (int i = 0; i < 2; i++)
#pragma unroll
        for (int j = 0; j < 4; j++)
#pragma unroll
            for (int q = 0; q < 4; q++) acc[i][j][q] = 0.f;

    int rowB[2];
#pragma unroll
    for (int p = 0; p < 2; p++) rowB[p] = wn * 32 + p * 16 + (sub >> 1) * 8 + lr;
    int chB = sub & 1;
    // trans-A addressing components (per-thread, constant over k16 via krow base)
    int tcolA = wm * 32 + (sub & 1) * 8;       // + fm*16 at use
    int krowA = (sub >> 1) * 8 + lr;           // + k16*16 at use

#pragma unroll 1
    for (int kt = 0; kt < nk; kt++) {
        int k0 = kt * 64;
        __syncthreads();
        // cp.async P tile: 64 rows x 16 chunks (16B), swizzled per 128B half-row
        const __half* Pg = P + ((size_t)bh * Tt + k0) * Tt + t0;
#pragma unroll
        for (int i = 0; i < 4; i++) {
            int idx = tid + i * 256;
            int r = idx >> 4, c = idx & 15;
            uint32_t so = (uint32_t)(r * 256 + ((c ^ (r & 7)) << 4));
            cp_async16(Ptb + so, Pg + (size_t)r * Tt + c * 8);
        }
        cp_commit();
        // V tile [64 k][64 s]: scale by inv[k], transpose -> Vt[s][k]
        const __half* Vg = qkvH + (size_t)(b * Tt + k0) * QKV_P + 2 * Cc + h * HSs;
#pragma unroll
        for (int i = 0; i < 8; i++) {
            int idx = tid + i * 256;
            int kk = idx >> 5, sp = idx & 31;
            uint32_t v = *reinterpret_cast<const uint32_t*>(Vg + (size_t)kk * QKV_P + sp * 2);
            float iv = invs[k0 + kk];
            __half2 h2 = *(const __half2*)&v;
            __half s0 = __float2half(__half2float(h2.x) * iv);
            __half s1 = __float2half(__half2float(h2.y) * iv);
            int s_ = sp * 2;
            Vt[s_ * 64 + ((((kk >> 3) ^ (s_ & 7)) << 3) | (kk & 7))] = s0;
            s_++;
            Vt[s_ * 64 + ((((kk >> 3) ^ (s_ & 7)) << 3) | (kk & 7))] = s1;
        }
        cp_wait<0>();
        __syncthreads();
#pragma unroll
        for (int k16 = 0; k16 < 4; k16++) {
            uint32_t afr[2][4];
#pragma unroll
            for (int fm = 0; fm < 2; fm++) {
                int krow = k16 * 16 + krowA;
                int tcol = tcolA + fm * 16;
                uint32_t addr = Ptb + krow * 256 + ((((tcol >> 3) ^ (krow & 7)) << 4));
                ldm_x4_trans(afr[fm], addr);
            }
            int cb = k16 * 2;
            uint32_t bfr[2][4];
#pragma unroll
            for (int p = 0; p < 2; p++) {
                int r = rowB[p];
                ldm_x4(bfr[p], Vtb + r * 128 + (((cb + chB) ^ (r & 7)) << 4));
            }
#pragma unroll
            for (int fm = 0; fm < 2; fm++)
#pragma unroll
                for (int fn = 0; fn < 4; fn++)
                    mma_f16(acc[fm][fn], afr[fm], &bfr[fn >> 1][(fn & 1) * 2]);
        }
    }

#pragma unroll
    for (int fm = 0; fm < 2; fm++) {
        int m_lo = t0 + wm * 32 + fm * 16 + grp;
        int m_hi = m_lo + 8;
#pragma unroll
        for (int fn = 0; fn < 4; fn++) {
            int s = wn * 32 + fn * 8 + tig * 2;
#pragma unroll
            for (int e = 0; e < 2; e++) {
                att[(size_t)(b * Tt + m_lo) * Cc + h * HSs + s + e] = __float2half(acc[fm][fn][e]);
                att[(size_t)(b * Tt + m_hi) * Cc + h * HSs + s + e] = __float2half(acc[fm][fn][e + 2]);
            }
        }
    }
}

// ================= fp16 LM head ==============================================
constexpr int LM_NKT = Cc / 64;  // 6

__global__ __launch_bounds__(256, 2)
void lmhead_fp16_kernel(const __half* __restrict__ A, const __half* __restrict__ Bt,
                        const float* __restrict__ bias, float* __restrict__ out) {
    extern __shared__ __half smh[];
    int tid = threadIdx.x;
    int warp = tid >> 5, lane = tid & 31;
    int wm = warp & 3, wn = warp >> 2;
    int grp = lane >> 2, tig = lane & 3;
    int lr = lane & 7, sub = lane >> 3;
    int m0 = blockIdx.x * 128, n0 = blockIdx.y * 128;
    const __half* Ab = A + (size_t)m0 * Cc;
    const __half* Bb = Bt + (size_t)n0 * Cc;

    uint32_t sbase = smem_u32(smh);

    auto issue = [&](int kt, int stage) {
        uint32_t as = sbase + stage * 32768u;
        uint32_t bs = as + 16384u;
#pragma unroll
        for (int it = 0; it < 4; it++) {
            int slot = tid + it * 256;
            int r = slot >> 3, c = slot & 7;
            uint32_t so = (uint32_t)(r * 128 + ((c ^ (r & 7)) << 4));
            cp_async16(as + so, Ab + (size_t)r * Cc + kt * 64 + c * 8);
            cp_async16(bs + so, Bb + (size_t)r * Cc + kt * 64 + c * 8);
        }
    };

    float acc[2][8][4];
#pragma unroll
    for (int i = 0; i < 2; i++)
#pragma unroll
        for (int j = 0; j < 8; j++)
#pragma unroll
            for (int q = 0; q < 4; q++) acc[i][j][q] = 0.f;

    int rowA[2], rowB[4];
#pragma unroll
    for (int fm = 0; fm < 2; fm++) rowA[fm] = wm * 32 + fm * 16 + (sub & 1) * 8 + lr;
#pragma unroll
    for (int p = 0; p < 4; p++) rowB[p] = wn * 64 + p * 16 + (sub >> 1) * 8 + lr;
    int chA = sub >> 1, chB = sub & 1;

    issue(0, 0);
    cp_commit();

#pragma unroll 1
    for (int kt = 0; kt < LM_NKT; kt++) {
        if (kt + 1 < LM_NKT) {
            issue(kt + 1, (kt + 1) & 1);
            cp_commit();
            cp_wait<1>();
        } else {
            cp_wait<0>();
        }
        __syncthreads();
        uint32_t as = sbase + (kt & 1) * 32768u;
        uint32_t bs = as + 16384u;
#pragma unroll
        for (int k16 = 0; k16 < 4; k16++) {
            int cb = k16 * 2;
            uint32_t afr[2][4];
#pragma unroll
            for (int fm = 0; fm < 2; fm++) {
                int r = rowA[fm];
                ldm_x4(afr[fm], as + r * 128 + (((cb + chA) ^ (r & 7)) << 4));
            }
            uint32_t bfr[4][4];
#pragma unroll
            for (int p = 0; p < 4; p++) {
                int r = rowB[p];
                ldm_x4(bfr[p], bs + r * 128 + (((cb + chB) ^ (r & 7)) << 4));
            }
#pragma unroll
            for (int fm = 0; fm < 2; fm++)
#pragma unroll
                for (int fn = 0; fn < 8; fn++)
                    mma_f16(acc[fm][fn], afr[fm], &bfr[fn >> 1][(fn & 1) * 2]);
        }
        __syncthreads();
    }

#pragma unroll
    for (int fm = 0; fm < 2; fm++) {
        int m_lo = m0 + wm * 32 + fm * 16 + grp;
        int m_hi = m_lo + 8;
#pragma unroll
        for (int fn = 0; fn < 8; fn++) {
            int n = n0 + wn * 64 + fn * 8 + tig * 2;
#pragma unroll
            for (int e = 0; e < 2; e++) {
                int nn = n + e;
                if (nn >= Vv) continue;
                float bv = bias[nn];
                out[(size_t)m_lo * Vv + nn] = acc[fm][fn][e]     + bv;
                out[(size_t)m_hi * Vv + nn] = acc[fm][fn][e + 2] + bv;
            }
        }
    }
}

// ---------------- host launcher ---------------------------------------------
static float* symaddr(const void* s) {
    void* p = nullptr;
    cudaGetSymbolAddress(&p, s);
    return (float*)p;
}

constexpr int GEMM_SMEM = 65536;

extern "C" void kernel_launch(void* const* d_in, const int* in_sizes, int n_in,
                              void* d_out, int out_size) {
    const int*   x    = (const int*)d_in[0];
    const float* tok  = (const float*)d_in[1];
    const float* pos  = (const float*)d_in[2];
    const float* Wq   = (const float*)d_in[3];
    const float* bq   = (const float*)d_in[4];
    const float* Wk   = (const float*)d_in[5];
    const float* bk   = (const float*)d_in[6];
    const float* Wv   = (const float*)d_in[7];
    const float* bv   = (const float*)d_in[8];
    const float* Wo   = (const float*)d_in[9];
    const float* bo   = (const float*)d_in[10];
    const float* ln1g = (const float*)d_in[11];
    const float* ln1b = (const float*)d_in[12];
    const float* W1   = (const float*)d_in[13];
    const float* b1   = (const float*)d_in[14];
    const float* W2   = (const float*)d_in[15];
    const float* b2   = (const float*)d_in[16];
    const float* ln2g = (const float*)d_in[17];
    const float* ln2b = (const float*)d_in[18];
    const float* Wlm  = (const float*)d_in[19];
    const float* blm  = (const float*)d_in[20];
    float* out = (float*)d_out;

    float* ph      = symaddr(g_h);
    __half* paH    = (__half*)symaddr(g_aH);
    __half* pqkvH  = (__half*)symaddr(g_qkvH);
    __half* pattH  = (__half*)symaddr(g_attH);
    __half* pmH    = (__half*)symaddr(g_mH);
    __half* pP     = (__half*)symaddr(g_P);
    float* ppsum   = symaddr(g_psum);
    __half* pWqkvT = (__half*)symaddr(g_WqkvT);
    float* pbqkv   = symaddr(g_bqkv);
    __half* pWoT   = (__half*)symaddr(g_WoT);
    __half* pW1T   = (__half*)symaddr(g_W1T);
    __half* pW2T   = (__half*)symaddr(g_W2T);
    __half* phH    = (__half*)symaddr(g_hH);
    __half* pWlmH  = (__half*)symaddr(g_WlmH);

    static bool attr_done = false;
    if (!attr_done) {
        cudaFuncSetAttribute((const void*)h16_gemm_kernel<0>,  cudaFuncAttributeMaxDynamicSharedMemorySize, H16_SMEM);
        cudaFuncSetAttribute((const void*)h16_gemm_kernel<1>,  cudaFuncAttributeMaxDynamicSharedMemorySize, H16_SMEM);
        cudaFuncSetAttribute((const void*)h16_gemm_kernel<2>,  cudaFuncAttributeMaxDynamicSharedMemorySize, H16_SMEM);
        cudaFuncSetAttribute((const void*)h16_gemm_kernel<18>, cudaFuncAttributeMaxDynamicSharedMemorySize, H16_SMEM);
        cudaFuncSetAttribute((const void*)lmhead_fp16_kernel,  cudaFuncAttributeMaxDynamicSharedMemorySize, GEMM_SMEM);
        attr_done = true;
    }

    embed_kernel<<<(M_ROWS * Cc + 255) / 256, 256>>>(x, tok, pos, ph);

    int qkvt_total = NLl * QKV_P * Cc;
    repack_qkvT_kernel<<<(qkvt_total + 255) / 256, 256>>>(Wq, Wk, Wv, pWqkvT);
    repack_bqkv_kernel<<<(NLl * QKV_P + 255) / 256, 256>>>(bq, bk, bv, pbqkv);
    dim3 tg(Cc / 32, Cc / 32, NLl);
    transpose_w_kernel<<<tg, dim3(32, 8)>>>(Wo, pWoT);
    transpose_w_kernel<<<tg, dim3(32, 8)>>>(W1, pW1T);
    transpose_w_kernel<<<tg, dim3(32, 8)>>>(W2, pW2T);
    transpose_wlm_kernel<<<dim3(V_PAD / 32, Cc / 32), dim3(32, 8)>>>(Wlm, pWlmH);

    dim3 g_qkv_grid(M_ROWS / 64, QKV_P / 128);   // (32, 9)
    dim3 g_c_grid(M_ROWS / 64, Cc / 128);        // (32, 3)

    for (int l = 0; l < NLl; l++) {
        ln_kernel<<<M_ROWS, 128>>>(ph, ln1g + l * Cc, ln1b + l * Cc, paH);

        h16_gemm_kernel<0><<<g_qkv_grid, 256, H16_SMEM>>>(
            paH, pWqkvT + (size_t)l * QKV_P * Cc, pbqkv + l * QKV_P, pqkvH, nullptr, QKV_P);

        scores_p_kernel<<<dim3(36, 1, BH), 256>>>(pqkvH, pP, ppsum);
        pv_fp16_kernel<<<dim3(8, BH), 256>>>(pP, pqkvH, ppsum, pattH);

        h16_gemm_kernel<2><<<g_c_grid, 256, H16_SMEM>>>(
            pattH, pWoT + (size_t)l * Cc * Cc, bo + l * Cc, ph, nullptr, Cc);

        ln_kernel<<<M_ROWS, 128>>>(ph, ln2g + l * Cc, ln2b + l * Cc, paH);

        h16_gemm_kernel<1><<<g_c_grid, 256, H16_SMEM>>>(
            paH, pW1T + (size_t)l * Cc * Cc, b1 + l * Cc, pmH, nullptr, Cc);

        if (l == NLl - 1) {
            h16_gemm_kernel<18><<<g_c_grid, 256, H16_SMEM>>>(
                pmH, pW2T + (size_t)l * Cc * Cc, b2 + l * Cc, ph, phH, Cc);
        } else {
            h16_gemm_kernel<2><<<g_c_grid, 256, H16_SMEM>>>(
                pmH, pW2T + (size_t)l * Cc * Cc, b2 + l * Cc, ph, nullptr, Cc);
        }
    }

    // LM head (fp16 tensor cores)
    lmhead_fp16_kernel<<<dim3(M_ROWS / 128, V_PAD / 128), 256, GEMM_SMEM>>>(
        phH, pWlmH, blm, out);
}

// round 10
// speedup vs baseline: 8.5981x; 1.0501x over previous
#include <cuda_runtime.h>
#include <cuda_fp16.h>
#include <cstdint>

// Problem constants
constexpr int Vv = 50257, Cc = 384, Tt = 1024, Hh = 6, HSs = 64, NLl = 3, Bb = 2;
constexpr int M_ROWS = Bb * Tt;   // 2048
constexpr int BH = Bb * Hh;       // 12
constexpr int V_PAD = 50304;      // 393 * 128
constexpr int QKV_P = 3 * Cc;     // 1152

// ---------------- scratch (__device__ globals; no allocation allowed) --------
__device__ float g_h[M_ROWS * Cc];
__device__ __half g_aH[M_ROWS * Cc];               // LN output fp16
__device__ __half g_qkvH[M_ROWS * QKV_P];          // fused QKV, fp16
__device__ __half g_attH[M_ROWS * Cc];             // PV output fp16
__device__ __half g_mH[M_ROWS * Cc];               // relu(W1) output fp16
__device__ __half g_P[(size_t)BH * Tt * Tt];       // unnormalized probs [bh][k][t]
__device__ float g_psum[BH * 8 * Tt];              // per-(bh,tb) row partial sums
__device__ __half g_WqkvT[NLl * QKV_P * Cc];       // [l][n][k] fp16
__device__ float g_bqkv[NLl * QKV_P];
__device__ __half g_WoT[NLl * Cc * Cc];
__device__ __half g_W1T[NLl * Cc * Cc];
__device__ __half g_W2T[NLl * Cc * Cc];
__device__ __half g_hH[M_ROWS * Cc];               // h as fp16 (LM head input)
__device__ __half g_WlmH[(size_t)V_PAD * Cc];      // Wlm^T as fp16 [n][k]

// ---------------- embedding --------------------------------------------------
__global__ void embed_kernel(const int* __restrict__ x, const float* __restrict__ tok,
                             const float* __restrict__ pos, float* __restrict__ h) {
    int i = blockIdx.x * blockDim.x + threadIdx.x;
    if (i >= M_ROWS * Cc) return;
    int row = i / Cc, c = i % Cc;
    int t = row % Tt;
    h[i] = tok[(size_t)x[row] * Cc + c] + pos[t * Cc + c];
}

// ---------------- repacks (one-time per call) --------------------------------
__global__ void repack_qkvT_kernel(const float* __restrict__ Wq, const float* __restrict__ Wk,
                                   const float* __restrict__ Wv, __half* __restrict__ O) {
    int i = blockIdx.x * blockDim.x + threadIdx.x;
    if (i >= NLl * QKV_P * Cc) return;
    int k = i % Cc;
    int n = (i / Cc) % QKV_P;
    int l = i / (Cc * QKV_P);
    int sel = n / Cc, h = (n % Cc) / HSs, s = n % HSs;
    const float* W = (sel == 0) ? Wq : (sel == 1) ? Wk : Wv;
    O[i] = __float2half(W[(((size_t)l * Hh + h) * Cc + k) * HSs + s]);
}

__global__ void repack_bqkv_kernel(const float* __restrict__ bq, const float* __restrict__ bk,
                                   const float* __restrict__ bv, float* __restrict__ O) {
    int i = blockIdx.x * blockDim.x + threadIdx.x;
    if (i >= NLl * QKV_P) return;
    int n = i % QKV_P, l = i / QKV_P;
    int sel = n / Cc, h = (n % Cc) / HSs, s = n % HSs;
    const float* B = (sel == 0) ? bq : (sel == 1) ? bk : bv;
    O[i] = B[((size_t)l * Hh + h) * HSs + s];
}

__global__ void transpose_w_kernel(const float* __restrict__ W, __half* __restrict__ WT) {
    __shared__ float t[32][33];
    int l = blockIdx.z;
    int n0 = blockIdx.x * 32, k0 = blockIdx.y * 32;
    const float* Wl = W + (size_t)l * Cc * Cc;
    __half* Tl = WT + (size_t)l * Cc * Cc;
    for (int dy = threadIdx.y; dy < 32; dy += 8)
        t[dy][threadIdx.x] = Wl[(size_t)(k0 + dy) * Cc + n0 + threadIdx.x];
    __syncthreads();
    for (int dy = threadIdx.y; dy < 32; dy += 8)
        Tl[(size_t)(n0 + dy) * Cc + k0 + threadIdx.x] = __float2half(t[threadIdx.x][dy]);
}

__global__ void transpose_wlm_kernel(const float* __restrict__ Wlm, __half* __restrict__ Bt) {
    __shared__ float tile[32][33];
    int n0 = blockIdx.x * 32, k0 = blockIdx.y * 32;
    for (int dy = threadIdx.y; dy < 32; dy += 8) {
        int k = k0 + dy, n = n0 + threadIdx.x;
        tile[dy][threadIdx.x] = (n < Vv) ? Wlm[(size_t)k * Vv + n] : 0.f;
    }
    __syncthreads();
    for (int dy = threadIdx.y; dy < 32; dy += 8) {
        int n = n0 + dy, k = k0 + threadIdx.x;
        Bt[(size_t)n * Cc + k] = __float2half(tile[threadIdx.x][dy]);
    }
}

// ---------------- layernorm (fp16 out) ---------------------------------------
__global__ void ln_kernel(const float* __restrict__ x, const float* __restrict__ g,
                          const float* __restrict__ b, __half* __restrict__ y) {
    int row = blockIdx.x;
    const float* xr = x + (size_t)row * Cc;
    __half* yr = y + (size_t)row * Cc;
    float lsum = 0.f, lsq = 0.f;
    for (int c = threadIdx.x; c < Cc; c += blockDim.x) {
        float v = xr[c]; lsum += v; lsq += v * v;
    }
    __shared__ float sh[64];
    int lane = threadIdx.x & 31, wid = threadIdx.x >> 5;
#pragma unroll
    for (int o = 16; o; o >>= 1) {
        lsum += __shfl_xor_sync(0xffffffffu, lsum, o);
        lsq  += __shfl_xor_sync(0xffffffffu, lsq,  o);
    }
    if (lane == 0) { sh[wid] = lsum; sh[wid + 32] = lsq; }
    __syncthreads();
    int nw = blockDim.x >> 5;
    if (threadIdx.x == 0) {
        float s = 0.f, q = 0.f;
        for (int w = 0; w < nw; w++) { s += sh[w]; q += sh[w + 32]; }
        sh[0] = s; sh[32] = q;
    }
    __syncthreads();
    float mu = sh[0] / Cc;
    float var = sh[32] / Cc - mu * mu;
    float rstd = rsqrtf(var + 1e-5f);
    for (int c = threadIdx.x; c < Cc; c += blockDim.x)
        yr[c] = __float2half((xr[c] - mu) * rstd * g[c] + b[c]);
}

// ---------------- common asm helpers ----------------------------------------
__device__ __forceinline__ uint32_t smem_u32(const void* p) {
    uint32_t a;
    asm("{ .reg .u64 t; cvta.to.shared.u64 t, %1; cvt.u32.u64 %0, t; }" : "=r"(a) : "l"(p));
    return a;
}
__device__ __forceinline__ void cp_async16(uint32_t saddr, const void* g) {
    asm volatile("cp.async.cg.shared.global [%0], [%1], 16;" :: "r"(saddr), "l"(g) : "memory");
}
__device__ __forceinline__ void cp_commit() {
    asm volatile("cp.async.commit_group;" ::: "memory");
}
template<int N>
__device__ __forceinline__ void cp_wait() {
    asm volatile("cp.async.wait_group %0;" :: "n"(N) : "memory");
}
__device__ __forceinline__ void ldm_x4(uint32_t* r, uint32_t addr) {
    asm volatile("ldmatrix.sync.aligned.m8n8.x4.shared.b16 {%0,%1,%2,%3}, [%4];"
                 : "=r"(r[0]), "=r"(r[1]), "=r"(r[2]), "=r"(r[3]) : "r"(addr));
}
__device__ __forceinline__ void ldm_x4_trans(uint32_t* r, uint32_t addr) {
    asm volatile("ldmatrix.sync.aligned.m8n8.x4.trans.shared.b16 {%0,%1,%2,%3}, [%4];"
                 : "=r"(r[0]), "=r"(r[1]), "=r"(r[2]), "=r"(r[3]) : "r"(addr));
}
__device__ __forceinline__ void mma_f16(float* c, const uint32_t* a, const uint32_t* b) {
    asm volatile(
        "mma.sync.aligned.m16n8k16.row.col.f32.f16.f16.f32 "
        "{%0,%1,%2,%3}, {%4,%5,%6,%7}, {%8,%9}, {%0,%1,%2,%3};"
        : "+f"(c[0]), "+f"(c[1]), "+f"(c[2]), "+f"(c[3])
        : "r"(a[0]), "r"(a[1]), "r"(a[2]), "r"(a[3]), "r"(b[0]), "r"(b[1]));
}

// ================= fp16 layer GEMM: CTA 64x128, K-tile 64, 3-stage ===========
constexpr int H16_NKT = Cc / 64;      // 6
constexpr int H16_STAGE = 24576;      // A 8KB + B 16KB
constexpr int H16_SMEM = 3 * H16_STAGE;  // 72KB

template<int FLAGS>  // 1=relu, 2=accumulate fp32, 16=also fp16 aux copy
__global__ __launch_bounds__(256, 2)
void h16_gemm_kernel(const __half* __restrict__ A, const __half* __restrict__ Bt,
                     const float* __restrict__ bias, void* __restrict__ Cv,
                     __half* __restrict__ aux, int ldc) {
    extern __shared__ __half smh[];
    int tid = threadIdx.x;
    int warp = tid >> 5, lane = tid & 31;
    int wm = warp & 1, wn = warp >> 1;
    int grp = lane >> 2, tig = lane & 3;
    int lr = lane & 7, sub = lane >> 3;
    int m0 = blockIdx.x * 64, n0 = blockIdx.y * 128;
    const __half* Ab = A + (size_t)m0 * Cc;
    const __half* Bb = Bt + (size_t)n0 * Cc;
    uint32_t sbase = smem_u32(smh);

    auto issue = [&](int kt, int stage) {
        uint32_t as = sbase + stage * (uint32_t)H16_STAGE;
        uint32_t bs = as + 8192u;
#pragma unroll
        for (int it = 0; it < 2; it++) {
            int slot = tid + it * 256;
            int r = slot >> 3, c = slot & 7;
            uint32_t so = (uint32_t)(r * 128 + ((c ^ (r & 7)) << 4));
            cp_async16(as + so, Ab + (size_t)r * Cc + kt * 64 + c * 8);
        }
#pragma unroll
        for (int it = 0; it < 4; it++) {
            int slot = tid + it * 256;
            int r = slot >> 3, c = slot & 7;
            uint32_t so = (uint32_t)(r * 128 + ((c ^ (r & 7)) << 4));
            cp_async16(bs + so, Bb + (size_t)r * Cc + kt * 64 + c * 8);
        }
    };

    float acc[2][4][4];
#pragma unroll
    for (int i = 0; i < 2; i++)
#pragma unroll
        for (int j = 0; j < 4; j++)
#pragma unroll
            for (int q = 0; q < 4; q++) acc[i][j][q] = 0.f;

    int rowA[2], rowB[2];
#pragma unroll
    for (int fm = 0; fm < 2; fm++) rowA[fm] = wm * 32 + fm * 16 + (sub & 1) * 8 + lr;
#pragma unroll
    for (int p = 0; p < 2; p++) rowB[p] = wn * 32 + p * 16 + (sub >> 1) * 8 + lr;
    int chA = sub >> 1, chB = sub & 1;

    issue(0, 0); cp_commit();
    issue(1, 1); cp_commit();

    int stage = 0;
#pragma unroll 1
    for (int kt = 0; kt < H16_NKT; kt++) {
        if (kt + 1 < H16_NKT) { cp_wait<1>(); } else { cp_wait<0>(); }  // drain fix
        __syncthreads();
        if (kt + 2 < H16_NKT) {
            int ns = stage + 2; if (ns >= 3) ns -= 3;
            issue(kt + 2, ns);
            cp_commit();
        }
        uint32_t as = sbase + stage * (uint32_t)H16_STAGE;
        uint32_t bs = as + 8192u;
#pragma unroll
        for (int k16 = 0; k16 < 4; k16++) {
            int cb = k16 * 2;
            uint32_t afr[2][4];
#pragma unroll
            for (int fm = 0; fm < 2; fm++) {
                int r = rowA[fm];
                ldm_x4(afr[fm], as + r * 128 + (((cb + chA) ^ (r & 7)) << 4));
            }
            uint32_t bfr[2][4];
#pragma unroll
            for (int p = 0; p < 2; p++) {
                int r = rowB[p];
                ldm_x4(bfr[p], bs + r * 128 + (((cb + chB) ^ (r & 7)) << 4));
            }
#pragma unroll
            for (int fm = 0; fm < 2; fm++)
#pragma unroll
                for (int fn = 0; fn < 4; fn++)
                    mma_f16(acc[fm][fn], afr[fm], &bfr[fn >> 1][(fn & 1) * 2]);
        }
        if (++stage >= 3) stage = 0;
    }

#pragma unroll
    for (int fm = 0; fm < 2; fm++) {
        int m_lo = m0 + wm * 32 + fm * 16 + grp;
        int m_hi = m_lo + 8;
#pragma unroll
        for (int fn = 0; fn < 4; fn++) {
            int n = n0 + wn * 32 + fn * 8 + tig * 2;
#pragma unroll
            for (int e = 0; e < 2; e++) {
                int nn = n + e;
                float bv = bias[nn];
                float v0 = acc[fm][fn][e]     + bv;
                float v1 = acc[fm][fn][e + 2] + bv;
                if (FLAGS & 1) { v0 = fmaxf(v0, 0.f); v1 = fmaxf(v1, 0.f); }
                if constexpr ((FLAGS & 2) != 0) {
                    float* C = (float*)Cv;
                    v0 += C[(size_t)m_lo * ldc + nn];
                    v1 += C[(size_t)m_hi * ldc + nn];
                    C[(size_t)m_lo * ldc + nn] = v0;
                    C[(size_t)m_hi * ldc + nn] = v1;
                    if constexpr ((FLAGS & 16) != 0) {
                        aux[(size_t)m_lo * ldc + nn] = __float2half(v0);
                        aux[(size_t)m_hi * ldc + nn] = __float2half(v1);
                    }
                } else {
                    __half* C = (__half*)Cv;
                    C[(size_t)m_lo * ldc + nn] = __float2half(v0);
                    C[(size_t)m_hi * ldc + nn] = __float2half(v1);
                }
            }
        }
    }
}

// ======== scores + exp + row-partial-sums (fp16 mma), P unnormalized =========
// grid: (36 lower-tri tile pairs, 1, BH)
__global__ __launch_bounds__(256)
void scores_p_kernel(const __half* __restrict__ qkvH, __half* __restrict__ P,
                     float* __restrict__ psum) {
    int q = blockIdx.x, bh = blockIdx.z;
    int tb = 0;
    while ((tb + 1) * (tb + 2) / 2 <= q) tb++;
    int kb = q - tb * (tb + 1) / 2;
    int b = bh / Hh, h = bh % Hh;
    int k0 = kb * 128, t0 = tb * 128;

    __shared__ __align__(16) __half ssm[128 * 136];
    __shared__ float sums[128][2];

    int tid = threadIdx.x;
    int warp = tid >> 5, lane = tid & 31;
    int wm = warp & 3, wn = warp >> 2;
    int grp = lane >> 2, tig = lane & 3;
    int lr = lane & 7, sub = lane >> 3;

    uint32_t sb = smem_u32(ssm);
    uint32_t Ksb = sb, Qsb = sb + 16384u;
    const __half* Kb_ = qkvH + (size_t)(b * Tt + k0) * QKV_P + Cc + h * HSs;
    const __half* Qb_ = qkvH + (size_t)(b * Tt + t0) * QKV_P + h * HSs;

#pragma unroll
    for (int it = 0; it < 4; it++) {
        int slot = tid + it * 256;
        int r = slot >> 3, c = slot & 7;
        uint32_t so = (uint32_t)(r * 128 + ((c ^ (r & 7)) << 4));
        cp_async16(Ksb + so, Kb_ + (size_t)r * QKV_P + c * 8);
        cp_async16(Qsb + so, Qb_ + (size_t)r * QKV_P + c * 8);
    }
    cp_commit();
    cp_wait<0>();
    __syncthreads();

    float acc[2][8][4];
#pragma unroll
    for (int i = 0; i < 2; i++)
#pragma unroll
        for (int j = 0; j < 8; j++)
#pragma unroll
            for (int q2 = 0; q2 < 4; q2++) acc[i][j][q2] = 0.f;

    int rowA[2], rowB[4];
#pragma unroll
    for (int fm = 0; fm < 2; fm++) rowA[fm] = wm * 32 + fm * 16 + (sub & 1) * 8 + lr;
#pragma unroll
    for (int p = 0; p < 4; p++) rowB[p] = wn * 64 + p * 16 + (sub >> 1) * 8 + lr;
    int chA = sub >> 1, chB = sub & 1;

#pragma unroll
    for (int k16 = 0; k16 < 4; k16++) {
        int cb = k16 * 2;
        uint32_t afr[2][4];
#pragma unroll
        for (int fm = 0; fm < 2; fm++) {
            int r = rowA[fm];
            ldm_x4(afr[fm], Ksb + r * 128 + (((cb + chA) ^ (r & 7)) << 4));
        }
        uint32_t bfr[4][4];
#pragma unroll
        for (int p = 0; p < 4; p++) {
            int r = rowB[p];
            ldm_x4(bfr[p], Qsb + r * 128 + (((cb + chB) ^ (r & 7)) << 4));
        }
#pragma unroll
        for (int fm = 0; fm < 2; fm++)
#pragma unroll
            for (int fn = 0; fn < 8; fn++)
                mma_f16(acc[fm][fn], afr[fm], &bfr[fn >> 1][(fn & 1) * 2]);
    }
    __syncthreads();

    float rp[2][2] = {{0.f, 0.f}, {0.f, 0.f}};
#pragma unroll
    for (int fm = 0; fm < 2; fm++) {
        int kl = wm * 32 + fm * 16 + grp;
        int kh = kl + 8;
#pragma unroll
        for (int fn = 0; fn < 8; fn++) {
            int tc = wn * 64 + fn * 8 + tig * 2;
#pragma unroll
            for (int e = 0; e < 2; e++) {
                int t = tc + e;
                float v0 = (t0 + t >= k0 + kl) ? __expf(0.125f * acc[fm][fn][e]) : 0.f;
                float v1 = (t0 + t >= k0 + kh) ? __expf(0.125f * acc[fm][fn][e + 2]) : 0.f;
                ssm[kl * 136 + t] = __float2half(v0);
                ssm[kh * 136 + t] = __float2half(v1);
                rp[fm][0] += v0;
                rp[fm][1] += v1;
            }
        }
    }
#pragma unroll
    for (int fm = 0; fm < 2; fm++)
#pragma unroll
        for (int hl = 0; hl < 2; hl++) {
            rp[fm][hl] += __shfl_xor_sync(0xffffffffu, rp[fm][hl], 1);
            rp[fm][hl] += __shfl_xor_sync(0xffffffffu, rp[fm][hl], 2);
        }
    if (tig == 0) {
#pragma unroll
        for (int fm = 0; fm < 2; fm++) {
            sums[wm * 32 + fm * 16 + grp][wn]     = rp[fm][0];
            sums[wm * 32 + fm * 16 + grp + 8][wn] = rp[fm][1];
        }
    }
    __syncthreads();

    __half* Pb = P + ((size_t)bh * Tt + k0) * Tt + t0;
#pragma unroll
    for (int i = 0; i < 8; i++) {
        int idx = tid + i * 256;
        int r = idx >> 4, c = idx & 15;
        uint4 v = *reinterpret_cast<const uint4*>(&ssm[r * 136 + c * 8]);
        *reinterpret_cast<uint4*>(Pb + (size_t)r * Tt + c * 8) = v;
    }
    if (tid < 128)
        psum[((size_t)bh * 8 + tb) * Tt + k0 + tid] = sums[tid][0] + sums[tid][1];
}

// ---------------- PV via fp16 mma: cp.async P + ldmatrix.trans ----------------
__global__ __launch_bounds__(256)
void pv_fp16_kernel(const __half* __restrict__ P, const __half* __restrict__ qkvH,
                    const float* __restrict__ psum, __half* __restrict__ att) {
    int tb = blockIdx.x, bh = blockIdx.y;
    int b = bh / Hh, h = bh % Hh;
    int t0 = tb * 128;

    __shared__ __align__(16) __half Pt[64 * 128];  // [k][t] 256B rows
    __shared__ __align__(16) __half Vt[64 * 64];   // [s][k] 128B rows
    __shared__ float invs[1024];

    int tid = threadIdx.x;
    int warp = tid >> 5, lane = tid & 31;
    int wm = warp & 3, wn = warp >> 2;
    int grp = lane >> 2, tig = lane & 3;
    int lr = lane & 7, sub = lane >> 3;

    uint32_t Ptb = smem_u32(Pt), Vtb = smem_u32(Vt);

    int nk = 2 * (tb + 1);
    int Kext = nk * 64;
    for (int i = tid; i < Kext; i += 256) {
        int tb0 = i >> 7;
        float s = 0.f;
        for (int t2 = tb0; t2 < 8; t2++)
            s += psum[((size_t)bh * 8 + t2) * Tt + i];
        invs[i] = 1.f / s;
    }

    float acc[2][4][4];
#pragma unroll
    for (int i = 0; i < 2; i++)
#pragma unroll
        for (int j = 0; j < 4; j++)
#pragma unroll
            for (int q = 0; q < 4; q++) acc[i][j][q] = 0.f;

    int rowB[2];
#pragma unroll
    for (int p = 0; p < 2; p++) rowB[p] = wn * 32 + p * 16 + (sub >> 1) * 8 + lr;
    int chB = sub & 1;
    int tcolA = wm * 32 + (sub & 1) * 8;
    int krowA = (sub >> 1) * 8 + lr;

#pragma unroll 1
    for (int kt = 0; kt < nk; kt++) {
        int k0 = kt * 64;
        __syncthreads();
        const __half* Pg = P + ((size_t)bh * Tt + k0) * Tt + t0;
#pragma unroll
        for (int i = 0; i < 4; i++) {
            int idx = tid + i * 256;
            int r = idx >> 4, c = idx & 15;
            uint32_t so = (uint32_t)(r * 256 + ((c ^ (r & 7)) << 4));
            cp_async16(Ptb + so, Pg + (size_t)r * Tt + c * 8);
        }
        cp_commit();
        const __half* Vg = qkvH + (size_t)(b * Tt + k0) * QKV_P + 2 * Cc + h * HSs;
#pragma unroll
        for (int i = 0; i < 8; i++) {
            int idx = tid + i * 256;
            int kk = idx >> 5, sp = idx & 31;
            uint32_t v = *reinterpret_cast<const uint32_t*>(Vg + (size_t)kk * QKV_P + sp * 2);
            float iv = invs[k0 + kk];
            __half2 h2 = *(const __half2*)&v;
            __half s0 = __float2half(__half2float(h2.x) * iv);
            __half s1 = __float2half(__half2float(h2.y) * iv);
            int s_ = sp * 2;
            Vt[s_ * 64 + ((((kk >> 3) ^ (s_ & 7)) << 3) | (kk & 7))] = s0;
            s_++;
            Vt[s_ * 64 + ((((kk >> 3) ^ (s_ & 7)) << 3) | (kk & 7))] = s1;
        }
        cp_wait<0>();
        __syncthreads();
#pragma unroll
        for (int k16 = 0; k16 < 4; k16++) {
            uint32_t afr[2][4];
#pragma unroll
            for (int fm = 0; fm < 2; fm++) {
                int krow = k16 * 16 + krowA;
                int tcol = tcolA + fm * 16;
                uint32_t addr = Ptb + krow * 256 + ((((tcol >> 3) ^ (krow & 7)) << 4));
                ldm_x4_trans(afr[fm], addr);
            }
            int cb = k16 * 2;
            uint32_t bfr[2][4];
#pragma unroll
            for (int p = 0; p < 2; p++) {
                int r = rowB[p];
                ldm_x4(bfr[p], Vtb + r * 128 + (((cb + chB) ^ (r & 7)) << 4));
            }
#pragma unroll
            for (int fm = 0; fm < 2; fm++)
#pragma unroll
                for (int fn = 0; fn < 4; fn++)
                    mma_f16(acc[fm][fn], afr[fm], &bfr[fn >> 1][(fn & 1) * 2]);
        }
    }

#pragma unroll
    for (int fm = 0; fm < 2; fm++) {
        int m_lo = t0 + wm * 32 + fm * 16 + grp;
        int m_hi = m_lo + 8;
#pragma unroll
        for (int fn = 0; fn < 4; fn++) {
            int s = wn * 32 + fn * 8 + tig * 2;
#pragma unroll
            for (int e = 0; e < 2; e++) {
                att[(size_t)(b * Tt + m_lo) * Cc + h * HSs + s + e] = __float2half(acc[fm][fn][e]);
                att[(size_t)(b * Tt + m_hi) * Cc + h * HSs + s + e] = __float2half(acc[fm][fn][e + 2]);
            }
        }
    }
}

// ================= fp16 LM head: 3-stage pipeline ============================
constexpr int LM_NKT = Cc / 64;       // 6
constexpr int LM_STAGE = 32768;       // A 16KB + B 16KB
constexpr int LM_SMEM = 3 * LM_STAGE; // 96KB

__global__ __launch_bounds__(256, 2)
void lmhead_fp16_kernel(const __half* __restrict__ A, const __half* __restrict__ Bt,
                        const float* __restrict__ bias, float* __restrict__ out) {
    extern __shared__ __half smh[];
    int tid = threadIdx.x;
    int warp = tid >> 5, lane = tid & 31;
    int wm = warp & 3, wn = warp >> 2;
    int grp = lane >> 2, tig = lane & 3;
    int lr = lane & 7, sub = lane >> 3;
    int m0 = blockIdx.x * 128, n0 = blockIdx.y * 128;
    const __half* Ab = A + (size_t)m0 * Cc;
    const __half* Bb = Bt + (size_t)n0 * Cc;

    uint32_t sbase = smem_u32(smh);

    auto issue = [&](int kt, int stage) {
        uint32_t as = sbase + stage * (uint32_t)LM_STAGE;
        uint32_t bs = as + 16384u;
#pragma unroll
        for (int it = 0; it < 4; it++) {
            int slot = tid + it * 256;
            int r = slot >> 3, c = slot & 7;
            uint32_t so = (uint32_t)(r * 128 + ((c ^ (r & 7)) << 4));
            cp_async16(as + so, Ab + (size_t)r * Cc + kt * 64 + c * 8);
            cp_async16(bs + so, Bb + (size_t)r * Cc + kt * 64 + c * 8);
        }
    };

    float acc[2][8][4];
#pragma unroll
    for (int i = 0; i < 2; i++)
#pragma unroll
        for (int j = 0; j < 8; j++)
#pragma unroll
            for (int q = 0; q < 4; q++) acc[i][j][q] = 0.f;

    int rowA[2], rowB[4];
#pragma unroll
    for (int fm = 0; fm < 2; fm++) rowA[fm] = wm * 32 + fm * 16 + (sub & 1) * 8 + lr;
#pragma unroll
    for (int p = 0; p < 4; p++) rowB[p] = wn * 64 + p * 16 + (sub >> 1) * 8 + lr;
    int chA = sub >> 1, chB = sub & 1;

    issue(0, 0); cp_commit();
    issue(1, 1); cp_commit();

    int stage = 0;
#pragma unroll 1
    for (int kt = 0; kt < LM_NKT; kt++) {
        if (kt + 1 < LM_NKT) { cp_wait<1>(); } else { cp_wait<0>(); }  // drain fix
        __syncthreads();
        if (kt + 2 < LM_NKT) {
            int ns = stage + 2; if (ns >= 3) ns -= 3;
            issue(kt + 2, ns);
            cp_commit();
        }
        uint32_t as = sbase + stage * (uint32_t)LM_STAGE;
        uint32_t bs = as + 16384u;
#pragma unroll
        for (int k16 = 0; k16 < 4; k16++) {
            int cb = k16 * 2;
            uint32_t afr[2][4];
#pragma unroll
            for (int fm = 0; fm < 2; fm++) {
                int r = rowA[fm];
                ldm_x4(afr[fm], as + r * 128 + (((cb + chA) ^ (r & 7)) << 4));
            }
            uint32_t bfr[4][4];
#pragma unroll
            for (int p = 0; p < 4; p++) {
                int r = rowB[p];
                ldm_x4(bfr[p], bs + r * 128 + (((cb + chB) ^ (r & 7)) << 4));
            }
#pragma unroll
            for (int fm = 0; fm < 2; fm++)
#pragma unroll
                for (int fn = 0; fn < 8; fn++)
                    mma_f16(acc[fm][fn], afr[fm], &bfr[fn >> 1][(fn & 1) * 2]);
        }
        if (++stage >= 3) stage = 0;
    }

#pragma unroll
    for (int fm = 0; fm < 2; fm++) {
        int m_lo = m0 + wm * 32 + fm * 16 + grp;
        int m_hi = m_lo + 8;
#pragma unroll
        for (int fn = 0; fn < 8; fn++) {
            int n = n0 + wn * 64 + fn * 8 + tig * 2;
#pragma unroll
            for (int e = 0; e < 2; e++) {
                int nn = n + e;
                if (nn >= Vv) continue;
                float bv = bias[nn];
                out[(size_t)m_lo * Vv + nn] = acc[fm][fn][e]     + bv;
                out[(size_t)m_hi * Vv + nn] = acc[fm][fn][e + 2] + bv;
            }
        }
    }
}

// ---------------- host launcher ---------------------------------------------
static float* symaddr(const void* s) {
    void* p = nullptr;
    cudaGetSymbolAddress(&p, s);
    return (float*)p;
}

extern "C" void kernel_launch(void* const* d_in, const int* in_sizes, int n_in,
                              void* d_out, int out_size) {
    const int*   x    = (const int*)d_in[0];
    const float* tok  = (const float*)d_in[1];
    const float* pos  = (const float*)d_in[2];
    const float* Wq   = (const float*)d_in[3];
    const float* bq   = (const float*)d_in[4];
    const float* Wk   = (const float*)d_in[5];
    const float* bk   = (const float*)d_in[6];
    const float* Wv   = (const float*)d_in[7];
    const float* bv   = (const float*)d_in[8];
    const float* Wo   = (const float*)d_in[9];
    const float* bo   = (const float*)d_in[10];
    const float* ln1g = (const float*)d_in[11];
    const float* ln1b = (const float*)d_in[12];
    const float* W1   = (const float*)d_in[13];
    const float* b1   = (const float*)d_in[14];
    const float* W2   = (const float*)d_in[15];
    const float* b2   = (const float*)d_in[16];
    const float* ln2g = (const float*)d_in[17];
    const float* ln2b = (const float*)d_in[18];
    const float* Wlm  = (const float*)d_in[19];
    const float* blm  = (const float*)d_in[20];
    float* out = (float*)d_out;

    float* ph      = symaddr(g_h);
    __half* paH    = (__half*)symaddr(g_aH);
    __half* pqkvH  = (__half*)symaddr(g_qkvH);
    __half* pattH  = (__half*)symaddr(g_attH);
    __half* pmH    = (__half*)symaddr(g_mH);
    __half* pP     = (__half*)symaddr(g_P);
    float* ppsum   = symaddr(g_psum);
    __half* pWqkvT = (__half*)symaddr(g_WqkvT);
    float* pbqkv   = symaddr(g_bqkv);
    __half* pWoT   = (__half*)symaddr(g_WoT);
    __half* pW1T   = (__half*)symaddr(g_W1T);
    __half* pW2T   = (__half*)symaddr(g_W2T);
    __half* phH    = (__half*)symaddr(g_hH);
    __half* pWlmH  = (__half*)symaddr(g_WlmH);

    static bool attr_done = false;
    if (!attr_done) {
        cudaFuncSetAttribute((const void*)h16_gemm_kernel<0>,  cudaFuncAttributeMaxDynamicSharedMemorySize, H16_SMEM);
        cudaFuncSetAttribute((const void*)h16_gemm_kernel<1>,  cudaFuncAttributeMaxDynamicSharedMemorySize, H16_SMEM);
        cudaFuncSetAttribute((const void*)h16_gemm_kernel<2>,  cudaFuncAttributeMaxDynamicSharedMemorySize, H16_SMEM);
        cudaFuncSetAttribute((const void*)h16_gemm_kernel<18>, cudaFuncAttributeMaxDynamicSharedMemorySize, H16_SMEM);
        cudaFuncSetAttribute((const void*)lmhead_fp16_kernel,  cudaFuncAttributeMaxDynamicSharedMemorySize, LM_SMEM);
        attr_done = true;
    }

    embed_kernel<<<(M_ROWS * Cc + 255) / 256, 256>>>(x, tok, pos, ph);

    int qkvt_total = NLl * QKV_P * Cc;
    repack_qkvT_kernel<<<(qkvt_total + 255) / 256, 256>>>(Wq, Wk, Wv, pWqkvT);
    repack_bqkv_kernel<<<(NLl * QKV_P + 255) / 256, 256>>>(bq, bk, bv, pbqkv);
    dim3 tg(Cc / 32, Cc / 32, NLl);
    transpose_w_kernel<<<tg, dim3(32, 8)>>>(Wo, pWoT);
    transpose_w_kernel<<<tg, dim3(32, 8)>>>(W1, pW1T);
    transpose_w_kernel<<<tg, dim3(32, 8)>>>(W2, pW2T);
    transpose_wlm_kernel<<<dim3(V_PAD / 32, Cc / 32), dim3(32, 8)>>>(Wlm, pWlmH);

    dim3 g_qkv_grid(M_ROWS / 64, QKV_P / 128);   // (32, 9)
    dim3 g_c_grid(M_ROWS / 64, Cc / 128);        // (32, 3)

    for (int l = 0; l < NLl; l++) {
        ln_kernel<<<M_ROWS, 128>>>(ph, ln1g + l * Cc, ln1b + l * Cc, paH);

        h16_gemm_kernel<0><<<g_qkv_grid, 256, H16_SMEM>>>(
            paH, pWqkvT + (size_t)l * QKV_P * Cc, pbqkv + l * QKV_P, pqkvH, nullptr, QKV_P);

        scores_p_kernel<<<dim3(36, 1, BH), 256>>>(pqkvH, pP, ppsum);
        pv_fp16_kernel<<<dim3(8, BH), 256>>>(pP, pqkvH, ppsum, pattH);

        h16_gemm_kernel<2><<<g_c_grid, 256, H16_SMEM>>>(
            pattH, pWoT + (size_t)l * Cc * Cc, bo + l * Cc, ph, nullptr, Cc);

        ln_kernel<<<M_ROWS, 128>>>(ph, ln2g + l * Cc, ln2b + l * Cc, paH);

        h16_gemm_kernel<1><<<g_c_grid, 256, H16_SMEM>>>(
            paH, pW1T + (size_t)l * Cc * Cc, b1 + l * Cc, pmH, nullptr, Cc);

        if (l == NLl - 1) {
            h16_gemm_kernel<18><<<g_c_grid, 256, H16_SMEM>>>(
                pmH, pW2T + (size_t)l * Cc * Cc, b2 + l * Cc, ph, phH, Cc);
        } else {
            h16_gemm_kernel<2><<<g_c_grid, 256, H16_SMEM>>>(
                pmH, pW2T + (size_t)l * Cc * Cc, b2 + l * Cc, ph, nullptr, Cc);
        }
    }

    // LM head (fp16 tensor cores, 3-stage pipeline)
    lmhead_fp16_kernel<<<dim3(M_ROWS / 128, V_PAD / 128), 256, LM_SMEM>>>(
        phH, pWlmH, blm, out);
}

// round 11
// speedup vs baseline: 8.8989x; 1.0350x over previous
#include <cuda_runtime.h>
#include <cuda_fp16.h>
#include <cstdint>

// Problem constants
constexpr int Vv = 50257, Cc = 384, Tt = 1024, Hh = 6, HSs = 64, NLl = 3, Bb = 2;
constexpr int M_ROWS = Bb * Tt;   // 2048
constexpr int BH = Bb * Hh;       // 12
constexpr int V_PAD = 50304;      // 393 * 128
constexpr int QKV_P = 3 * Cc;     // 1152

// ---------------- scratch (__device__ globals; no allocation allowed) --------
__device__ float g_h[M_ROWS * Cc];
__device__ __half g_aH[M_ROWS * Cc];               // LN output fp16
__device__ __half g_qkvH[M_ROWS * QKV_P];          // fused QKV, fp16
__device__ __half g_attH[M_ROWS * Cc];             // PV output fp16
__device__ __half g_mH[M_ROWS * Cc];               // relu(W1) output fp16
__device__ __half g_P[(size_t)BH * Tt * Tt];       // unnormalized probs [bh][k][t]
__device__ float g_psum[BH * 8 * Tt];              // per-(bh,tb) row partial sums
__device__ __half g_WqkvT[NLl * QKV_P * Cc];       // [l][n][k] fp16
__device__ float g_bqkv[NLl * QKV_P];
__device__ __half g_WoT[NLl * Cc * Cc];
__device__ __half g_W1T[NLl * Cc * Cc];
__device__ __half g_W2T[NLl * Cc * Cc];
__device__ __half g_hH[M_ROWS * Cc];               // h as fp16 (LM head input)
__device__ __half g_WlmH[(size_t)V_PAD * Cc];      // Wlm^T as fp16 [n][k]

// ---------------- embedding --------------------------------------------------
__global__ void embed_kernel(const int* __restrict__ x, const float* __restrict__ tok,
                             const float* __restrict__ pos, float* __restrict__ h) {
    int i = blockIdx.x * blockDim.x + threadIdx.x;
    if (i >= M_ROWS * Cc) return;
    int row = i / Cc, c = i % Cc;
    int t = row % Tt;
    h[i] = tok[(size_t)x[row] * Cc + c] + pos[t * Cc + c];
}

// ---------------- combined QKV weight + bias repack --------------------------
__global__ void repack_qkv_comb_kernel(const float* __restrict__ Wq, const float* __restrict__ Wk,
                                       const float* __restrict__ Wv,
                                       const float* __restrict__ bq, const float* __restrict__ bk,
                                       const float* __restrict__ bv,
                                       __half* __restrict__ OW, float* __restrict__ OB) {
    int i = blockIdx.x * blockDim.x + threadIdx.x;
    int total_w = NLl * QKV_P * Cc;
    if (i < total_w) {
        int k = i % Cc;
        int n = (i / Cc) % QKV_P;
        int l = i / (Cc * QKV_P);
        int sel = n / Cc, h = (n % Cc) / HSs, s = n % HSs;
        const float* W = (sel == 0) ? Wq : (sel == 1) ? Wk : Wv;
        OW[i] = __float2half(W[(((size_t)l * Hh + h) * Cc + k) * HSs + s]);
    } else {
        int j = i - total_w;
        if (j < NLl * QKV_P) {
            int n = j % QKV_P, l = j / QKV_P;
            int sel = n / Cc, h = (n % Cc) / HSs, s = n % HSs;
            const float* B = (sel == 0) ? bq : (sel == 1) ? bk : bv;
            OB[j] = B[((size_t)l * Hh + h) * HSs + s];
        }
    }
}

// ---------------- all three square weights transposed in one launch ----------
__global__ void transpose_all_kernel(const float* __restrict__ Wo, const float* __restrict__ W1,
                                     const float* __restrict__ W2,
                                     __half* __restrict__ To, __half* __restrict__ T1,
                                     __half* __restrict__ T2) {
    __shared__ float t[32][33];
    int wi = blockIdx.z % 3, l = blockIdx.z / 3;
    const float* W = ((wi == 0) ? Wo : (wi == 1) ? W1 : W2) + (size_t)l * Cc * Cc;
    __half* T = ((wi == 0) ? To : (wi == 1) ? T1 : T2) + (size_t)l * Cc * Cc;
    int n0 = blockIdx.x * 32, k0 = blockIdx.y * 32;
    for (int dy = threadIdx.y; dy < 32; dy += 8)
        t[dy][threadIdx.x] = W[(size_t)(k0 + dy) * Cc + n0 + threadIdx.x];
    __syncthreads();
    for (int dy = threadIdx.y; dy < 32; dy += 8)
        T[(size_t)(n0 + dy) * Cc + k0 + threadIdx.x] = __float2half(t[threadIdx.x][dy]);
}

__global__ void transpose_wlm_kernel(const float* __restrict__ Wlm, __half* __restrict__ Bt) {
    __shared__ float tile[32][33];
    int n0 = blockIdx.x * 32, k0 = blockIdx.y * 32;
    for (int dy = threadIdx.y; dy < 32; dy += 8) {
        int k = k0 + dy, n = n0 + threadIdx.x;
        tile[dy][threadIdx.x] = (n < Vv) ? Wlm[(size_t)k * Vv + n] : 0.f;
    }
    __syncthreads();
    for (int dy = threadIdx.y; dy < 32; dy += 8) {
        int n = n0 + dy, k = k0 + threadIdx.x;
        Bt[(size_t)n * Cc + k] = __float2half(tile[threadIdx.x][dy]);
    }
}

// ---------------- layernorm (vectorized, fp16 out) ---------------------------
__global__ void ln_kernel(const float* __restrict__ x, const float* __restrict__ g,
                          const float* __restrict__ b, __half* __restrict__ y) {
    int row = blockIdx.x;
    const float4* xr4 = reinterpret_cast<const float4*>(x + (size_t)row * Cc);
    float4 v = make_float4(0.f, 0.f, 0.f, 0.f);
    int tid = threadIdx.x;
    if (tid < 96) v = xr4[tid];
    float lsum = v.x + v.y + v.z + v.w;
    float lsq = v.x * v.x + v.y * v.y + v.z * v.z + v.w * v.w;
    __shared__ float sh[64];
    int lane = tid & 31, wid = tid >> 5;
#pragma unroll
    for (int o = 16; o; o >>= 1) {
        lsum += __shfl_xor_sync(0xffffffffu, lsum, o);
        lsq  += __shfl_xor_sync(0xffffffffu, lsq,  o);
    }
    if (lane == 0) { sh[wid] = lsum; sh[wid + 32] = lsq; }
    __syncthreads();
    if (tid == 0) {
        float s = 0.f, q = 0.f;
        for (int w = 0; w < 4; w++) { s += sh[w]; q += sh[w + 32]; }
        sh[0] = s; sh[32] = q;
    }
    __syncthreads();
    float mu = sh[0] / Cc;
    float var = sh[32] / Cc - mu * mu;
    float rstd = rsqrtf(var + 1e-5f);
    if (tid < 96) {
        const float4 g4 = reinterpret_cast<const float4*>(g)[tid];
        const float4 b4 = reinterpret_cast<const float4*>(b)[tid];
        __half2 o0 = __floats2half2_rn((v.x - mu) * rstd * g4.x + b4.x,
                                       (v.y - mu) * rstd * g4.y + b4.y);
        __half2 o1 = __floats2half2_rn((v.z - mu) * rstd * g4.z + b4.z,
                                       (v.w - mu) * rstd * g4.w + b4.w);
        uint2 pack;
        pack.x = *reinterpret_cast<uint32_t*>(&o0);
        pack.y = *reinterpret_cast<uint32_t*>(&o1);
        reinterpret_cast<uint2*>(y + (size_t)row * Cc)[tid] = pack;
    }
}

// ---------------- common asm helpers ----------------------------------------
__device__ __forceinline__ uint32_t smem_u32(const void* p) {
    uint32_t a;
    asm("{ .reg .u64 t; cvta.to.shared.u64 t, %1; cvt.u32.u64 %0, t; }" : "=r"(a) : "l"(p));
    return a;
}
__device__ __forceinline__ void cp_async16(uint32_t saddr, const void* g) {
    asm volatile("cp.async.cg.shared.global [%0], [%1], 16;" :: "r"(saddr), "l"(g) : "memory");
}
__device__ __forceinline__ void cp_commit() {
    asm volatile("cp.async.commit_group;" ::: "memory");
}
template<int N>
__device__ __forceinline__ void cp_wait() {
    asm volatile("cp.async.wait_group %0;" :: "n"(N) : "memory");
}
__device__ __forceinline__ void ldm_x4(uint32_t* r, uint32_t addr) {
    asm volatile("ldmatrix.sync.aligned.m8n8.x4.shared.b16 {%0,%1,%2,%3}, [%4];"
                 : "=r"(r[0]), "=r"(r[1]), "=r"(r[2]), "=r"(r[3]) : "r"(addr));
}
__device__ __forceinline__ void ldm_x4_trans(uint32_t* r, uint32_t addr) {
    asm volatile("ldmatrix.sync.aligned.m8n8.x4.trans.shared.b16 {%0,%1,%2,%3}, [%4];"
                 : "=r"(r[0]), "=r"(r[1]), "=r"(r[2]), "=r"(r[3]) : "r"(addr));
}
__device__ __forceinline__ void mma_f16(float* c, const uint32_t* a, const uint32_t* b) {
    asm volatile(
        "mma.sync.aligned.m16n8k16.row.col.f32.f16.f16.f32 "
        "{%0,%1,%2,%3}, {%4,%5,%6,%7}, {%8,%9}, {%0,%1,%2,%3};"
        : "+f"(c[0]), "+f"(c[1]), "+f"(c[2]), "+f"(c[3])
        : "r"(a[0]), "r"(a[1]), "r"(a[2]), "r"(a[3]), "r"(b[0]), "r"(b[1]));
}

// ================= fp16 layer GEMM: CTA 64x128, K-tile 64, 3-stage ===========
constexpr int H16_NKT = Cc / 64;      // 6
constexpr int H16_STAGE = 24576;      // A 8KB + B 16KB
constexpr int H16_SMEM = 3 * H16_STAGE;  // 72KB

template<int FLAGS>  // 1=relu, 2=accumulate fp32, 16=also fp16 aux copy
__global__ __launch_bounds__(256, 2)
void h16_gemm_kernel(const __half* __restrict__ A, const __half* __restrict__ Bt,
                     const float* __restrict__ bias, void* __restrict__ Cv,
                     __half* __restrict__ aux, int ldc) {
    extern __shared__ __half smh[];
    int tid = threadIdx.x;
    int warp = tid >> 5, lane = tid & 31;
    int wm = warp & 1, wn = warp >> 1;
    int grp = lane >> 2, tig = lane & 3;
    int lr = lane & 7, sub = lane >> 3;
    int m0 = blockIdx.x * 64, n0 = blockIdx.y * 128;
    const __half* Ab = A + (size_t)m0 * Cc;
    const __half* Bb = Bt + (size_t)n0 * Cc;
    uint32_t sbase = smem_u32(smh);

    auto issue = [&](int kt, int stage) {
        uint32_t as = sbase + stage * (uint32_t)H16_STAGE;
        uint32_t bs = as + 8192u;
#pragma unroll
        for (int it = 0; it < 2; it++) {
            int slot = tid + it * 256;
            int r = slot >> 3, c = slot & 7;
            uint32_t so = (uint32_t)(r * 128 + ((c ^ (r & 7)) << 4));
            cp_async16(as + so, Ab + (size_t)r * Cc + kt * 64 + c * 8);
        }
#pragma unroll
        for (int it = 0; it < 4; it++) {
            int slot = tid + it * 256;
            int r = slot >> 3, c = slot & 7;
            uint32_t so = (uint32_t)(r * 128 + ((c ^ (r & 7)) << 4));
            cp_async16(bs + so, Bb + (size_t)r * Cc + kt * 64 + c * 8);
        }
    };

    float acc[2][4][4];
#pragma unroll
    for (int i = 0; i < 2; i++)
#pragma unroll
        for (int j = 0; j < 4; j++)
#pragma unroll
            for (int q = 0; q < 4; q++) acc[i][j][q] = 0.f;

    int rowA[2], rowB[2];
#pragma unroll
    for (int fm = 0; fm < 2; fm++) rowA[fm] = wm * 32 + fm * 16 + (sub & 1) * 8 + lr;
#pragma unroll
    for (int p = 0; p < 2; p++) rowB[p] = wn * 32 + p * 16 + (sub >> 1) * 8 + lr;
    int chA = sub >> 1, chB = sub & 1;

    issue(0, 0); cp_commit();
    issue(1, 1); cp_commit();

    int stage = 0;
#pragma unroll 1
    for (int kt = 0; kt < H16_NKT; kt++) {
        if (kt + 1 < H16_NKT) { cp_wait<1>(); } else { cp_wait<0>(); }
        __syncthreads();
        if (kt + 2 < H16_NKT) {
            int ns = stage + 2; if (ns >= 3) ns -= 3;
            issue(kt + 2, ns);
            cp_commit();
        }
        uint32_t as = sbase + stage * (uint32_t)H16_STAGE;
        uint32_t bs = as + 8192u;
#pragma unroll
        for (int k16 = 0; k16 < 4; k16++) {
            int cb = k16 * 2;
            uint32_t afr[2][4];
#pragma unroll
            for (int fm = 0; fm < 2; fm++) {
                int r = rowA[fm];
                ldm_x4(afr[fm], as + r * 128 + (((cb + chA) ^ (r & 7)) << 4));
            }
            uint32_t bfr[2][4];
#pragma unroll
            for (int p = 0; p < 2; p++) {
                int r = rowB[p];
                ldm_x4(bfr[p], bs + r * 128 + (((cb + chB) ^ (r & 7)) << 4));
            }
#pragma unroll
            for (int fm = 0; fm < 2; fm++)
#pragma unroll
                for (int fn = 0; fn < 4; fn++)
                    mma_f16(acc[fm][fn], afr[fm], &bfr[fn >> 1][(fn & 1) * 2]);
        }
        if (++stage >= 3) stage = 0;
    }

#pragma unroll
    for (int fm = 0; fm < 2; fm++) {
        int m_lo = m0 + wm * 32 + fm * 16 + grp;
        int m_hi = m_lo + 8;
#pragma unroll
        for (int fn = 0; fn < 4; fn++) {
            int n = n0 + wn * 32 + fn * 8 + tig * 2;
#pragma unroll
            for (int e = 0; e < 2; e++) {
                int nn = n + e;
                float bv = bias[nn];
                float v0 = acc[fm][fn][e]     + bv;
                float v1 = acc[fm][fn][e + 2] + bv;
                if (FLAGS & 1) { v0 = fmaxf(v0, 0.f); v1 = fmaxf(v1, 0.f); }
                if constexpr ((FLAGS & 2) != 0) {
                    float* C = (float*)Cv;
                    v0 += C[(size_t)m_lo * ldc + nn];
                    v1 += C[(size_t)m_hi * ldc + nn];
                    C[(size_t)m_lo * ldc + nn] = v0;
                    C[(size_t)m_hi * ldc + nn] = v1;
                    if constexpr ((FLAGS & 16) != 0) {
                        aux[(size_t)m_lo * ldc + nn] = __float2half(v0);
                        aux[(size_t)m_hi * ldc + nn] = __float2half(v1);
                    }
                } else {
                    __half* C = (__half*)Cv;
                    C[(size_t)m_lo * ldc + nn] = __float2half(v0);
                    C[(size_t)m_hi * ldc + nn] = __float2half(v1);
                }
            }
        }
    }
}

// ======== scores + exp + row-partial-sums (fp16 mma), P unnormalized =========
// grid: (36 lower-tri tile pairs, 1, BH)
__global__ __launch_bounds__(256, 2)
void scores_p_kernel(const __half* __restrict__ qkvH, __half* __restrict__ P,
                     float* __restrict__ psum) {
    int q = blockIdx.x, bh = blockIdx.z;
    int tb = 0;
    while ((tb + 1) * (tb + 2) / 2 <= q) tb++;
    int kb = q - tb * (tb + 1) / 2;
    int b = bh / Hh, h = bh % Hh;
    int k0 = kb * 128, t0 = tb * 128;

    __shared__ __align__(16) __half ssm[128 * 136];
    __shared__ float sums[128][2];

    int tid = threadIdx.x;
    int warp = tid >> 5, lane = tid & 31;
    int wm = warp & 3, wn = warp >> 2;
    int grp = lane >> 2, tig = lane & 3;
    int lr = lane & 7, sub = lane >> 3;

    uint32_t sb = smem_u32(ssm);
    uint32_t Ksb = sb, Qsb = sb + 16384u;
    const __half* Kb_ = qkvH + (size_t)(b * Tt + k0) * QKV_P + Cc + h * HSs;
    const __half* Qb_ = qkvH + (size_t)(b * Tt + t0) * QKV_P + h * HSs;

#pragma unroll
    for (int it = 0; it < 4; it++) {
        int slot = tid + it * 256;
        int r = slot >> 3, c = slot & 7;
        uint32_t so = (uint32_t)(r * 128 + ((c ^ (r & 7)) << 4));
        cp_async16(Ksb + so, Kb_ + (size_t)r * QKV_P + c * 8);
        cp_async16(Qsb + so, Qb_ + (size_t)r * QKV_P + c * 8);
    }
    cp_commit();
    cp_wait<0>();
    __syncthreads();

    float acc[2][8][4];
#pragma unroll
    for (int i = 0; i < 2; i++)
#pragma unroll
        for (int j = 0; j < 8; j++)
#pragma unroll
            for (int q2 = 0; q2 < 4; q2++) acc[i][j][q2] = 0.f;

    int rowA[2], rowB[4];
#pragma unroll
    for (int fm = 0; fm < 2; fm++) rowA[fm] = wm * 32 + fm * 16 + (sub & 1) * 8 + lr;
#pragma unroll
    for (int p = 0; p < 4; p++) rowB[p] = wn * 64 + p * 16 + (sub >> 1) * 8 + lr;
    int chA = sub >> 1, chB = sub & 1;

#pragma unroll
    for (int k16 = 0; k16 < 4; k16++) {
        int cb = k16 * 2;
        uint32_t afr[2][4];
#pragma unroll
        for (int fm = 0; fm < 2; fm++) {
            int r = rowA[fm];
            ldm_x4(afr[fm], Ksb + r * 128 + (((cb + chA) ^ (r & 7)) << 4));
        }
        uint32_t bfr[4][4];
#pragma unroll
        for (int p = 0; p < 4; p++) {
            int r = rowB[p];
            ldm_x4(bfr[p], Qsb + r * 128 + (((cb + chB) ^ (r & 7)) << 4));
        }
#pragma unroll
        for (int fm = 0; fm < 2; fm++)
#pragma unroll
            for (int fn = 0; fn < 8; fn++)
                mma_f16(acc[fm][fn], afr[fm], &bfr[fn >> 1][(fn & 1) * 2]);
    }
    __syncthreads();

    float rp[2][2] = {{0.f, 0.f}, {0.f, 0.f}};
#pragma unroll
    for (int fm = 0; fm < 2; fm++) {
        int kl = wm * 32 + fm * 16 + grp;
        int kh = kl + 8;
#pragma unroll
        for (int fn = 0; fn < 8; fn++) {
            int tc = wn * 64 + fn * 8 + tig * 2;
#pragma unroll
            for (int e = 0; e < 2; e++) {
                int t = tc + e;
                float v0 = (t0 + t >= k0 + kl) ? __expf(0.125f * acc[fm][fn][e]) : 0.f;
                float v1 = (t0 + t >= k0 + kh) ? __expf(0.125f * acc[fm][fn][e + 2]) : 0.f;
                ssm[kl * 136 + t] = __float2half(v0);
                ssm[kh * 136 + t] = __float2half(v1);
                rp[fm][0] += v0;
                rp[fm][1] += v1;
            }
        }
    }
#pragma unroll
    for (int fm = 0; fm < 2; fm++)
#pragma unroll
        for (int hl = 0; hl < 2; hl++) {
            rp[fm][hl] += __shfl_xor_sync(0xffffffffu, rp[fm][hl], 1);
            rp[fm][hl] += __shfl_xor_sync(0xffffffffu, rp[fm][hl], 2);
        }
    if (tig == 0) {
#pragma unroll
        for (int fm = 0; fm < 2; fm++) {
            sums[wm * 32 + fm * 16 + grp][wn]     = rp[fm][0];
            sums[wm * 32 + fm * 16 + grp + 8][wn] = rp[fm][1];
        }
    }
    __syncthreads();

    __half* Pb = P + ((size_t)bh * Tt + k0) * Tt + t0;
#pragma unroll
    for (int i = 0; i < 8; i++) {
        int idx = tid + i * 256;
        int r = idx >> 4, c = idx & 15;
        uint4 v = *reinterpret_cast<const uint4*>(&ssm[r * 136 + c * 8]);
        *reinterpret_cast<uint4*>(Pb + (size_t)r * Tt + c * 8) = v;
    }
    if (tid < 128)
        psum[((size_t)bh * 8 + tb) * Tt + k0 + tid] = sums[tid][0] + sums[tid][1];
}

// ---------------- PV via fp16 mma: cp.async P + ldmatrix.trans ----------------
__global__ __launch_bounds__(256)
void pv_fp16_kernel(const __half* __restrict__ P, const __half* __restrict__ qkvH,
                    const float* __restrict__ psum, __half* __restrict__ att) {
    int tb = blockIdx.x, bh = blockIdx.y;
    int b = bh / Hh, h = bh % Hh;
    int t0 = tb * 128;

    __shared__ __align__(16) __half Pt[64 * 128];  // [k][t] 256B rows
    __shared__ __align__(16) __half Vt[64 * 64];   // [s][k] 128B rows
    __shared__ float invs[1024];

    int tid = threadIdx.x;
    int warp = tid >> 5, lane = tid & 31;
    int wm = warp & 3, wn = warp >> 2;
    int grp = lane >> 2, tig = lane & 3;
    int lr = lane & 7, sub = lane >> 3;

    uint32_t Ptb = smem_u32(Pt), Vtb = smem_u32(Vt);

    int nk = 2 * (tb + 1);
    int Kext = nk * 64;
    for (int i = tid; i < Kext; i += 256) {
        int tb0 = i >> 7;
        float s = 0.f;
        for (int t2 = tb0; t2 < 8; t2++)
            s += psum[((size_t)bh * 8 + t2) * Tt + i];
        invs[i] = 1.f / s;
    }

    float acc[2][4][4];
#pragma unroll
    for (int i = 0; i < 2; i++)
#pragma unroll
        for (int j = 0; j < 4; j++)
#pragma unroll
            for (int q = 0; q < 4; q++) acc[i][j][q] = 0.f;

    int rowB[2];
#pragma unroll
    for (int p = 0; p < 2; p++) rowB[p] = wn * 32 + p * 16 + (sub >> 1) * 8 + lr;
    int chB = sub & 1;
    int tcolA = wm * 32 + (sub & 1) * 8;
    int krowA = (sub >> 1) * 8 + lr;

#pragma unroll 1
    for (int kt = 0; kt < nk; kt++) {
        int k0 = kt * 64;
        __syncthreads();
        const __half* Pg = P + ((size_t)bh * Tt + k0) * Tt + t0;
#pragma unroll
        for (int i = 0; i < 4; i++) {
            int idx = tid + i * 256;
            int r = idx >> 4, c = idx & 15;
            uint32_t so = (uint32_t)(r * 256 + ((c ^ (r & 7)) << 4));
            cp_async16(Ptb + so, Pg + (size_t)r * Tt + c * 8);
        }
        cp_commit();
        const __half* Vg = qkvH + (size_t)(b * Tt + k0) * QKV_P + 2 * Cc + h * HSs;
#pragma unroll
        for (int i = 0; i < 8; i++) {
            int idx = tid + i * 256;
            int kk = idx >> 5, sp = idx & 31;
            uint32_t v = *reinterpret_cast<const uint32_t*>(Vg + (size_t)kk * QKV_P + sp * 2);
            float iv = invs[k0 + kk];
            __half2 h2 = *(const __half2*)&v;
            __half s0 = __float2half(__half2float(h2.x) * iv);
            __half s1 = __float2half(__half2float(h2.y) * iv);
            int s_ = sp * 2;
            Vt[s_ * 64 + ((((kk >> 3) ^ (s_ & 7)) << 3) | (kk & 7))] = s0;
            s_++;
            Vt[s_ * 64 + ((((kk >> 3) ^ (s_ & 7)) << 3) | (kk & 7))] = s1;
        }
        cp_wait<0>();
        __syncthreads();
#pragma unroll
        for (int k16 = 0; k16 < 4; k16++) {
            uint32_t afr[2][4];
#pragma unroll
            for (int fm = 0; fm < 2; fm++) {
                int krow = k16 * 16 + krowA;
                int tcol = tcolA + fm * 16;
                uint32_t addr = Ptb + krow * 256 + ((((tcol >> 3) ^ (krow & 7)) << 4));
                ldm_x4_trans(afr[fm], addr);
            }
            int cb = k16 * 2;
            uint32_t bfr[2][4];
#pragma unroll
            for (int p = 0; p < 2; p++) {
                int r = rowB[p];
                ldm_x4(bfr[p], Vtb + r * 128 + (((cb + chB) ^ (r & 7)) << 4));
            }
#pragma unroll
            for (int fm = 0; fm < 2; fm++)
#pragma unroll
                for (int fn = 0; fn < 4; fn++)
                    mma_f16(acc[fm][fn], afr[fm], &bfr[fn >> 1][(fn & 1) * 2]);
        }
    }

#pragma unroll
    for (int fm = 0; fm < 2; fm++) {
        int m_lo = t0 + wm * 32 + fm * 16 + grp;
        int m_hi = m_lo + 8;
#pragma unroll
        for (int fn = 0; fn < 4; fn++) {
            int s = wn * 32 + fn * 8 + tig * 2;
#pragma unroll
            for (int e = 0; e < 2; e++) {
                att[(size_t)(b * Tt + m_lo) * Cc + h * HSs + s + e] = __float2half(acc[fm][fn][e]);
                att[(size_t)(b * Tt + m_hi) * Cc + h * HSs + s + e] = __float2half(acc[fm][fn][e + 2]);
            }
        }
    }
}

// ================= fp16 LM head: 3-stage pipeline ============================
constexpr int LM_NKT = Cc / 64;       // 6
constexpr int LM_STAGE = 32768;       // A 16KB + B 16KB
constexpr int LM_SMEM = 3 * LM_STAGE; // 96KB

__global__ __launch_bounds__(256, 2)
void lmhead_fp16_kernel(const __half* __restrict__ A, const __half* __restrict__ Bt,
                        const float* __restrict__ bias, float* __restrict__ out) {
    extern __shared__ __half smh[];
    int tid = threadIdx.x;
    int warp = tid >> 5, lane = tid & 31;
    int wm = warp & 3, wn = warp >> 2;
    int grp = lane >> 2, tig = lane & 3;
    int lr = lane & 7, sub = lane >> 3;
    int m0 = blockIdx.x * 128, n0 = blockIdx.y * 128;
    const __half* Ab = A + (size_t)m0 * Cc;
    const __half* Bb = Bt + (size_t)n0 * Cc;

    uint32_t sbase = smem_u32(smh);

    auto issue = [&](int kt, int stage) {
        uint32_t as = sbase + stage * (uint32_t)LM_STAGE;
        uint32_t bs = as + 16384u;
#pragma unroll
        for (int it = 0; it < 4; it++) {
            int slot = tid + it * 256;
            int r = slot >> 3, c = slot & 7;
            uint32_t so = (uint32_t)(r * 128 + ((c ^ (r & 7)) << 4));
            cp_async16(as + so, Ab + (size_t)r * Cc + kt * 64 + c * 8);
            cp_async16(bs + so, Bb + (size_t)r * Cc + kt * 64 + c * 8);
        }
    };

    float acc[2][8][4];
#pragma unroll
    for (int i = 0; i < 2; i++)
#pragma unroll
        for (int j = 0; j < 8; j++)
#pragma unroll
            for (int q = 0; q < 4; q++) acc[i][j][q] = 0.f;

    int rowA[2], rowB[4];
#pragma unroll
    for (int fm = 0; fm < 2; fm++) rowA[fm] = wm * 32 + fm * 16 + (sub & 1) * 8 + lr;
#pragma unroll
    for (int p = 0; p < 4; p++) rowB[p] = wn * 64 + p * 16 + (sub >> 1) * 8 + lr;
    int chA = sub >> 1, chB = sub & 1;

    issue(0, 0); cp_commit();
    issue(1, 1); cp_commit();

    int stage = 0;
#pragma unroll 1
    for (int kt = 0; kt < LM_NKT; kt++) {
        if (kt + 1 < LM_NKT) { cp_wait<1>(); } else { cp_wait<0>(); }
        __syncthreads();
        if (kt + 2 < LM_NKT) {
            int ns = stage + 2; if (ns >= 3) ns -= 3;
            issue(kt + 2, ns);
            cp_commit();
        }
        uint32_t as = sbase + stage * (uint32_t)LM_STAGE;
        uint32_t bs = as + 16384u;
#pragma unroll
        for (int k16 = 0; k16 < 4; k16++) {
            int cb = k16 * 2;
            uint32_t afr[2][4];
#pragma unroll
            for (int fm = 0; fm < 2; fm++) {
                int r = rowA[fm];
                ldm_x4(afr[fm], as + r * 128 + (((cb + chA) ^ (r & 7)) << 4));
            }
            uint32_t bfr[4][4];
#pragma unroll
            for (int p = 0; p < 4; p++) {
                int r = rowB[p];
                ldm_x4(bfr[p], bs + r * 128 + (((cb + chB) ^ (r & 7)) << 4));
            }
#pragma unroll
            for (int fm = 0; fm < 2; fm++)
#pragma unroll
                for (int fn = 0; fn < 8; fn++)
                    mma_f16(acc[fm][fn], afr[fm], &bfr[fn >> 1][(fn & 1) * 2]);
        }
        if (++stage >= 3) stage = 0;
    }

#pragma unroll
    for (int fm = 0; fm < 2; fm++) {
        int m_lo = m0 + wm * 32 + fm * 16 + grp;
        int m_hi = m_lo + 8;
#pragma unroll
        for (int fn = 0; fn < 8; fn++) {
            int n = n0 + wn * 64 + fn * 8 + tig * 2;
#pragma unroll
            for (int e = 0; e < 2; e++) {
                int nn = n + e;
                if (nn >= Vv) continue;
                float bv = bias[nn];
                out[(size_t)m_lo * Vv + nn] = acc[fm][fn][e]     + bv;
                out[(size_t)m_hi * Vv + nn] = acc[fm][fn][e + 2] + bv;
            }
        }
    }
}

// ---------------- host launcher ---------------------------------------------
static float* symaddr(const void* s) {
    void* p = nullptr;
    cudaGetSymbolAddress(&p, s);
    return (float*)p;
}

extern "C" void kernel_launch(void* const* d_in, const int* in_sizes, int n_in,
                              void* d_out, int out_size) {
    const int*   x    = (const int*)d_in[0];
    const float* tok  = (const float*)d_in[1];
    const float* pos  = (const float*)d_in[2];
    const float* Wq   = (const float*)d_in[3];
    const float* bq   = (const float*)d_in[4];
    const float* Wk   = (const float*)d_in[5];
    const float* bk   = (const float*)d_in[6];
    const float* Wv   = (const float*)d_in[7];
    const float* bv   = (const float*)d_in[8];
    const float* Wo   = (const float*)d_in[9];
    const float* bo   = (const float*)d_in[10];
    const float* ln1g = (const float*)d_in[11];
    const float* ln1b = (const float*)d_in[12];
    const float* W1   = (const float*)d_in[13];
    const float* b1   = (const float*)d_in[14];
    const float* W2   = (const float*)d_in[15];
    const float* b2   = (const float*)d_in[16];
    const float* ln2g = (const float*)d_in[17];
    const float* ln2b = (const float*)d_in[18];
    const float* Wlm  = (const float*)d_in[19];
    const float* blm  = (const float*)d_in[20];
    float* out = (float*)d_out;

    float* ph      = symaddr(g_h);
    __half* paH    = (__half*)symaddr(g_aH);
    __half* pqkvH  = (__half*)symaddr(g_qkvH);
    __half* pattH  = (__half*)symaddr(g_attH);
    __half* pmH    = (__half*)symaddr(g_mH);
    __half* pP     = (__half*)symaddr(g_P);
    float* ppsum   = symaddr(g_psum);
    __half* pWqkvT = (__half*)symaddr(g_WqkvT);
    float* pbqkv   = symaddr(g_bqkv);
    __half* pWoT   = (__half*)symaddr(g_WoT);
    __half* pW1T   = (__half*)symaddr(g_W1T);
    __half* pW2T   = (__half*)symaddr(g_W2T);
    __half* phH    = (__half*)symaddr(g_hH);
    __half* pWlmH  = (__half*)symaddr(g_WlmH);

    static bool attr_done = false;
    if (!attr_done) {
        cudaFuncSetAttribute((const void*)h16_gemm_kernel<0>,  cudaFuncAttributeMaxDynamicSharedMemorySize, H16_SMEM);
        cudaFuncSetAttribute((const void*)h16_gemm_kernel<1>,  cudaFuncAttributeMaxDynamicSharedMemorySize, H16_SMEM);
        cudaFuncSetAttribute((const void*)h16_gemm_kernel<2>,  cudaFuncAttributeMaxDynamicSharedMemorySize, H16_SMEM);
        cudaFuncSetAttribute((const void*)h16_gemm_kernel<18>, cudaFuncAttributeMaxDynamicSharedMemorySize, H16_SMEM);
        cudaFuncSetAttribute((const void*)lmhead_fp16_kernel,  cudaFuncAttributeMaxDynamicSharedMemorySize, LM_SMEM);
        attr_done = true;
    }

    // order matters for ncu (-s 5 -c 1 profiles launch #6 = QKV GEMM)
    embed_kernel<<<(M_ROWS * Cc + 255) / 256, 256>>>(x, tok, pos, ph);                  // 1
    int comb_total = NLl * QKV_P * Cc + NLl * QKV_P;
    repack_qkv_comb_kernel<<<(comb_total + 255) / 256, 256>>>(Wq, Wk, Wv, bq, bk, bv,
                                                              pWqkvT, pbqkv);           // 2
    transpose_all_kernel<<<dim3(Cc / 32, Cc / 32, 3 * NLl), dim3(32, 8)>>>(
        Wo, W1, W2, pWoT, pW1T, pW2T);                                                  // 3
    transpose_wlm_kernel<<<dim3(V_PAD / 32, Cc / 32), dim3(32, 8)>>>(Wlm, pWlmH);       // 4

    dim3 g_qkv_grid(M_ROWS / 64, QKV_P / 128);   // (32, 9)
    dim3 g_c_grid(M_ROWS / 64, Cc / 128);        // (32, 3)

    for (int l = 0; l < NLl; l++) {
        ln_kernel<<<M_ROWS, 128>>>(ph, ln1g + l * Cc, ln1b + l * Cc, paH);              // 5 (l=0)

        h16_gemm_kernel<0><<<g_qkv_grid, 256, H16_SMEM>>>(
            paH, pWqkvT + (size_t)l * QKV_P * Cc, pbqkv + l * QKV_P, pqkvH, nullptr, QKV_P);  // 6 (l=0)

        scores_p_kernel<<<dim3(36, 1, BH), 256>>>(pqkvH, pP, ppsum);
        pv_fp16_kernel<<<dim3(8, BH), 256>>>(pP, pqkvH, ppsum, pattH);

        h16_gemm_kernel<2><<<g_c_grid, 256, H16_SMEM>>>(
            pattH, pWoT + (size_t)l * Cc * Cc, bo + l * Cc, ph, nullptr, Cc);

        ln_kernel<<<M_ROWS, 128>>>(ph, ln2g + l * Cc, ln2b + l * Cc, paH);

        h16_gemm_kernel<1><<<g_c_grid, 256, H16_SMEM>>>(
            paH, pW1T + (size_t)l * Cc * Cc, b1 + l * Cc, pmH, nullptr, Cc);

        if (l == NLl - 1) {
            h16_gemm_kernel<18><<<g_c_grid, 256, H16_SMEM>>>(
                pmH, pW2T + (size_t)l * Cc * Cc, b2 + l * Cc, ph, phH, Cc);
        } else {
            h16_gemm_kernel<2><<<g_c_grid, 256, H16_SMEM>>>(
                pmH, pW2T + (size_t)l * Cc * Cc, b2 + l * Cc, ph, nullptr, Cc);
        }
    }

    // LM head (fp16 tensor cores, 3-stage pipeline)
    lmhead_fp16_kernel<<<dim3(M_ROWS / 128, V_PAD / 128), 256, LM_SMEM>>>(
        phH, pWlmH, blm, out);
}

// round 12
// speedup vs baseline: 9.2198x; 1.0361x over previous
#include <cuda_runtime.h>
#include <cuda_fp16.h>
#include <cstdint>

// Problem constants
constexpr int Vv = 50257, Cc = 384, Tt = 1024, Hh = 6, HSs = 64, NLl = 3, Bb = 2;
constexpr int M_ROWS = Bb * Tt;   // 2048
constexpr int BH = Bb * Hh;       // 12
constexpr int V_PAD = 50304;      // 393 * 128
constexpr int QKV_P = 3 * Cc;     // 1152

// ---------------- scratch (__device__ globals; no allocation allowed) --------
__device__ float g_h[M_ROWS * Cc];
__device__ __half g_aH[M_ROWS * Cc];               // LN output fp16
__device__ __half g_qkvH[M_ROWS * QKV_P];          // fused QKV, fp16
__device__ __half g_attH[M_ROWS * Cc];             // PV output fp16
__device__ __half g_mH[M_ROWS * Cc];               // relu(W1) output fp16
__device__ __half g_P[(size_t)BH * Tt * Tt];       // unnormalized probs [bh][k][t]
__device__ float g_psum[BH * 8 * Tt];              // per-(bh,tb) row partial sums
__device__ __half g_WqkvT[NLl * QKV_P * Cc];       // [l][n][k] fp16
__device__ float g_bqkv[NLl * QKV_P];
__device__ __half g_WoT[NLl * Cc * Cc];
__device__ __half g_W1T[NLl * Cc * Cc];
__device__ __half g_W2T[NLl * Cc * Cc];
__device__ __half g_hH[M_ROWS * Cc];               // h as fp16 (LM head input)
__device__ __half g_WlmH[(size_t)V_PAD * Cc];      // Wlm^T as fp16 [n][k]

// ---------------- embedding --------------------------------------------------
__global__ void embed_kernel(const int* __restrict__ x, const float* __restrict__ tok,
                             const float* __restrict__ pos, float* __restrict__ h) {
    int i = blockIdx.x * blockDim.x + threadIdx.x;
    if (i >= M_ROWS * Cc) return;
    int row = i / Cc, c = i % Cc;
    int t = row % Tt;
    h[i] = tok[(size_t)x[row] * Cc + c] + pos[t * Cc + c];
}

// ---------------- combined QKV weight + bias repack --------------------------
__global__ void repack_qkv_comb_kernel(const float* __restrict__ Wq, const float* __restrict__ Wk,
                                       const float* __restrict__ Wv,
                                       const float* __restrict__ bq, const float* __restrict__ bk,
                                       const float* __restrict__ bv,
                                       __half* __restrict__ OW, float* __restrict__ OB) {
    int i = blockIdx.x * blockDim.x + threadIdx.x;
    int total_w = NLl * QKV_P * Cc;
    if (i < total_w) {
        int k = i % Cc;
        int n = (i / Cc) % QKV_P;
        int l = i / (Cc * QKV_P);
        int sel = n / Cc, h = (n % Cc) / HSs, s = n % HSs;
        const float* W = (sel == 0) ? Wq : (sel == 1) ? Wk : Wv;
        OW[i] = __float2half(W[(((size_t)l * Hh + h) * Cc + k) * HSs + s]);
    } else {
        int j = i - total_w;
        if (j < NLl * QKV_P) {
            int n = j % QKV_P, l = j / QKV_P;
            int sel = n / Cc, h = (n % Cc) / HSs, s = n % HSs;
            const float* B = (sel == 0) ? bq : (sel == 1) ? bk : bv;
            OB[j] = B[((size_t)l * Hh + h) * HSs + s];
        }
    }
}

// ---------------- all three square weights transposed in one launch ----------
__global__ void transpose_all_kernel(const float* __restrict__ Wo, const float* __restrict__ W1,
                                     const float* __restrict__ W2,
                                     __half* __restrict__ To, __half* __restrict__ T1,
                                     __half* __restrict__ T2) {
    __shared__ float t[32][33];
    int wi = blockIdx.z % 3, l = blockIdx.z / 3;
    const float* W = ((wi == 0) ? Wo : (wi == 1) ? W1 : W2) + (size_t)l * Cc * Cc;
    __half* T = ((wi == 0) ? To : (wi == 1) ? T1 : T2) + (size_t)l * Cc * Cc;
    int n0 = blockIdx.x * 32, k0 = blockIdx.y * 32;
    for (int dy = threadIdx.y; dy < 32; dy += 8)
        t[dy][threadIdx.x] = W[(size_t)(k0 + dy) * Cc + n0 + threadIdx.x];
    __syncthreads();
    for (int dy = threadIdx.y; dy < 32; dy += 8)
        T[(size_t)(n0 + dy) * Cc + k0 + threadIdx.x] = __float2half(t[threadIdx.x][dy]);
}

// Wlm (K=384 x V) -> WlmH (V_PAD x K) fp16. 64k x 64n tiles, vectorized stores.
__global__ __launch_bounds__(256)
void transpose_wlm_kernel(const float* __restrict__ Wlm, __half* __restrict__ Bt) {
    __shared__ float tile[64][65];
    int n0 = blockIdx.x * 64, k0 = blockIdx.y * 64;
    int tid = threadIdx.x;
    // load 64 k-rows x 64 n-cols (scalar: Wlm rows are only 4B-aligned, Vv odd)
#pragma unroll
    for (int it = 0; it < 16; it++) {
        int idx = tid + it * 256;           // 4096 elements
        int r = idx >> 6, c = idx & 63;     // r = k offset, c = n offset
        int n = n0 + c;
        tile[r][c] = (n < Vv) ? Wlm[(size_t)(k0 + r) * Vv + n] : 0.f;
    }
    __syncthreads();
    // store: each thread emits uint4 = 8 halfs along k for one n
#pragma unroll
    for (int it = 0; it < 2; it++) {
        int idx = tid + it * 256;           // 512 chunks: 64 n x 8 k-chunks
        int n = idx >> 3, kc = idx & 7;
        __half hv[8];
#pragma unroll
        for (int j = 0; j < 8; j++) hv[j] = __float2half(tile[kc * 8 + j][n]);
        *reinterpret_cast<uint4*>(Bt + (size_t)(n0 + n) * Cc + k0 + kc * 8) =
            *reinterpret_cast<const uint4*>(hv);
    }
}

// ---------------- layernorm (vectorized, fp16 out) ---------------------------
__global__ void ln_kernel(const float* __restrict__ x, const float* __restrict__ g,
                          const float* __restrict__ b, __half* __restrict__ y) {
    int row = blockIdx.x;
    const float4* xr4 = reinterpret_cast<const float4*>(x + (size_t)row * Cc);
    float4 v = make_float4(0.f, 0.f, 0.f, 0.f);
    int tid = threadIdx.x;
    if (tid < 96) v = xr4[tid];
    float lsum = v.x + v.y + v.z + v.w;
    float lsq = v.x * v.x + v.y * v.y + v.z * v.z + v.w * v.w;
    __shared__ float sh[64];
    int lane = tid & 31, wid = tid >> 5;
#pragma unroll
    for (int o = 16; o; o >>= 1) {
        lsum += __shfl_xor_sync(0xffffffffu, lsum, o);
        lsq  += __shfl_xor_sync(0xffffffffu, lsq,  o);
    }
    if (lane == 0) { sh[wid] = lsum; sh[wid + 32] = lsq; }
    __syncthreads();
    if (tid == 0) {
        float s = 0.f, q = 0.f;
        for (int w = 0; w < 4; w++) { s += sh[w]; q += sh[w + 32]; }
        sh[0] = s; sh[32] = q;
    }
    __syncthreads();
    float mu = sh[0] / Cc;
    float var = sh[32] / Cc - mu * mu;
    float rstd = rsqrtf(var + 1e-5f);
    if (tid < 96) {
        const float4 g4 = reinterpret_cast<const float4*>(g)[tid];
        const float4 b4 = reinterpret_cast<const float4*>(b)[tid];
        __half2 o0 = __floats2half2_rn((v.x - mu) * rstd * g4.x + b4.x,
                                       (v.y - mu) * rstd * g4.y + b4.y);
        __half2 o1 = __floats2half2_rn((v.z - mu) * rstd * g4.z + b4.z,
                                       (v.w - mu) * rstd * g4.w + b4.w);
        uint2 pack;
        pack.x = *reinterpret_cast<uint32_t*>(&o0);
        pack.y = *reinterpret_cast<uint32_t*>(&o1);
        reinterpret_cast<uint2*>(y + (size_t)row * Cc)[tid] = pack;
    }
}

// ---------------- common asm helpers ----------------------------------------
__device__ __forceinline__ uint32_t smem_u32(const void* p) {
    uint32_t a;
    asm("{ .reg .u64 t; cvta.to.shared.u64 t, %1; cvt.u32.u64 %0, t; }" : "=r"(a) : "l"(p));
    return a;
}
__device__ __forceinline__ void cp_async16(uint32_t saddr, const void* g) {
    asm volatile("cp.async.cg.shared.global [%0], [%1], 16;" :: "r"(saddr), "l"(g) : "memory");
}
__device__ __forceinline__ void cp_commit() {
    asm volatile("cp.async.commit_group;" ::: "memory");
}
template<int N>
__device__ __forceinline__ void cp_wait() {
    asm volatile("cp.async.wait_group %0;" :: "n"(N) : "memory");
}
__device__ __forceinline__ void ldm_x4(uint32_t* r, uint32_t addr) {
    asm volatile("ldmatrix.sync.aligned.m8n8.x4.shared.b16 {%0,%1,%2,%3}, [%4];"
                 : "=r"(r[0]), "=r"(r[1]), "=r"(r[2]), "=r"(r[3]) : "r"(addr));
}
__device__ __forceinline__ void ldm_x4_trans(uint32_t* r, uint32_t addr) {
    asm volatile("ldmatrix.sync.aligned.m8n8.x4.trans.shared.b16 {%0,%1,%2,%3}, [%4];"
                 : "=r"(r[0]), "=r"(r[1]), "=r"(r[2]), "=r"(r[3]) : "r"(addr));
}
__device__ __forceinline__ void mma_f16(float* c, const uint32_t* a, const uint32_t* b) {
    asm volatile(
        "mma.sync.aligned.m16n8k16.row.col.f32.f16.f16.f32 "
        "{%0,%1,%2,%3}, {%4,%5,%6,%7}, {%8,%9}, {%0,%1,%2,%3};"
        : "+f"(c[0]), "+f"(c[1]), "+f"(c[2]), "+f"(c[3])
        : "r"(a[0]), "r"(a[1]), "r"(a[2]), "r"(a[3]), "r"(b[0]), "r"(b[1]));
}

// ================= fp16 layer GEMM: CTA 64x128, K-tile 64, 3-stage ===========
constexpr int H16_NKT = Cc / 64;      // 6
constexpr int H16_STAGE = 24576;      // A 8KB + B 16KB
constexpr int H16_SMEM = 3 * H16_STAGE;  // 72KB

template<int FLAGS>  // 1=relu, 2=accumulate fp32, 16=also fp16 aux copy
__global__ __launch_bounds__(256, 2)
void h16_gemm_kernel(const __half* __restrict__ A, const __half* __restrict__ Bt,
                     const float* __restrict__ bias, void* __restrict__ Cv,
                     __half* __restrict__ aux, int ldc) {
    extern __shared__ __half smh[];
    int tid = threadIdx.x;
    int warp = tid >> 5, lane = tid & 31;
    int wm = warp & 1, wn = warp >> 1;
    int grp = lane >> 2, tig = lane & 3;
    int lr = lane & 7, sub = lane >> 3;
    int m0 = blockIdx.x * 64, n0 = blockIdx.y * 128;
    const __half* Ab = A + (size_t)m0 * Cc;
    const __half* Bb = Bt + (size_t)n0 * Cc;
    uint32_t sbase = smem_u32(smh);

    auto issue = [&](int kt, int stage) {
        uint32_t as = sbase + stage * (uint32_t)H16_STAGE;
        uint32_t bs = as + 8192u;
#pragma unroll
        for (int it = 0; it < 2; it++) {
            int slot = tid + it * 256;
            int r = slot >> 3, c = slot & 7;
            uint32_t so = (uint32_t)(r * 128 + ((c ^ (r & 7)) << 4));
            cp_async16(as + so, Ab + (size_t)r * Cc + kt * 64 + c * 8);
        }
#pragma unroll
        for (int it = 0; it < 4; it++) {
            int slot = tid + it * 256;
            int r = slot >> 3, c = slot & 7;
            uint32_t so = (uint32_t)(r * 128 + ((c ^ (r & 7)) << 4));
            cp_async16(bs + so, Bb + (size_t)r * Cc + kt * 64 + c * 8);
        }
    };

    float acc[2][4][4];
#pragma unroll
    for (int i = 0; i < 2; i++)
#pragma unroll
        for (int j = 0; j < 4; j++)
#pragma unroll
            for (int q = 0; q < 4; q++) acc[i][j][q] = 0.f;

    int rowA[2], rowB[2];
#pragma unroll
    for (int fm = 0; fm < 2; fm++) rowA[fm] = wm * 32 + fm * 16 + (sub & 1) * 8 + lr;
#pragma unroll
    for (int p = 0; p < 2; p++) rowB[p] = wn * 32 + p * 16 + (sub >> 1) * 8 + lr;
    int chA = sub >> 1, chB = sub & 1;

    issue(0, 0); cp_commit();
    issue(1, 1); cp_commit();

    int stage = 0;
#pragma unroll 1
    for (int kt = 0; kt < H16_NKT; kt++) {
        if (kt + 1 < H16_NKT) { cp_wait<1>(); } else { cp_wait<0>(); }
        __syncthreads();
        if (kt + 2 < H16_NKT) {
            int ns = stage + 2; if (ns >= 3) ns -= 3;
            issue(kt + 2, ns);
            cp_commit();
        }
        uint32_t as = sbase + stage * (uint32_t)H16_STAGE;
        uint32_t bs = as + 8192u;
#pragma unroll
        for (int k16 = 0; k16 < 4; k16++) {
            int cb = k16 * 2;
            uint32_t afr[2][4];
#pragma unroll
            for (int fm = 0; fm < 2; fm++) {
                int r = rowA[fm];
                ldm_x4(afr[fm], as + r * 128 + (((cb + chA) ^ (r & 7)) << 4));
            }
            uint32_t bfr[2][4];
#pragma unroll
            for (int p = 0; p < 2; p++) {
                int r = rowB[p];
                ldm_x4(bfr[p], bs + r * 128 + (((cb + chB) ^ (r & 7)) << 4));
            }
#pragma unroll
            for (int fm = 0; fm < 2; fm++)
#pragma unroll
                for (int fn = 0; fn < 4; fn++)
                    mma_f16(acc[fm][fn], afr[fm], &bfr[fn >> 1][(fn & 1) * 2]);
        }
        if (++stage >= 3) stage = 0;
    }

#pragma unroll
    for (int fm = 0; fm < 2; fm++) {
        int m_lo = m0 + wm * 32 + fm * 16 + grp;
        int m_hi = m_lo + 8;
#pragma unroll
        for (int fn = 0; fn < 4; fn++) {
            int n = n0 + wn * 32 + fn * 8 + tig * 2;
#pragma unroll
            for (int e = 0; e < 2; e++) {
                int nn = n + e;
                float bv = bias[nn];
                float v0 = acc[fm][fn][e]     + bv;
                float v1 = acc[fm][fn][e + 2] + bv;
                if (FLAGS & 1) { v0 = fmaxf(v0, 0.f); v1 = fmaxf(v1, 0.f); }
                if constexpr ((FLAGS & 2) != 0) {
                    float* C = (float*)Cv;
                    v0 += C[(size_t)m_lo * ldc + nn];
                    v1 += C[(size_t)m_hi * ldc + nn];
                    C[(size_t)m_lo * ldc + nn] = v0;
                    C[(size_t)m_hi * ldc + nn] = v1;
                    if constexpr ((FLAGS & 16) != 0) {
                        aux[(size_t)m_lo * ldc + nn] = __float2half(v0);
                        aux[(size_t)m_hi * ldc + nn] = __float2half(v1);
                    }
                } else {
                    __half* C = (__half*)Cv;
                    C[(size_t)m_lo * ldc + nn] = __float2half(v0);
                    C[(size_t)m_hi * ldc + nn] = __float2half(v1);
                }
            }
        }
    }
}

// ======== scores + exp + row-partial-sums (fp16 mma), P unnormalized =========
// grid: (36 lower-tri tile pairs, 1, BH)
__global__ __launch_bounds__(256, 2)
void scores_p_kernel(const __half* __restrict__ qkvH, __half* __restrict__ P,
                     float* __restrict__ psum) {
    int q = blockIdx.x, bh = blockIdx.z;
    int tb = 0;
    while ((tb + 1) * (tb + 2) / 2 <= q) tb++;
    int kb = q - tb * (tb + 1) / 2;
    int b = bh / Hh, h = bh % Hh;
    int k0 = kb * 128, t0 = tb * 128;

    __shared__ __align__(16) __half ssm[128 * 136];
    __shared__ float sums[128][2];

    int tid = threadIdx.x;
    int warp = tid >> 5, lane = tid & 31;
    int wm = warp & 3, wn = warp >> 2;
    int grp = lane >> 2, tig = lane & 3;
    int lr = lane & 7, sub = lane >> 3;

    uint32_t sb = smem_u32(ssm);
    uint32_t Ksb = sb, Qsb = sb + 16384u;
    const __half* Kb_ = qkvH + (size_t)(b * Tt + k0) * QKV_P + Cc + h * HSs;
    const __half* Qb_ = qkvH + (size_t)(b * Tt + t0) * QKV_P + h * HSs;

#pragma unroll
    for (int it = 0; it < 4; it++) {
        int slot = tid + it * 256;
        int r = slot >> 3, c = slot & 7;
        uint32_t so = (uint32_t)(r * 128 + ((c ^ (r & 7)) << 4));
        cp_async16(Ksb + so, Kb_ + (size_t)r * QKV_P + c * 8);
        cp_async16(Qsb + so, Qb_ + (size_t)r * QKV_P + c * 8);
    }
    cp_commit();
    cp_wait<0>();
    __syncthreads();

    float acc[2][8][4];
#pragma unroll
    for (int i = 0; i < 2; i++)
#pragma unroll
        for (int j = 0; j < 8; j++)
#pragma unroll
            for (int q2 = 0; q2 < 4; q2++) acc[i][j][q2] = 0.f;

    int rowA[2], rowB[4];
#pragma unroll
    for (int fm = 0; fm < 2; fm++) rowA[fm] = wm * 32 + fm * 16 + (sub & 1) * 8 + lr;
#pragma unroll
    for (int p = 0; p < 4; p++) rowB[p] = wn * 64 + p * 16 + (sub >> 1) * 8 + lr;
    int chA = sub >> 1, chB = sub & 1;

#pragma unroll
    for (int k16 = 0; k16 < 4; k16++) {
        int cb = k16 * 2;
        uint32_t afr[2][4];
#pragma unroll
        for (int fm = 0; fm < 2; fm++) {
            int r = rowA[fm];
            ldm_x4(afr[fm], Ksb + r * 128 + (((cb + chA) ^ (r & 7)) << 4));
        }
        uint32_t bfr[4][4];
#pragma unroll
        for (int p = 0; p < 4; p++) {
            int r = rowB[p];
            ldm_x4(bfr[p], Qsb + r * 128 + (((cb + chB) ^ (r & 7)) << 4));
        }
#pragma unroll
        for (int fm = 0; fm < 2; fm++)
#pragma unroll
            for (int fn = 0; fn < 8; fn++)
                mma_f16(acc[fm][fn], afr[fm], &bfr[fn >> 1][(fn & 1) * 2]);
    }
    __syncthreads();

    float rp[2][2] = {{0.f, 0.f}, {0.f, 0.f}};
#pragma unroll
    for (int fm = 0; fm < 2; fm++) {
        int kl = wm * 32 + fm * 16 + grp;
        int kh = kl + 8;
#pragma unroll
        for (int fn = 0; fn < 8; fn++) {
            int tc = wn * 64 + fn * 8 + tig * 2;
#pragma unroll
            for (int e = 0; e < 2; e++) {
                int t = tc + e;
                float v0 = (t0 + t >= k0 + kl) ? __expf(0.125f * acc[fm][fn][e]) : 0.f;
                float v1 = (t0 + t >= k0 + kh) ? __expf(0.125f * acc[fm][fn][e + 2]) : 0.f;
                ssm[kl * 136 + t] = __float2half(v0);
                ssm[kh * 136 + t] = __float2half(v1);
                rp[fm][0] += v0;
                rp[fm][1] += v1;
            }
        }
    }
#pragma unroll
    for (int fm = 0; fm < 2; fm++)
#pragma unroll
        for (int hl = 0; hl < 2; hl++) {
            rp[fm][hl] += __shfl_xor_sync(0xffffffffu, rp[fm][hl], 1);
            rp[fm][hl] += __shfl_xor_sync(0xffffffffu, rp[fm][hl], 2);
        }
    if (tig == 0) {
#pragma unroll
        for (int fm = 0; fm < 2; fm++) {
            sums[wm * 32 + fm * 16 + grp][wn]     = rp[fm][0];
            sums[wm * 32 + fm * 16 + grp + 8][wn] = rp[fm][1];
        }
    }
    __syncthreads();

    __half* Pb = P + ((size_t)bh * Tt + k0) * Tt + t0;
#pragma unroll
    for (int i = 0; i < 8; i++) {
        int idx = tid + i * 256;
        int r = idx >> 4, c = idx & 15;
        uint4 v = *reinterpret_cast<const uint4*>(&ssm[r * 136 + c * 8]);
        *reinterpret_cast<uint4*>(Pb + (size_t)r * Tt + c * 8) = v;
    }
    if (tid < 128)
        psum[((size_t)bh * 8 + tb) * Tt + k0 + tid] = sums[tid][0] + sums[tid][1];
}

// ---------------- PV via fp16 mma: cp.async P + ldmatrix.trans ----------------
__global__ __launch_bounds__(256, 2)
void pv_fp16_kernel(const __half* __restrict__ P, const __half* __restrict__ qkvH,
                    const float* __restrict__ psum, __half* __restrict__ att) {
    int tb = blockIdx.x, bh = blockIdx.y;
    int b = bh / Hh, h = bh % Hh;
    int t0 = tb * 128;

    __shared__ __align__(16) __half Pt[64 * 128];  // [k][t] 256B rows
    __shared__ __align__(16) __half Vt[64 * 64];   // [s][k] 128B rows
    __shared__ float invs[1024];

    int tid = threadIdx.x;
    int warp = tid >> 5, lane = tid & 31;
    int wm = warp & 3, wn = warp >> 2;
    int grp = lane >> 2, tig = lane & 3;
    int lr = lane & 7, sub = lane >> 3;

    uint32_t Ptb = smem_u32(Pt), Vtb = smem_u32(Vt);

    int nk = 2 * (tb + 1);
    int Kext = nk * 64;
    for (int i = tid; i < Kext; i += 256) {
        int tb0 = i >> 7;
        float s = 0.f;
        for (int t2 = tb0; t2 < 8; t2++)
            s += psum[((size_t)bh * 8 + t2) * Tt + i];
        invs[i] = 1.f / s;
    }

    float acc[2][4][4];
#pragma unroll
    for (int i = 0; i < 2; i++)
#pragma unroll
        for (int j = 0; j < 4; j++)
#pragma unroll
            for (int q = 0; q < 4; q++) acc[i][j][q] = 0.f;

    int rowB[2];
#pragma unroll
    for (int p = 0; p < 2; p++) rowB[p] = wn * 32 + p * 16 + (sub >> 1) * 8 + lr;
    int chB = sub & 1;
    int tcolA = wm * 32 + (sub & 1) * 8;
    int krowA = (sub >> 1) * 8 + lr;

#pragma unroll 1
    for (int kt = 0; kt < nk; kt++) {
        int k0 = kt * 64;
        __syncthreads();
        const __half* Pg = P + ((size_t)bh * Tt + k0) * Tt + t0;
#pragma unroll
        for (int i = 0; i < 4; i++) {
            int idx = tid + i * 256;
            int r = idx >> 4, c = idx & 15;
            uint32_t so = (uint32_t)(r * 256 + ((c ^ (r & 7)) << 4));
            cp_async16(Ptb + so, Pg + (size_t)r * Tt + c * 8);
        }
        cp_commit();
        const __half* Vg = qkvH + (size_t)(b * Tt + k0) * QKV_P + 2 * Cc + h * HSs;
#pragma unroll
        for (int i = 0; i < 8; i++) {
            int idx = tid + i * 256;
            int kk = idx >> 5, sp = idx & 31;
            uint32_t v = *reinterpret_cast<const uint32_t*>(Vg + (size_t)kk * QKV_P + sp * 2);
            float iv = invs[k0 + kk];
            __half2 h2 = *(const __half2*)&v;
            __half s0 = __float2half(__half2float(h2.x) * iv);
            __half s1 = __float2half(__half2float(h2.y) * iv);
            int s_ = sp * 2;
            Vt[s_ * 64 + ((((kk >> 3) ^ (s_ & 7)) << 3) | (kk & 7))] = s0;
            s_++;
            Vt[s_ * 64 + ((((kk >> 3) ^ (s_ & 7)) << 3) | (kk & 7))] = s1;
        }
        cp_wait<0>();
        __syncthreads();
#pragma unroll
        for (int k16 = 0; k16 < 4; k16++) {
            uint32_t afr[2][4];
#pragma unroll
            for (int fm = 0; fm < 2; fm++) {
                int krow = k16 * 16 + krowA;
                int tcol = tcolA + fm * 16;
                uint32_t addr = Ptb + krow * 256 + ((((tcol >> 3) ^ (krow & 7)) << 4));
                ldm_x4_trans(afr[fm], addr);
            }
            int cb = k16 * 2;
            uint32_t bfr[2][4];
#pragma unroll
            for (int p = 0; p < 2; p++) {
                int r = rowB[p];
                ldm_x4(bfr[p], Vtb + r * 128 + (((cb + chB) ^ (r & 7)) << 4));
            }
#pragma unroll
            for (int fm = 0; fm < 2; fm++)
#pragma unroll
                for (int fn = 0; fn < 4; fn++)
                    mma_f16(acc[fm][fn], afr[fm], &bfr[fn >> 1][(fn & 1) * 2]);
        }
    }

#pragma unroll
    for (int fm = 0; fm < 2; fm++) {
        int m_lo = t0 + wm * 32 + fm * 16 + grp;
        int m_hi = m_lo + 8;
#pragma unroll
        for (int fn = 0; fn < 4; fn++) {
            int s = wn * 32 + fn * 8 + tig * 2;
#pragma unroll
            for (int e = 0; e < 2; e++) {
                att[(size_t)(b * Tt + m_lo) * Cc + h * HSs + s + e] = __float2half(acc[fm][fn][e]);
                att[(size_t)(b * Tt + m_hi) * Cc + h * HSs + s + e] = __float2half(acc[fm][fn][e + 2]);
            }
        }
    }
}

// ================= fp16 LM head: 3-stage pipeline ============================
constexpr int LM_NKT = Cc / 64;       // 6
constexpr int LM_STAGE = 32768;       // A 16KB + B 16KB
constexpr int LM_SMEM = 3 * LM_STAGE; // 96KB

__global__ __launch_bounds__(256, 2)
void lmhead_fp16_kernel(const __half* __restrict__ A, const __half* __restrict__ Bt,
                        const float* __restrict__ bias, float* __restrict__ out) {
    extern __shared__ __half smh[];
    int tid = threadIdx.x;
    int warp = tid >> 5, lane = tid & 31;
    int wm = warp & 3, wn = warp >> 2;
    int grp = lane >> 2, tig = lane & 3;
    int lr = lane & 7, sub = lane >> 3;
    int m0 = blockIdx.x * 128, n0 = blockIdx.y * 128;
    const __half* Ab = A + (size_t)m0 * Cc;
    const __half* Bb = Bt + (size_t)n0 * Cc;

    uint32_t sbase = smem_u32(smh);

    auto issue = [&](int kt, int stage) {
        uint32_t as = sbase + stage * (uint32_t)LM_STAGE;
        uint32_t bs = as + 16384u;
#pragma unroll
        for (int it = 0; it < 4; it++) {
            int slot = tid + it * 256;
            int r = slot >> 3, c = slot & 7;
            uint32_t so = (uint32_t)(r * 128 + ((c ^ (r & 7)) << 4));
            cp_async16(as + so, Ab + (size_t)r * Cc + kt * 64 + c * 8);
            cp_async16(bs + so, Bb + (size_t)r * Cc + kt * 64 + c * 8);
        }
    };

    float acc[2][8][4];
#pragma unroll
    for (int i = 0; i < 2; i++)
#pragma unroll
        for (int j = 0; j < 8; j++)
#pragma unroll
            for (int q = 0; q < 4; q++) acc[i][j][q] = 0.f;

    int rowA[2], rowB[4];
#pragma unroll
    for (int fm = 0; fm < 2; fm++) rowA[fm] = wm * 32 + fm * 16 + (sub & 1) * 8 + lr;
#pragma unroll
    for (int p = 0; p < 4; p++) rowB[p] = wn * 64 + p * 16 + (sub >> 1) * 8 + lr;
    int chA = sub >> 1, chB = sub & 1;

    issue(0, 0); cp_commit();
    issue(1, 1); cp_commit();

    int stage = 0;
#pragma unroll 1
    for (int kt = 0; kt < LM_NKT; kt++) {
        if (kt + 1 < LM_NKT) { cp_wait<1>(); } else { cp_wait<0>(); }
        __syncthreads();
        if (kt + 2 < LM_NKT) {
            int ns = stage + 2; if (ns >= 3) ns -= 3;
            issue(kt + 2, ns);
            cp_commit();
        }
        uint32_t as = sbase + stage * (uint32_t)LM_STAGE;
        uint32_t bs = as + 16384u;
#pragma unroll
        for (int k16 = 0; k16 < 4; k16++) {
            int cb = k16 * 2;
            uint32_t afr[2][4];
#pragma unroll
            for (int fm = 0; fm < 2; fm++) {
                int r = rowA[fm];
                ldm_x4(afr[fm], as + r * 128 + (((cb + chA) ^ (r & 7)) << 4));
            }
            uint32_t bfr[4][4];
#pragma unroll
            for (int p = 0; p < 4; p++) {
                int r = rowB[p];
                ldm_x4(bfr[p], bs + r * 128 + (((cb + chB) ^ (r & 7)) << 4));
            }
#pragma unroll
            for (int fm = 0; fm < 2; fm++)
#pragma unroll
                for (int fn = 0; fn < 8; fn++)
                    mma_f16(acc[fm][fn], afr[fm], &bfr[fn >> 1][(fn & 1) * 2]);
        }
        if (++stage >= 3) stage = 0;
    }

#pragma unroll
    for (int fm = 0; fm < 2; fm++) {
        int m_lo = m0 + wm * 32 + fm * 16 + grp;
        int m_hi = m_lo + 8;
#pragma unroll
        for (int fn = 0; fn < 8; fn++) {
            int n = n0 + wn * 64 + fn * 8 + tig * 2;
#pragma unroll
            for (int e = 0; e < 2; e++) {
                int nn = n + e;
                if (nn >= Vv) continue;
                float bv = bias[nn];
                out[(size_t)m_lo * Vv + nn] = acc[fm][fn][e]     + bv;
                out[(size_t)m_hi * Vv + nn] = acc[fm][fn][e + 2] + bv;
            }
        }
    }
}

// ---------------- host launcher ---------------------------------------------
static float* symaddr(const void* s) {
    void* p = nullptr;
    cudaGetSymbolAddress(&p, s);
    return (float*)p;
}

extern "C" void kernel_launch(void* const* d_in, const int* in_sizes, int n_in,
                              void* d_out, int out_size) {
    const int*   x    = (const int*)d_in[0];
    const float* tok  = (const float*)d_in[1];
    const float* pos  = (const float*)d_in[2];
    const float* Wq   = (const float*)d_in[3];
    const float* bq   = (const float*)d_in[4];
    const float* Wk   = (const float*)d_in[5];
    const float* bk   = (const float*)d_in[6];
    const float* Wv   = (const float*)d_in[7];
    const float* bv   = (const float*)d_in[8];
    const float* Wo   = (const float*)d_in[9];
    const float* bo   = (const float*)d_in[10];
    const float* ln1g = (const float*)d_in[11];
    const float* ln1b = (const float*)d_in[12];
    const float* W1   = (const float*)d_in[13];
    const float* b1   = (const float*)d_in[14];
    const float* W2   = (const float*)d_in[15];
    const float* b2   = (const float*)d_in[16];
    const float* ln2g = (const float*)d_in[17];
    const float* ln2b = (const float*)d_in[18];
    const float* Wlm  = (const float*)d_in[19];
    const float* blm  = (const float*)d_in[20];
    float* out = (float*)d_out;

    float* ph      = symaddr(g_h);
    __half* paH    = (__half*)symaddr(g_aH);
    __half* pqkvH  = (__half*)symaddr(g_qkvH);
    __half* pattH  = (__half*)symaddr(g_attH);
    __half* pmH    = (__half*)symaddr(g_mH);
    __half* pP     = (__half*)symaddr(g_P);
    float* ppsum   = symaddr(g_psum);
    __half* pWqkvT = (__half*)symaddr(g_WqkvT);
    float* pbqkv   = symaddr(g_bqkv);
    __half* pWoT   = (__half*)symaddr(g_WoT);
    __half* pW1T   = (__half*)symaddr(g_W1T);
    __half* pW2T   = (__half*)symaddr(g_W2T);
    __half* phH    = (__half*)symaddr(g_hH);
    __half* pWlmH  = (__half*)symaddr(g_WlmH);

    static bool attr_done = false;
    if (!attr_done) {
        cudaFuncSetAttribute((const void*)h16_gemm_kernel<0>,  cudaFuncAttributeMaxDynamicSharedMemorySize, H16_SMEM);
        cudaFuncSetAttribute((const void*)h16_gemm_kernel<1>,  cudaFuncAttributeMaxDynamicSharedMemorySize, H16_SMEM);
        cudaFuncSetAttribute((const void*)h16_gemm_kernel<2>,  cudaFuncAttributeMaxDynamicSharedMemorySize, H16_SMEM);
        cudaFuncSetAttribute((const void*)h16_gemm_kernel<18>, cudaFuncAttributeMaxDynamicSharedMemorySize, H16_SMEM);
        cudaFuncSetAttribute((const void*)lmhead_fp16_kernel,  cudaFuncAttributeMaxDynamicSharedMemorySize, LM_SMEM);
        attr_done = true;
    }

    embed_kernel<<<(M_ROWS * Cc + 255) / 256, 256>>>(x, tok, pos, ph);
    int comb_total = NLl * QKV_P * Cc + NLl * QKV_P;
    repack_qkv_comb_kernel<<<(comb_total + 255) / 256, 256>>>(Wq, Wk, Wv, bq, bk, bv,
                                                              pWqkvT, pbqkv);
    transpose_all_kernel<<<dim3(Cc / 32, Cc / 32, 3 * NLl), dim3(32, 8)>>>(
        Wo, W1, W2, pWoT, pW1T, pW2T);
    transpose_wlm_kernel<<<dim3(V_PAD / 64, Cc / 64), 256>>>(Wlm, pWlmH);

    dim3 g_qkv_grid(M_ROWS / 64, QKV_P / 128);   // (32, 9)
    dim3 g_c_grid(M_ROWS / 64, Cc / 128);        // (32, 3)

    for (int l = 0; l < NLl; l++) {
        ln_kernel<<<M_ROWS, 128>>>(ph, ln1g + l * Cc, ln1b + l * Cc, paH);

        h16_gemm_kernel<0><<<g_qkv_grid, 256, H16_SMEM>>>(
            paH, pWqkvT + (size_t)l * QKV_P * Cc, pbqkv + l * QKV_P, pqkvH, nullptr, QKV_P);

        scores_p_kernel<<<dim3(36, 1, BH), 256>>>(pqkvH, pP, ppsum);
        pv_fp16_kernel<<<dim3(8, BH), 256>>>(pP, pqkvH, ppsum, pattH);

        h16_gemm_kernel<2><<<g_c_grid, 256, H16_SMEM>>>(
            pattH, pWoT + (size_t)l * Cc * Cc, bo + l * Cc, ph, nullptr, Cc);

        ln_kernel<<<M_ROWS, 128>>>(ph, ln2g + l * Cc, ln2b + l * Cc, paH);

        h16_gemm_kernel<1><<<g_c_grid, 256, H16_SMEM>>>(
            paH, pW1T + (size_t)l * Cc * Cc, b1 + l * Cc, pmH, nullptr, Cc);

        if (l == NLl - 1) {
            h16_gemm_kernel<18><<<g_c_grid, 256, H16_SMEM>>>(
                pmH, pW2T + (size_t)l * Cc * Cc, b2 + l * Cc, ph, phH, Cc);
        } else {
            h16_gemm_kernel<2><<<g_c_grid, 256, H16_SMEM>>>(
                pmH, pW2T + (size_t)l * Cc * Cc, b2 + l * Cc, ph, nullptr, Cc);
        }
    }

    // LM head (fp16 tensor cores, 3-stage pipeline)
    lmhead_fp16_kernel<<<dim3(M_ROWS / 128, V_PAD / 128), 256, LM_SMEM>>>(
        phH, pWlmH, blm, out);
}

// round 13
// speedup vs baseline: 9.2746x; 1.0059x over previous
#include <cuda_runtime.h>
#include <cuda_fp16.h>
#include <cstdint>

// Problem constants
constexpr int Vv = 50257, Cc = 384, Tt = 1024, Hh = 6, HSs = 64, NLl = 3, Bb = 2;
constexpr int M_ROWS = Bb * Tt;   // 2048
constexpr int BH = Bb * Hh;       // 12
constexpr int V_PAD = 50304;      // 393 * 128
constexpr int QKV_P = 3 * Cc;     // 1152

// ---------------- scratch (__device__ globals; no allocation allowed) --------
__device__ float g_h[M_ROWS * Cc];
__device__ __half g_aH[M_ROWS * Cc];               // LN output fp16
__device__ __half g_qkvH[M_ROWS * QKV_P];          // fused QKV, fp16
__device__ __half g_attH[M_ROWS * Cc];             // PV output fp16
__device__ __half g_mH[M_ROWS * Cc];               // relu(W1) output fp16
__device__ __half g_P[(size_t)BH * Tt * Tt];       // unnormalized probs [bh][k][t]
__device__ float g_psum[BH * 8 * Tt];              // per-(bh,tb) row partial sums
__device__ __half g_WqkvT[NLl * QKV_P * Cc];       // [l][n][k] fp16
__device__ float g_bqkv[NLl * QKV_P];
__device__ __half g_WoT[NLl * Cc * Cc];
__device__ __half g_W1T[NLl * Cc * Cc];
__device__ __half g_W2T[NLl * Cc * Cc];
__device__ __half g_hH[M_ROWS * Cc];               // h as fp16 (LM head input)
__device__ __half g_WlmH[(size_t)V_PAD * Cc];      // Wlm^T as fp16 [n][k]

// ---------------- embedding --------------------------------------------------
__global__ void embed_kernel(const int* __restrict__ x, const float* __restrict__ tok,
                             const float* __restrict__ pos, float* __restrict__ h) {
    int i = blockIdx.x * blockDim.x + threadIdx.x;
    if (i >= M_ROWS * Cc) return;
    int row = i / Cc, c = i % Cc;
    int t = row % Tt;
    h[i] = tok[(size_t)x[row] * Cc + c] + pos[t * Cc + c];
}

// ---------------- unified weight prep (one launch) ---------------------------
// Region 0: Wlm (K=384 x V) -> WlmH (V_PAD x K) fp16, 64x64 tiles, uint4 stores
// Region 1: Wo/W1/W2 [l][k][n] -> [l][n][k] fp16, 32x32 tiles
// Region 2: Wq/Wk/Wv (NL,H,C,HS) + biases -> WqkvT [l][n][k] fp16 + bqkv
constexpr int NB_WLM = (V_PAD / 64) * (Cc / 64);            // 786*6 = 4716
constexpr int NB_TRA = (Cc / 32) * (Cc / 32) * 3 * NLl;     // 12*12*9 = 1296
constexpr int QKV_ELEMS = NLl * QKV_P * Cc + NLl * QKV_P;   // 1330560
constexpr int NB_QKV = (QKV_ELEMS + 255) / 256;             // 5198

__global__ __launch_bounds__(256)
void prep_kernel(const float* __restrict__ Wlm, __half* __restrict__ Bt,
                 const float* __restrict__ Wo, const float* __restrict__ W1,
                 const float* __restrict__ W2,
                 __half* __restrict__ To, __half* __restrict__ T1, __half* __restrict__ T2,
                 const float* __restrict__ Wq, const float* __restrict__ Wk,
                 const float* __restrict__ Wv,
                 const float* __restrict__ bq, const float* __restrict__ bk,
                 const float* __restrict__ bv,
                 __half* __restrict__ OW, float* __restrict__ OB) {
    __shared__ float tile[64 * 65];
    int bid = blockIdx.x;
    int tid = threadIdx.x;

    if (bid < NB_WLM) {
        // ---- Wlm transpose tile ----
        int n0 = (bid % (V_PAD / 64)) * 64, k0 = (bid / (V_PAD / 64)) * 64;
#pragma unroll
        for (int it = 0; it < 16; it++) {
            int idx = tid + it * 256;
            int r = idx >> 6, c = idx & 63;
            int n = n0 + c;
            tile[r * 65 + c] = (n < Vv) ? Wlm[(size_t)(k0 + r) * Vv + n] : 0.f;
        }
        __syncthreads();
#pragma unroll
        for (int it = 0; it < 2; it++) {
            int idx = tid + it * 256;
            int n = idx >> 3, kc = idx & 7;
            __half hv[8];
#pragma unroll
            for (int j = 0; j < 8; j++) hv[j] = __float2half(tile[(kc * 8 + j) * 65 + n]);
            *reinterpret_cast<uint4*>(Bt + (size_t)(n0 + n) * Cc + k0 + kc * 8) =
                *reinterpret_cast<const uint4*>(hv);
        }
    } else if (bid < NB_WLM + NB_TRA) {
        // ---- square-W transposes ----
        int id = bid - NB_WLM;
        int id2 = id % 144;
        int xt = id2 % 12, yt = id2 / 12;
        int z = id / 144;
        int wi = z % 3, l = z / 3;
        const float* W = ((wi == 0) ? Wo : (wi == 1) ? W1 : W2) + (size_t)l * Cc * Cc;
        __half* T = ((wi == 0) ? To : (wi == 1) ? T1 : T2) + (size_t)l * Cc * Cc;
        int n0 = xt * 32, k0 = yt * 32;
        int tx = tid & 31, ty = tid >> 5;
        for (int dy = ty; dy < 32; dy += 8)
            tile[dy * 33 + tx] = W[(size_t)(k0 + dy) * Cc + n0 + tx];
        __syncthreads();
        for (int dy = ty; dy < 32; dy += 8)
            T[(size_t)(n0 + dy) * Cc + k0 + tx] = __float2half(tile[tx * 33 + dy]);
    } else {
        // ---- QKV repack (elementwise) ----
        int i = (bid - NB_WLM - NB_TRA) * 256 + tid;
        int total_w = NLl * QKV_P * Cc;
        if (i < total_w) {
            int k = i % Cc;
            int n = (i / Cc) % QKV_P;
            int l = i / (Cc * QKV_P);
            int sel = n / Cc, h = (n % Cc) / HSs, s = n % HSs;
            const float* W = (sel == 0) ? Wq : (sel == 1) ? Wk : Wv;
            OW[i] = __float2half(W[(((size_t)l * Hh + h) * Cc + k) * HSs + s]);
        } else {
            int j = i - total_w;
            if (j < NLl * QKV_P) {
                int n = j % QKV_P, l = j / QKV_P;
                int sel = n / Cc, h = (n % Cc) / HSs, s = n % HSs;
                const float* B = (sel == 0) ? bq : (sel == 1) ? bk : bv;
                OB[j] = B[((size_t)l * Hh + h) * HSs + s];
            }
        }
    }
}

// ---------------- layernorm (vectorized, fp16 out) ---------------------------
__global__ void ln_kernel(const float* __restrict__ x, const float* __restrict__ g,
                          const float* __restrict__ b, __half* __restrict__ y) {
    int row = blockIdx.x;
    const float4* xr4 = reinterpret_cast<const float4*>(x + (size_t)row * Cc);
    float4 v = make_float4(0.f, 0.f, 0.f, 0.f);
    int tid = threadIdx.x;
    if (tid < 96) v = xr4[tid];
    float lsum = v.x + v.y + v.z + v.w;
    float lsq = v.x * v.x + v.y * v.y + v.z * v.z + v.w * v.w;
    __shared__ float sh[64];
    int lane = tid & 31, wid = tid >> 5;
#pragma unroll
    for (int o = 16; o; o >>= 1) {
        lsum += __shfl_xor_sync(0xffffffffu, lsum, o);
        lsq  += __shfl_xor_sync(0xffffffffu, lsq,  o);
    }
    if (lane == 0) { sh[wid] = lsum; sh[wid + 32] = lsq; }
    __syncthreads();
    if (tid == 0) {
        float s = 0.f, q = 0.f;
        for (int w = 0; w < 4; w++) { s += sh[w]; q += sh[w + 32]; }
        sh[0] = s; sh[32] = q;
    }
    __syncthreads();
    float mu = sh[0] / Cc;
    float var = sh[32] / Cc - mu * mu;
    float rstd = rsqrtf(var + 1e-5f);
    if (tid < 96) {
        const float4 g4 = reinterpret_cast<const float4*>(g)[tid];
        const float4 b4 = reinterpret_cast<const float4*>(b)[tid];
        __half2 o0 = __floats2half2_rn((v.x - mu) * rstd * g4.x + b4.x,
                                       (v.y - mu) * rstd * g4.y + b4.y);
        __half2 o1 = __floats2half2_rn((v.z - mu) * rstd * g4.z + b4.z,
                                       (v.w - mu) * rstd * g4.w + b4.w);
        uint2 pack;
        pack.x = *reinterpret_cast<uint32_t*>(&o0);
        pack.y = *reinterpret_cast<uint32_t*>(&o1);
        reinterpret_cast<uint2*>(y + (size_t)row * Cc)[tid] = pack;
    }
}

// ---------------- common asm helpers ----------------------------------------
__device__ __forceinline__ uint32_t smem_u32(const void* p) {
    uint32_t a;
    asm("{ .reg .u64 t; cvta.to.shared.u64 t, %1; cvt.u32.u64 %0, t; }" : "=r"(a) : "l"(p));
    return a;
}
__device__ __forceinline__ void cp_async16(uint32_t saddr, const void* g) {
    asm volatile("cp.async.cg.shared.global [%0], [%1], 16;" :: "r"(saddr), "l"(g) : "memory");
}
__device__ __forceinline__ void cp_commit() {
    asm volatile("cp.async.commit_group;" ::: "memory");
}
template<int N>
__device__ __forceinline__ void cp_wait() {
    asm volatile("cp.async.wait_group %0;" :: "n"(N) : "memory");
}
__device__ __forceinline__ void ldm_x4(uint32_t* r, uint32_t addr) {
    asm volatile("ldmatrix.sync.aligned.m8n8.x4.shared.b16 {%0,%1,%2,%3}, [%4];"
                 : "=r"(r[0]), "=r"(r[1]), "=r"(r[2]), "=r"(r[3]) : "r"(addr));
}
__device__ __forceinline__ void ldm_x4_trans(uint32_t* r, uint32_t addr) {
    asm volatile("ldmatrix.sync.aligned.m8n8.x4.trans.shared.b16 {%0,%1,%2,%3}, [%4];"
                 : "=r"(r[0]), "=r"(r[1]), "=r"(r[2]), "=r"(r[3]) : "r"(addr));
}
__device__ __forceinline__ void mma_f16(float* c, const uint32_t* a, const uint32_t* b) {
    asm volatile(
        "mma.sync.aligned.m16n8k16.row.col.f32.f16.f16.f32 "
        "{%0,%1,%2,%3}, {%4,%5,%6,%7}, {%8,%9}, {%0,%1,%2,%3};"
        : "+f"(c[0]), "+f"(c[1]), "+f"(c[2]), "+f"(c[3])
        : "r"(a[0]), "r"(a[1]), "r"(a[2]), "r"(a[3]), "r"(b[0]), "r"(b[1]));
}

// ================= fp16 layer GEMM: CTA 64x128, K-tile 64, 3-stage ===========
constexpr int H16_NKT = Cc / 64;      // 6
constexpr int H16_STAGE = 24576;      // A 8KB + B 16KB
constexpr int H16_SMEM = 3 * H16_STAGE;  // 72KB

template<int FLAGS>  // 1=relu, 2=accumulate fp32, 16=also fp16 aux copy
__global__ __launch_bounds__(256, 2)
void h16_gemm_kernel(const __half* __restrict__ A, const __half* __restrict__ Bt,
                     const float* __restrict__ bias, void* __restrict__ Cv,
                     __half* __restrict__ aux, int ldc) {
    extern __shared__ __half smh[];
    int tid = threadIdx.x;
    int warp = tid >> 5, lane = tid & 31;
    int wm = warp & 1, wn = warp >> 1;
    int grp = lane >> 2, tig = lane & 3;
    int lr = lane & 7, sub = lane >> 3;
    int m0 = blockIdx.x * 64, n0 = blockIdx.y * 128;
    const __half* Ab = A + (size_t)m0 * Cc;
    const __half* Bb = Bt + (size_t)n0 * Cc;
    uint32_t sbase = smem_u32(smh);

    auto issue = [&](int kt, int stage) {
        uint32_t as = sbase + stage * (uint32_t)H16_STAGE;
        uint32_t bs = as + 8192u;
#pragma unroll
        for (int it = 0; it < 2; it++) {
            int slot = tid + it * 256;
            int r = slot >> 3, c = slot & 7;
            uint32_t so = (uint32_t)(r * 128 + ((c ^ (r & 7)) << 4));
            cp_async16(as + so, Ab + (size_t)r * Cc + kt * 64 + c * 8);
        }
#pragma unroll
        for (int it = 0; it < 4; it++) {
            int slot = tid + it * 256;
            int r = slot >> 3, c = slot & 7;
            uint32_t so = (uint32_t)(r * 128 + ((c ^ (r & 7)) << 4));
            cp_async16(bs + so, Bb + (size_t)r * Cc + kt * 64 + c * 8);
        }
    };

    float acc[2][4][4];
#pragma unroll
    for (int i = 0; i < 2; i++)
#pragma unroll
        for (int j = 0; j < 4; j++)
#pragma unroll
            for (int q = 0; q < 4; q++) acc[i][j][q] = 0.f;

    int rowA[2], rowB[2];
#pragma unroll
    for (int fm = 0; fm < 2; fm++) rowA[fm] = wm * 32 + fm * 16 + (sub & 1) * 8 + lr;
#pragma unroll
    for (int p = 0; p < 2; p++) rowB[p] = wn * 32 + p * 16 + (sub >> 1) * 8 + lr;
    int chA = sub >> 1, chB = sub & 1;

    issue(0, 0); cp_commit();
    issue(1, 1); cp_commit();

    int stage = 0;
#pragma unroll 1
    for (int kt = 0; kt < H16_NKT; kt++) {
        if (kt + 1 < H16_NKT) { cp_wait<1>(); } else { cp_wait<0>(); }
        __syncthreads();
        if (kt + 2 < H16_NKT) {
            int ns = stage + 2; if (ns >= 3) ns -= 3;
            issue(kt + 2, ns);
            cp_commit();
        }
        uint32_t as = sbase + stage * (uint32_t)H16_STAGE;
        uint32_t bs = as + 8192u;
#pragma unroll
        for (int k16 = 0; k16 < 4; k16++) {
            int cb = k16 * 2;
            uint32_t afr[2][4];
#pragma unroll
            for (int fm = 0; fm < 2; fm++) {
                int r = rowA[fm];
                ldm_x4(afr[fm], as + r * 128 + (((cb + chA) ^ (r & 7)) << 4));
            }
            uint32_t bfr[2][4];
#pragma unroll
            for (int p = 0; p < 2; p++) {
                int r = rowB[p];
                ldm_x4(bfr[p], bs + r * 128 + (((cb + chB) ^ (r & 7)) << 4));
            }
#pragma unroll
            for (int fm = 0; fm < 2; fm++)
#pragma unroll
                for (int fn = 0; fn < 4; fn++)
                    mma_f16(acc[fm][fn], afr[fm], &bfr[fn >> 1][(fn & 1) * 2]);
        }
        if (++stage >= 3) stage = 0;
    }

#pragma unroll
    for (int fm = 0; fm < 2; fm++) {
        int m_lo = m0 + wm * 32 + fm * 16 + grp;
        int m_hi = m_lo + 8;
#pragma unroll
        for (int fn = 0; fn < 4; fn++) {
            int n = n0 + wn * 32 + fn * 8 + tig * 2;
#pragma unroll
            for (int e = 0; e < 2; e++) {
                int nn = n + e;
                float bv = bias[nn];
                float v0 = acc[fm][fn][e]     + bv;
                float v1 = acc[fm][fn][e + 2] + bv;
                if (FLAGS & 1) { v0 = fmaxf(v0, 0.f); v1 = fmaxf(v1, 0.f); }
                if constexpr ((FLAGS & 2) != 0) {
                    float* C = (float*)Cv;
                    v0 += C[(size_t)m_lo * ldc + nn];
                    v1 += C[(size_t)m_hi * ldc + nn];
                    C[(size_t)m_lo * ldc + nn] = v0;
                    C[(size_t)m_hi * ldc + nn] = v1;
                    if constexpr ((FLAGS & 16) != 0) {
                        aux[(size_t)m_lo * ldc + nn] = __float2half(v0);
                        aux[(size_t)m_hi * ldc + nn] = __float2half(v1);
                    }
                } else {
                    __half* C = (__half*)Cv;
                    C[(size_t)m_lo * ldc + nn] = __float2half(v0);
                    C[(size_t)m_hi * ldc + nn] = __float2half(v1);
                }
            }
        }
    }
}

// ======== scores + exp + row-partial-sums (fp16 mma), P unnormalized =========
// grid: (36 lower-tri tile pairs, 1, BH)
__global__ __launch_bounds__(256, 2)
void scores_p_kernel(const __half* __restrict__ qkvH, __half* __restrict__ P,
                     float* __restrict__ psum) {
    int q = blockIdx.x, bh = blockIdx.z;
    int tb = 0;
    while ((tb + 1) * (tb + 2) / 2 <= q) tb++;
    int kb = q - tb * (tb + 1) / 2;
    int b = bh / Hh, h = bh % Hh;
    int k0 = kb * 128, t0 = tb * 128;

    __shared__ __align__(16) __half ssm[128 * 136];
    __shared__ float sums[128][2];

    int tid = threadIdx.x;
    int warp = tid >> 5, lane = tid & 31;
    int wm = warp & 3, wn = warp >> 2;
    int grp = lane >> 2, tig = lane & 3;
    int lr = lane & 7, sub = lane >> 3;

    uint32_t sb = smem_u32(ssm);
    uint32_t Ksb = sb, Qsb = sb + 16384u;
    const __half* Kb_ = qkvH + (size_t)(b * Tt + k0) * QKV_P + Cc + h * HSs;
    const __half* Qb_ = qkvH + (size_t)(b * Tt + t0) * QKV_P + h * HSs;

#pragma unroll
    for (int it = 0; it < 4; it++) {
        int slot = tid + it * 256;
        int r = slot >> 3, c = slot & 7;
        uint32_t so = (uint32_t)(r * 128 + ((c ^ (r & 7)) << 4));
        cp_async16(Ksb + so, Kb_ + (size_t)r * QKV_P + c * 8);
        cp_async16(Qsb + so, Qb_ + (size_t)r * QKV_P + c * 8);
    }
    cp_commit();
    cp_wait<0>();
    __syncthreads();

    float acc[2][8][4];
#pragma unroll
    for (int i = 0; i < 2; i++)
#pragma unroll
        for (int j = 0; j < 8; j++)
#pragma unroll
            for (int q2 = 0; q2 < 4; q2++) acc[i][j][q2] = 0.f;

    int rowA[2], rowB[4];
#pragma unroll
    for (int fm = 0; fm < 2; fm++) rowA[fm] = wm * 32 + fm * 16 + (sub & 1) * 8 + lr;
#pragma unroll
    for (int p = 0; p < 4; p++) rowB[p] = wn * 64 + p * 16 + (sub >> 1) * 8 + lr;
    int chA = sub >> 1, chB = sub & 1;

#pragma unroll
    for (int k16 = 0; k16 < 4; k16++) {
        int cb = k16 * 2;
        uint32_t afr[2][4];
#pragma unroll
        for (int fm = 0; fm < 2; fm++) {
            int r = rowA[fm];
            ldm_x4(afr[fm], Ksb + r * 128 + (((cb + chA) ^ (r & 7)) << 4));
        }
        uint32_t bfr[4][4];
#pragma unroll
        for (int p = 0; p < 4; p++) {
            int r = rowB[p];
            ldm_x4(bfr[p], Qsb + r * 128 + (((cb + chB) ^ (r & 7)) << 4));
        }
#pragma unroll
        for (int fm = 0; fm < 2; fm++)
#pragma unroll
            for (int fn = 0; fn < 8; fn++)
                mma_f16(acc[fm][fn], afr[fm], &bfr[fn >> 1][(fn & 1) * 2]);
    }
    __syncthreads();

    float rp[2][2] = {{0.f, 0.f}, {0.f, 0.f}};
#pragma unroll
    for (int fm = 0; fm < 2; fm++) {
        int kl = wm * 32 + fm * 16 + grp;
        int kh = kl + 8;
#pragma unroll
        for (int fn = 0; fn < 8; fn++) {
            int tc = wn * 64 + fn * 8 + tig * 2;
#pragma unroll
            for (int e = 0; e < 2; e++) {
                int t = tc + e;
                float v0 = (t0 + t >= k0 + kl) ? __expf(0.125f * acc[fm][fn][e]) : 0.f;
                float v1 = (t0 + t >= k0 + kh) ? __expf(0.125f * acc[fm][fn][e + 2]) : 0.f;
                ssm[kl * 136 + t] = __float2half(v0);
                ssm[kh * 136 + t] = __float2half(v1);
                rp[fm][0] += v0;
                rp[fm][1] += v1;
            }
        }
    }
#pragma unroll
    for (int fm = 0; fm < 2; fm++)
#pragma unroll
        for (int hl = 0; hl < 2; hl++) {
            rp[fm][hl] += __shfl_xor_sync(0xffffffffu, rp[fm][hl], 1);
            rp[fm][hl] += __shfl_xor_sync(0xffffffffu, rp[fm][hl], 2);
        }
    if (tig == 0) {
#pragma unroll
        for (int fm = 0; fm < 2; fm++) {
            sums[wm * 32 + fm * 16 + grp][wn]     = rp[fm][0];
            sums[wm * 32 + fm * 16 + grp + 8][wn] = rp[fm][1];
        }
    }
    __syncthreads();

    __half* Pb = P + ((size_t)bh * Tt + k0) * Tt + t0;
#pragma unroll
    for (int i = 0; i < 8; i++) {
        int idx = tid + i * 256;
        int r = idx >> 4, c = idx & 15;
        uint4 v = *reinterpret_cast<const uint4*>(&ssm[r * 136 + c * 8]);
        *reinterpret_cast<uint4*>(Pb + (size_t)r * Tt + c * 8) = v;
    }
    if (tid < 128)
        psum[((size_t)bh * 8 + tb) * Tt + k0 + tid] = sums[tid][0] + sums[tid][1];
}

// ---------------- PV via fp16 mma: cp.async P + ldmatrix.trans ----------------
__global__ __launch_bounds__(256, 2)
void pv_fp16_kernel(const __half* __restrict__ P, const __half* __restrict__ qkvH,
                    const float* __restrict__ psum, __half* __restrict__ att) {
    int tb = blockIdx.x, bh = blockIdx.y;
    int b = bh / Hh, h = bh % Hh;
    int t0 = tb * 128;

    __shared__ __align__(16) __half Pt[64 * 128];  // [k][t] 256B rows
    __shared__ __align__(16) __half Vt[64 * 64];   // [s][k] 128B rows
    __shared__ float invs[1024];

    int tid = threadIdx.x;
    int warp = tid >> 5, lane = tid & 31;
    int wm = warp & 3, wn = warp >> 2;
    int grp = lane >> 2, tig = lane & 3;
    int lr = lane & 7, sub = lane >> 3;

    uint32_t Ptb = smem_u32(Pt), Vtb = smem_u32(Vt);

    int nk = 2 * (tb + 1);
    int Kext = nk * 64;
    for (int i = tid; i < Kext; i += 256) {
        int tb0 = i >> 7;
        float s = 0.f;
        for (int t2 = tb0; t2 < 8; t2++)
            s += psum[((size_t)bh * 8 + t2) * Tt + i];
        invs[i] = 1.f / s;
    }

    float acc[2][4][4];
#pragma unroll
    for (int i = 0; i < 2; i++)
#pragma unroll
        for (int j = 0; j < 4; j++)
#pragma unroll
            for (int q = 0; q < 4; q++) acc[i][j][q] = 0.f;

    int rowB[2];
#pragma unroll
    for (int p = 0; p < 2; p++) rowB[p] = wn * 32 + p * 16 + (sub >> 1) * 8 + lr;
    int chB = sub & 1;
    int tcolA = wm * 32 + (sub & 1) * 8;
    int krowA = (sub >> 1) * 8 + lr;

#pragma unroll 1
    for (int kt = 0; kt < nk; kt++) {
        int k0 = kt * 64;
        __syncthreads();
        const __half* Pg = P + ((size_t)bh * Tt + k0) * Tt + t0;
#pragma unroll
        for (int i = 0; i < 4; i++) {
            int idx = tid + i * 256;
            int r = idx >> 4, c = idx & 15;
            uint32_t so = (uint32_t)(r * 256 + ((c ^ (r & 7)) << 4));
            cp_async16(Ptb + so, Pg + (size_t)r * Tt + c * 8);
        }
        cp_commit();
        const __half* Vg = qkvH + (size_t)(b * Tt + k0) * QKV_P + 2 * Cc + h * HSs;
#pragma unroll
        for (int i = 0; i < 8; i++) {
            int idx = tid + i * 256;
            int kk = idx >> 5, sp = idx & 31;
            uint32_t v = *reinterpret_cast<const uint32_t*>(Vg + (size_t)kk * QKV_P + sp * 2);
            float iv = invs[k0 + kk];
            __half2 h2 = *(const __half2*)&v;
            __half s0 = __float2half(__half2float(h2.x) * iv);
            __half s1 = __float2half(__half2float(h2.y) * iv);
            int s_ = sp * 2;
            Vt[s_ * 64 + ((((kk >> 3) ^ (s_ & 7)) << 3) | (kk & 7))] = s0;
            s_++;
            Vt[s_ * 64 + ((((kk >> 3) ^ (s_ & 7)) << 3) | (kk & 7))] = s1;
        }
        cp_wait<0>();
        __syncthreads();
#pragma unroll
        for (int k16 = 0; k16 < 4; k16++) {
            uint32_t afr[2][4];
#pragma unroll
            for (int fm = 0; fm < 2; fm++) {
                int krow = k16 * 16 + krowA;
                int tcol = tcolA + fm * 16;
                uint32_t addr = Ptb + krow * 256 + ((((tcol >> 3) ^ (krow & 7)) << 4));
                ldm_x4_trans(afr[fm], addr);
            }
            int cb = k16 * 2;
            uint32_t bfr[2][4];
#pragma unroll
            for (int p = 0; p < 2; p++) {
                int r = rowB[p];
                ldm_x4(bfr[p], Vtb + r * 128 + (((cb + chB) ^ (r & 7)) << 4));
            }
#pragma unroll
            for (int fm = 0; fm < 2; fm++)
#pragma unroll
                for (int fn = 0; fn < 4; fn++)
                    mma_f16(acc[fm][fn], afr[fm], &bfr[fn >> 1][(fn & 1) * 2]);
        }
    }

#pragma unroll
    for (int fm = 0; fm < 2; fm++) {
        int m_lo = t0 + wm * 32 + fm * 16 + grp;
        int m_hi = m_lo + 8;
#pragma unroll
        for (int fn = 0; fn < 4; fn++) {
            int s = wn * 32 + fn * 8 + tig * 2;
#pragma unroll
            for (int e = 0; e < 2; e++) {
                att[(size_t)(b * Tt + m_lo) * Cc + h * HSs + s + e] = __float2half(acc[fm][fn][e]);
                att[(size_t)(b * Tt + m_hi) * Cc + h * HSs + s + e] = __float2half(acc[fm][fn][e + 2]);
            }
        }
    }
}

// ================= fp16 LM head: 3-stage pipeline ============================
constexpr int LM_NKT = Cc / 64;       // 6
constexpr int LM_STAGE = 32768;       // A 16KB + B 16KB
constexpr int LM_SMEM = 3 * LM_STAGE; // 96KB

__global__ __launch_bounds__(256, 2)
void lmhead_fp16_kernel(const __half* __restrict__ A, const __half* __restrict__ Bt,
                        const float* __restrict__ bias, float* __restrict__ out) {
    extern __shared__ __half smh[];
    int tid = threadIdx.x;
    int warp = tid >> 5, lane = tid & 31;
    int wm = warp & 3, wn = warp >> 2;
    int grp = lane >> 2, tig = lane & 3;
    int lr = lane & 7, sub = lane >> 3;
    int m0 = blockIdx.x * 128, n0 = blockIdx.y * 128;
    const __half* Ab = A + (size_t)m0 * Cc;
    const __half* Bb = Bt + (size_t)n0 * Cc;

    uint32_t sbase = smem_u32(smh);

    auto issue = [&](int kt, int stage) {
        uint32_t as = sbase + stage * (uint32_t)LM_STAGE;
        uint32_t bs = as + 16384u;
#pragma unroll
        for (int it = 0; it < 4; it++) {
            int slot = tid + it * 256;
            int r = slot >> 3, c = slot & 7;
            uint32_t so = (uint32_t)(r * 128 + ((c ^ (r & 7)) << 4));
            cp_async16(as + so, Ab + (size_t)r * Cc + kt * 64 + c * 8);
            cp_async16(bs + so, Bb + (size_t)r * Cc + kt * 64 + c * 8);
        }
    };

    float acc[2][8][4];
#pragma unroll
    for (int i = 0; i < 2; i++)
#pragma unroll
        for (int j = 0; j < 8; j++)
#pragma unroll
            for (int q = 0; q < 4; q++) acc[i][j][q] = 0.f;

    int rowA[2], rowB[4];
#pragma unroll
    for (int fm = 0; fm < 2; fm++) rowA[fm] = wm * 32 + fm * 16 + (sub & 1) * 8 + lr;
#pragma unroll
    for (int p = 0; p < 4; p++) rowB[p] = wn * 64 + p * 16 + (sub >> 1) * 8 + lr;
    int chA = sub >> 1, chB = sub & 1;

    issue(0, 0); cp_commit();
    issue(1, 1); cp_commit();

    int stage = 0;
#pragma unroll 1
    for (int kt = 0; kt < LM_NKT; kt++) {
        if (kt + 1 < LM_NKT) { cp_wait<1>(); } else { cp_wait<0>(); }
        __syncthreads();
        if (kt + 2 < LM_NKT) {
            int ns = stage + 2; if (ns >= 3) ns -= 3;
            issue(kt + 2, ns);
            cp_commit();
        }
        uint32_t as = sbase + stage * (uint32_t)LM_STAGE;
        uint32_t bs = as + 16384u;
#pragma unroll
        for (int k16 = 0; k16 < 4; k16++) {
            int cb = k16 * 2;
            uint32_t afr[2][4];
#pragma unroll
            for (int fm = 0; fm < 2; fm++) {
                int r = rowA[fm];
                ldm_x4(afr[fm], as + r * 128 + (((cb + chA) ^ (r & 7)) << 4));
            }
            uint32_t bfr[4][4];
#pragma unroll
            for (int p = 0; p < 4; p++) {
                int r = rowB[p];
                ldm_x4(bfr[p], bs + r * 128 + (((cb + chB) ^ (r & 7)) << 4));
            }
#pragma unroll
            for (int fm = 0; fm < 2; fm++)
#pragma unroll
                for (int fn = 0; fn < 8; fn++)
                    mma_f16(acc[fm][fn], afr[fm], &bfr[fn >> 1][(fn & 1) * 2]);
        }
        if (++stage >= 3) stage = 0;
    }

#pragma unroll
    for (int fm = 0; fm < 2; fm++) {
        int m_lo = m0 + wm * 32 + fm * 16 + grp;
        int m_hi = m_lo + 8;
#pragma unroll
        for (int fn = 0; fn < 8; fn++) {
            int n = n0 + wn * 64 + fn * 8 + tig * 2;
#pragma unroll
            for (int e = 0; e < 2; e++) {
                int nn = n + e;
                if (nn >= Vv) continue;
                float bv = bias[nn];
                out[(size_t)m_lo * Vv + nn] = acc[fm][fn][e]     + bv;
                out[(size_t)m_hi * Vv + nn] = acc[fm][fn][e + 2] + bv;
            }
        }
    }
}

// ---------------- host launcher ---------------------------------------------
static float* symaddr(const void* s) {
    void* p = nullptr;
    cudaGetSymbolAddress(&p, s);
    return (float*)p;
}

extern "C" void kernel_launch(void* const* d_in, const int* in_sizes, int n_in,
                              void* d_out, int out_size) {
    const int*   x    = (const int*)d_in[0];
    const float* tok  = (const float*)d_in[1];
    const float* pos  = (const float*)d_in[2];
    const float* Wq   = (const float*)d_in[3];
    const float* bq   = (const float*)d_in[4];
    const float* Wk   = (const float*)d_in[5];
    const float* bk   = (const float*)d_in[6];
    const float* Wv   = (const float*)d_in[7];
    const float* bv   = (const float*)d_in[8];
    const float* Wo   = (const float*)d_in[9];
    const float* bo   = (const float*)d_in[10];
    const float* ln1g = (const float*)d_in[11];
    const float* ln1b = (const float*)d_in[12];
    const float* W1   = (const float*)d_in[13];
    const float* b1   = (const float*)d_in[14];
    const float* W2   = (const float*)d_in[15];
    const float* b2   = (const float*)d_in[16];
    const float* ln2g = (const float*)d_in[17];
    const float* ln2b = (const float*)d_in[18];
    const float* Wlm  = (const float*)d_in[19];
    const float* blm  = (const float*)d_in[20];
    float* out = (float*)d_out;

    float* ph      = symaddr(g_h);
    __half* paH    = (__half*)symaddr(g_aH);
    __half* pqkvH  = (__half*)symaddr(g_qkvH);
    __half* pattH  = (__half*)symaddr(g_attH);
    __half* pmH    = (__half*)symaddr(g_mH);
    __half* pP     = (__half*)symaddr(g_P);
    float* ppsum   = symaddr(g_psum);
    __half* pWqkvT = (__half*)symaddr(g_WqkvT);
    float* pbqkv   = symaddr(g_bqkv);
    __half* pWoT   = (__half*)symaddr(g_WoT);
    __half* pW1T   = (__half*)symaddr(g_W1T);
    __half* pW2T   = (__half*)symaddr(g_W2T);
    __half* phH    = (__half*)symaddr(g_hH);
    __half* pWlmH  = (__half*)symaddr(g_WlmH);

    static bool attr_done = false;
    if (!attr_done) {
        cudaFuncSetAttribute((const void*)h16_gemm_kernel<0>,  cudaFuncAttributeMaxDynamicSharedMemorySize, H16_SMEM);
        cudaFuncSetAttribute((const void*)h16_gemm_kernel<1>,  cudaFuncAttributeMaxDynamicSharedMemorySize, H16_SMEM);
        cudaFuncSetAttribute((const void*)h16_gemm_kernel<2>,  cudaFuncAttributeMaxDynamicSharedMemorySize, H16_SMEM);
        cudaFuncSetAttribute((const void*)h16_gemm_kernel<18>, cudaFuncAttributeMaxDynamicSharedMemorySize, H16_SMEM);
        cudaFuncSetAttribute((const void*)lmhead_fp16_kernel,  cudaFuncAttributeMaxDynamicSharedMemorySize, LM_SMEM);
        attr_done = true;
    }

    // launch 1: embedding
    embed_kernel<<<(M_ROWS * Cc + 255) / 256, 256>>>(x, tok, pos, ph);
    // launch 2: all weight prep in one kernel
    prep_kernel<<<NB_WLM + NB_TRA + NB_QKV, 256>>>(
        Wlm, pWlmH, Wo, W1, W2, pWoT, pW1T, pW2T,
        Wq, Wk, Wv, bq, bk, bv, pWqkvT, pbqkv);

    dim3 g_qkv_grid(M_ROWS / 64, QKV_P / 128);   // (32, 9)
    dim3 g_c_grid(M_ROWS / 64, Cc / 128);        // (32, 3)

    for (int l = 0; l < NLl; l++) {
        ln_kernel<<<M_ROWS, 128>>>(ph, ln1g + l * Cc, ln1b + l * Cc, paH);  // launch 3 (l=0)

        h16_gemm_kernel<0><<<g_qkv_grid, 256, H16_SMEM>>>(
            paH, pWqkvT + (size_t)l * QKV_P * Cc, pbqkv + l * QKV_P, pqkvH, nullptr, QKV_P);  // launch 4 (l=0)

        scores_p_kernel<<<dim3(36, 1, BH), 256>>>(pqkvH, pP, ppsum);
        pv_fp16_kernel<<<dim3(8, BH), 256>>>(pP, pqkvH, ppsum, pattH);

        h16_gemm_kernel<2><<<g_c_grid, 256, H16_SMEM>>>(
            pattH, pWoT + (size_t)l * Cc * Cc, bo + l * Cc, ph, nullptr, Cc);

        ln_kernel<<<M_ROWS, 128>>>(ph, ln2g + l * Cc, ln2b + l * Cc, paH);

        h16_gemm_kernel<1><<<g_c_grid, 256, H16_SMEM>>>(
            paH, pW1T + (size_t)l * Cc * Cc, b1 + l * Cc, pmH, nullptr, Cc);

        if (l == NLl - 1) {
            h16_gemm_kernel<18><<<g_c_grid, 256, H16_SMEM>>>(
                pmH, pW2T + (size_t)l * Cc * Cc, b2 + l * Cc, ph, phH, Cc);
        } else {
            h16_gemm_kernel<2><<<g_c_grid, 256, H16_SMEM>>>(
                pmH, pW2T + (size_t)l * Cc * Cc, b2 + l * Cc, ph, nullptr, Cc);
        }
    }

    // LM head (fp16 tensor cores, 3-stage pipeline)
    lmhead_fp16_kernel<<<dim3(M_ROWS / 128, V_PAD / 128), 256, LM_SMEM>>>(
        phH, pWlmH, blm, out);
}

// round 14
// speedup vs baseline: 9.5153x; 1.0260x over previous
#include <cuda_runtime.h>
#include <cuda_fp16.h>
#include <cstdint>

// Problem constants
constexpr int Vv = 50257, Cc = 384, Tt = 1024, Hh = 6, HSs = 64, NLl = 3, Bb = 2;
constexpr int M_ROWS = Bb * Tt;   // 2048
constexpr int BH = Bb * Hh;       // 12
constexpr int V_PAD = 50304;      // 393 * 128
constexpr int QKV_P = 3 * Cc;     // 1152

// ---------------- scratch (__device__ globals; no allocation allowed) --------
__device__ float g_h[M_ROWS * Cc];
__device__ __half g_aH[M_ROWS * Cc];               // LN output fp16
__device__ __half g_qkvH[M_ROWS * QKV_P];          // fused QKV, fp16
__device__ __half g_attH[M_ROWS * Cc];             // PV output fp16
__device__ __half g_mH[M_ROWS * Cc];               // relu(W1) output fp16
__device__ __half g_P[(size_t)BH * Tt * Tt];       // unnormalized probs [bh][k][t]
__device__ float g_psum[BH * 8 * Tt];              // per-(bh,tb) row partial sums
__device__ __half g_WqkvT[NLl * QKV_P * Cc];       // [l][n][k] fp16
__device__ float g_bqkv[NLl * QKV_P];
__device__ __half g_WoT[NLl * Cc * Cc];
__device__ __half g_W1T[NLl * Cc * Cc];
__device__ __half g_W2T[NLl * Cc * Cc];
__device__ __half g_hH[M_ROWS * Cc];               // h as fp16 (LM head input)
__device__ __half g_WlmH[(size_t)V_PAD * Cc];      // Wlm^T as fp16 [n][k]

// ---------------- embedding --------------------------------------------------
__global__ void embed_kernel(const int* __restrict__ x, const float* __restrict__ tok,
                             const float* __restrict__ pos, float* __restrict__ h) {
    int i = blockIdx.x * blockDim.x + threadIdx.x;
    if (i >= M_ROWS * Cc) return;
    int row = i / Cc, c = i % Cc;
    int t = row % Tt;
    h[i] = tok[(size_t)x[row] * Cc + c] + pos[t * Cc + c];
}

// ---------------- unified weight prep (one launch) ---------------------------
constexpr int NB_WLM = (V_PAD / 64) * (Cc / 64);
constexpr int NB_TRA = (Cc / 32) * (Cc / 32) * 3 * NLl;
constexpr int QKV_ELEMS = NLl * QKV_P * Cc + NLl * QKV_P;
constexpr int NB_QKV = (QKV_ELEMS + 255) / 256;

__global__ __launch_bounds__(256)
void prep_kernel(const float* __restrict__ Wlm, __half* __restrict__ Bt,
                 const float* __restrict__ Wo, const float* __restrict__ W1,
                 const float* __restrict__ W2,
                 __half* __restrict__ To, __half* __restrict__ T1, __half* __restrict__ T2,
                 const float* __restrict__ Wq, const float* __restrict__ Wk,
                 const float* __restrict__ Wv,
                 const float* __restrict__ bq, const float* __restrict__ bk,
                 const float* __restrict__ bv,
                 __half* __restrict__ OW, float* __restrict__ OB) {
    __shared__ float tile[64 * 65];
    int bid = blockIdx.x;
    int tid = threadIdx.x;

    if (bid < NB_WLM) {
        int n0 = (bid % (V_PAD / 64)) * 64, k0 = (bid / (V_PAD / 64)) * 64;
#pragma unroll
        for (int it = 0; it < 16; it++) {
            int idx = tid + it * 256;
            int r = idx >> 6, c = idx & 63;
            int n = n0 + c;
            tile[r * 65 + c] = (n < Vv) ? Wlm[(size_t)(k0 + r) * Vv + n] : 0.f;
        }
        __syncthreads();
#pragma unroll
        for (int it = 0; it < 2; it++) {
            int idx = tid + it * 256;
            int n = idx >> 3, kc = idx & 7;
            __half hv[8];
#pragma unroll
            for (int j = 0; j < 8; j++) hv[j] = __float2half(tile[(kc * 8 + j) * 65 + n]);
            *reinterpret_cast<uint4*>(Bt + (size_t)(n0 + n) * Cc + k0 + kc * 8) =
                *reinterpret_cast<const uint4*>(hv);
        }
    } else if (bid < NB_WLM + NB_TRA) {
        int id = bid - NB_WLM;
        int id2 = id % 144;
        int xt = id2 % 12, yt = id2 / 12;
        int z = id / 144;
        int wi = z % 3, l = z / 3;
        const float* W = ((wi == 0) ? Wo : (wi == 1) ? W1 : W2) + (size_t)l * Cc * Cc;
        __half* T = ((wi == 0) ? To : (wi == 1) ? T1 : T2) + (size_t)l * Cc * Cc;
        int n0 = xt * 32, k0 = yt * 32;
        int tx = tid & 31, ty = tid >> 5;
        for (int dy = ty; dy < 32; dy += 8)
            tile[dy * 33 + tx] = W[(size_t)(k0 + dy) * Cc + n0 + tx];
        __syncthreads();
        for (int dy = ty; dy < 32; dy += 8)
            T[(size_t)(n0 + dy) * Cc + k0 + tx] = __float2half(tile[tx * 33 + dy]);
    } else {
        int i = (bid - NB_WLM - NB_TRA) * 256 + tid;
        int total_w = NLl * QKV_P * Cc;
        if (i < total_w) {
            int k = i % Cc;
            int n = (i / Cc) % QKV_P;
            int l = i / (Cc * QKV_P);
            int sel = n / Cc, h = (n % Cc) / HSs, s = n % HSs;
            const float* W = (sel == 0) ? Wq : (sel == 1) ? Wk : Wv;
            OW[i] = __float2half(W[(((size_t)l * Hh + h) * Cc + k) * HSs + s]);
        } else {
            int j = i - total_w;
            if (j < NLl * QKV_P) {
                int n = j % QKV_P, l = j / QKV_P;
                int sel = n / Cc, h = (n % Cc) / HSs, s = n % HSs;
                const float* B = (sel == 0) ? bq : (sel == 1) ? bk : bv;
                OB[j] = B[((size_t)l * Hh + h) * HSs + s];
            }
        }
    }
}

// ---------------- layernorm (vectorized, fp16 out) ---------------------------
__global__ void ln_kernel(const float* __restrict__ x, const float* __restrict__ g,
                          const float* __restrict__ b, __half* __restrict__ y) {
    int row = blockIdx.x;
    const float4* xr4 = reinterpret_cast<const float4*>(x + (size_t)row * Cc);
    float4 v = make_float4(0.f, 0.f, 0.f, 0.f);
    int tid = threadIdx.x;
    if (tid < 96) v = xr4[tid];
    float lsum = v.x + v.y + v.z + v.w;
    float lsq = v.x * v.x + v.y * v.y + v.z * v.z + v.w * v.w;
    __shared__ float sh[64];
    int lane = tid & 31, wid = tid >> 5;
#pragma unroll
    for (int o = 16; o; o >>= 1) {
        lsum += __shfl_xor_sync(0xffffffffu, lsum, o);
        lsq  += __shfl_xor_sync(0xffffffffu, lsq,  o);
    }
    if (lane == 0) { sh[wid] = lsum; sh[wid + 32] = lsq; }
    __syncthreads();
    if (tid == 0) {
        float s = 0.f, q = 0.f;
        for (int w = 0; w < 4; w++) { s += sh[w]; q += sh[w + 32]; }
        sh[0] = s; sh[32] = q;
    }
    __syncthreads();
    float mu = sh[0] / Cc;
    float var = sh[32] / Cc - mu * mu;
    float rstd = rsqrtf(var + 1e-5f);
    if (tid < 96) {
        const float4 g4 = reinterpret_cast<const float4*>(g)[tid];
        const float4 b4 = reinterpret_cast<const float4*>(b)[tid];
        __half2 o0 = __floats2half2_rn((v.x - mu) * rstd * g4.x + b4.x,
                                       (v.y - mu) * rstd * g4.y + b4.y);
        __half2 o1 = __floats2half2_rn((v.z - mu) * rstd * g4.z + b4.z,
                                       (v.w - mu) * rstd * g4.w + b4.w);
        uint2 pack;
        pack.x = *reinterpret_cast<uint32_t*>(&o0);
        pack.y = *reinterpret_cast<uint32_t*>(&o1);
        reinterpret_cast<uint2*>(y + (size_t)row * Cc)[tid] = pack;
    }
}

// ---------------- common asm helpers ----------------------------------------
__device__ __forceinline__ uint32_t smem_u32(const void* p) {
    uint32_t a;
    asm("{ .reg .u64 t; cvta.to.shared.u64 t, %1; cvt.u32.u64 %0, t; }" : "=r"(a) : "l"(p));
    return a;
}
__device__ __forceinline__ void cp_async16(uint32_t saddr, const void* g) {
    asm volatile("cp.async.cg.shared.global [%0], [%1], 16;" :: "r"(saddr), "l"(g) : "memory");
}
__device__ __forceinline__ void cp_commit() {
    asm volatile("cp.async.commit_group;" ::: "memory");
}
template<int N>
__device__ __forceinline__ void cp_wait() {
    asm volatile("cp.async.wait_group %0;" :: "n"(N) : "memory");
}
__device__ __forceinline__ void ldm_x4(uint32_t* r, uint32_t addr) {
    asm volatile("ldmatrix.sync.aligned.m8n8.x4.shared.b16 {%0,%1,%2,%3}, [%4];"
                 : "=r"(r[0]), "=r"(r[1]), "=r"(r[2]), "=r"(r[3]) : "r"(addr));
}
__device__ __forceinline__ void ldm_x4_trans(uint32_t* r, uint32_t addr) {
    asm volatile("ldmatrix.sync.aligned.m8n8.x4.trans.shared.b16 {%0,%1,%2,%3}, [%4];"
                 : "=r"(r[0]), "=r"(r[1]), "=r"(r[2]), "=r"(r[3]) : "r"(addr));
}
__device__ __forceinline__ void mma_f16(float* c, const uint32_t* a, const uint32_t* b) {
    asm volatile(
        "mma.sync.aligned.m16n8k16.row.col.f32.f16.f16.f32 "
        "{%0,%1,%2,%3}, {%4,%5,%6,%7}, {%8,%9}, {%0,%1,%2,%3};"
        : "+f"(c[0]), "+f"(c[1]), "+f"(c[2]), "+f"(c[3])
        : "r"(a[0]), "r"(a[1]), "r"(a[2]), "r"(a[3]), "r"(b[0]), "r"(b[1]));
}

// ================= fp16 layer GEMM: CTA 64x128, K-tile 64, 3-stage ===========
constexpr int H16_NKT = Cc / 64;      // 6
constexpr int H16_STAGE = 24576;      // A 8KB + B 16KB
constexpr int H16_SMEM = 3 * H16_STAGE;  // 72KB

template<int FLAGS>  // 1=relu, 2=accumulate fp32, 16=also fp16 aux copy
__global__ __launch_bounds__(256, 2)
void h16_gemm_kernel(const __half* __restrict__ A, const __half* __restrict__ Bt,
                     const float* __restrict__ bias, void* __restrict__ Cv,
                     __half* __restrict__ aux, int ldc) {
    extern __shared__ __half smh[];
    int tid = threadIdx.x;
    int warp = tid >> 5, lane = tid & 31;
    int wm = warp & 1, wn = warp >> 1;
    int grp = lane >> 2, tig = lane & 3;
    int lr = lane & 7, sub = lane >> 3;
    int m0 = blockIdx.x * 64, n0 = blockIdx.y * 128;
    const __half* Ab = A + (size_t)m0 * Cc;
    const __half* Bb = Bt + (size_t)n0 * Cc;
    uint32_t sbase = smem_u32(smh);

    auto issue = [&](int kt, int stage) {
        uint32_t as = sbase + stage * (uint32_t)H16_STAGE;
        uint32_t bs = as + 8192u;
#pragma unroll
        for (int it = 0; it < 2; it++) {
            int slot = tid + it * 256;
            int r = slot >> 3, c = slot & 7;
            uint32_t so = (uint32_t)(r * 128 + ((c ^ (r & 7)) << 4));
            cp_async16(as + so, Ab + (size_t)r * Cc + kt * 64 + c * 8);
        }
#pragma unroll
        for (int it = 0; it < 4; it++) {
            int slot = tid + it * 256;
            int r = slot >> 3, c = slot & 7;
            uint32_t so = (uint32_t)(r * 128 + ((c ^ (r & 7)) << 4));
            cp_async16(bs + so, Bb + (size_t)r * Cc + kt * 64 + c * 8);
        }
    };

    float acc[2][4][4];
#pragma unroll
    for (int i = 0; i < 2; i++)
#pragma unroll
        for (int j = 0; j < 4; j++)
#pragma unroll
            for (int q = 0; q < 4; q++) acc[i][j][q] = 0.f;

    int rowA[2], rowB[2];
#pragma unroll
    for (int fm = 0; fm < 2; fm++) rowA[fm] = wm * 32 + fm * 16 + (sub & 1) * 8 + lr;
#pragma unroll
    for (int p = 0; p < 2; p++) rowB[p] = wn * 32 + p * 16 + (sub >> 1) * 8 + lr;
    int chA = sub >> 1, chB = sub & 1;

    issue(0, 0); cp_commit();
    issue(1, 1); cp_commit();

    int stage = 0;
#pragma unroll 1
    for (int kt = 0; kt < H16_NKT; kt++) {
        if (kt + 1 < H16_NKT) { cp_wait<1>(); } else { cp_wait<0>(); }
        __syncthreads();
        if (kt + 2 < H16_NKT) {
            int ns = stage + 2; if (ns >= 3) ns -= 3;
            issue(kt + 2, ns);
            cp_commit();
        }
        uint32_t as = sbase + stage * (uint32_t)H16_STAGE;
        uint32_t bs = as + 8192u;
#pragma unroll
        for (int k16 = 0; k16 < 4; k16++) {
            int cb = k16 * 2;
            uint32_t afr[2][4];
#pragma unroll
            for (int fm = 0; fm < 2; fm++) {
                int r = rowA[fm];
                ldm_x4(afr[fm], as + r * 128 + (((cb + chA) ^ (r & 7)) << 4));
            }
            uint32_t bfr[2][4];
#pragma unroll
            for (int p = 0; p < 2; p++) {
                int r = rowB[p];
                ldm_x4(bfr[p], bs + r * 128 + (((cb + chB) ^ (r & 7)) << 4));
            }
#pragma unroll
            for (int fm = 0; fm < 2; fm++)
#pragma unroll
                for (int fn = 0; fn < 4; fn++)
                    mma_f16(acc[fm][fn], afr[fm], &bfr[fn >> 1][(fn & 1) * 2]);
        }
        if (++stage >= 3) stage = 0;
    }

#pragma unroll
    for (int fm = 0; fm < 2; fm++) {
        int m_lo = m0 + wm * 32 + fm * 16 + grp;
        int m_hi = m_lo + 8;
#pragma unroll
        for (int fn = 0; fn < 4; fn++) {
            int n = n0 + wn * 32 + fn * 8 + tig * 2;
#pragma unroll
            for (int e = 0; e < 2; e++) {
                int nn = n + e;
                float bv = bias[nn];
                float v0 = acc[fm][fn][e]     + bv;
                float v1 = acc[fm][fn][e + 2] + bv;
                if (FLAGS & 1) { v0 = fmaxf(v0, 0.f); v1 = fmaxf(v1, 0.f); }
                if constexpr ((FLAGS & 2) != 0) {
                    float* C = (float*)Cv;
                    v0 += C[(size_t)m_lo * ldc + nn];
                    v1 += C[(size_t)m_hi * ldc + nn];
                    C[(size_t)m_lo * ldc + nn] = v0;
                    C[(size_t)m_hi * ldc + nn] = v1;
                    if constexpr ((FLAGS & 16) != 0) {
                        aux[(size_t)m_lo * ldc + nn] = __float2half(v0);
                        aux[(size_t)m_hi * ldc + nn] = __float2half(v1);
                    }
                } else {
                    __half* C = (__half*)Cv;
                    C[(size_t)m_lo * ldc + nn] = __float2half(v0);
                    C[(size_t)m_hi * ldc + nn] = __float2half(v1);
                }
            }
        }
    }
}

// ======== scores + exp + row-partial-sums (fp16 mma), P unnormalized =========
__global__ __launch_bounds__(256, 2)
void scores_p_kernel(const __half* __restrict__ qkvH, __half* __restrict__ P,
                     float* __restrict__ psum) {
    int q = blockIdx.x, bh = blockIdx.z;
    int tb = 0;
    while ((tb + 1) * (tb + 2) / 2 <= q) tb++;
    int kb = q - tb * (tb + 1) / 2;
    int b = bh / Hh, h = bh % Hh;
    int k0 = kb * 128, t0 = tb * 128;

    __shared__ __align__(16) __half ssm[128 * 136];
    __shared__ float sums[128][2];

    int tid = threadIdx.x;
    int warp = tid >> 5, lane = tid & 31;
    int wm = warp & 3, wn = warp >> 2;
    int grp = lane >> 2, tig = lane & 3;
    int lr = lane & 7, sub = lane >> 3;

    uint32_t sb = smem_u32(ssm);
    uint32_t Ksb = sb, Qsb = sb + 16384u;
    const __half* Kb_ = qkvH + (size_t)(b * Tt + k0) * QKV_P + Cc + h * HSs;
    const __half* Qb_ = qkvH + (size_t)(b * Tt + t0) * QKV_P + h * HSs;

#pragma unroll
    for (int it = 0; it < 4; it++) {
        int slot = tid + it * 256;
        int r = slot >> 3, c = slot & 7;
        uint32_t so = (uint32_t)(r * 128 + ((c ^ (r & 7)) << 4));
        cp_async16(Ksb + so, Kb_ + (size_t)r * QKV_P + c * 8);
        cp_async16(Qsb + so, Qb_ + (size_t)r * QKV_P + c * 8);
    }
    cp_commit();
    cp_wait<0>();
    __syncthreads();

    float acc[2][8][4];
#pragma unroll
    for (int i = 0; i < 2; i++)
#pragma unroll
        for (int j = 0; j < 8; j++)
#pragma unroll
            for (int q2 = 0; q2 < 4; q2++) acc[i][j][q2] = 0.f;

    int rowA[2], rowB[4];
#pragma unroll
    for (int fm = 0; fm < 2; fm++) rowA[fm] = wm * 32 + fm * 16 + (sub & 1) * 8 + lr;
#pragma unroll
    for (int p = 0; p < 4; p++) rowB[p] = wn * 64 + p * 16 + (sub >> 1) * 8 + lr;
    int chA = sub >> 1, chB = sub & 1;

#pragma unroll
    for (int k16 = 0; k16 < 4; k16++) {
        int cb = k16 * 2;
        uint32_t afr[2][4];
#pragma unroll
        for (int fm = 0; fm < 2; fm++) {
            int r = rowA[fm];
            ldm_x4(afr[fm], Ksb + r * 128 + (((cb + chA) ^ (r & 7)) << 4));
        }
        uint32_t bfr[4][4];
#pragma unroll
        for (int p = 0; p < 4; p++) {
            int r = rowB[p];
            ldm_x4(bfr[p], Qsb + r * 128 + (((cb + chB) ^ (r & 7)) << 4));
        }
#pragma unroll
        for (int fm = 0; fm < 2; fm++)
#pragma unroll
            for (int fn = 0; fn < 8; fn++)
                mma_f16(acc[fm][fn], afr[fm], &bfr[fn >> 1][(fn & 1) * 2]);
    }
    __syncthreads();

    float rp[2][2] = {{0.f, 0.f}, {0.f, 0.f}};
#pragma unroll
    for (int fm = 0; fm < 2; fm++) {
        int kl = wm * 32 + fm * 16 + grp;
        int kh = kl + 8;
#pragma unroll
        for (int fn = 0; fn < 8; fn++) {
            int tc = wn * 64 + fn * 8 + tig * 2;
#pragma unroll
            for (int e = 0; e < 2; e++) {
                int t = tc + e;
                float v0 = (t0 + t >= k0 + kl) ? __expf(0.125f * acc[fm][fn][e]) : 0.f;
                float v1 = (t0 + t >= k0 + kh) ? __expf(0.125f * acc[fm][fn][e + 2]) : 0.f;
                ssm[kl * 136 + t] = __float2half(v0);
                ssm[kh * 136 + t] = __float2half(v1);
                rp[fm][0] += v0;
                rp[fm][1] += v1;
            }
        }
    }
#pragma unroll
    for (int fm = 0; fm < 2; fm++)
#pragma unroll
        for (int hl = 0; hl < 2; hl++) {
            rp[fm][hl] += __shfl_xor_sync(0xffffffffu, rp[fm][hl], 1);
            rp[fm][hl] += __shfl_xor_sync(0xffffffffu, rp[fm][hl], 2);
        }
    if (tig == 0) {
#pragma unroll
        for (int fm = 0; fm < 2; fm++) {
            sums[wm * 32 + fm * 16 + grp][wn]     = rp[fm][0];
            sums[wm * 32 + fm * 16 + grp + 8][wn] = rp[fm][1];
        }
    }
    __syncthreads();

    __half* Pb = P + ((size_t)bh * Tt + k0) * Tt + t0;
#pragma unroll
    for (int i = 0; i < 8; i++) {
        int idx = tid + i * 256;
        int r = idx >> 4, c = idx & 15;
        uint4 v = *reinterpret_cast<const uint4*>(&ssm[r * 136 + c * 8]);
        *reinterpret_cast<uint4*>(Pb + (size_t)r * Tt + c * 8) = v;
    }
    if (tid < 128)
        psum[((size_t)bh * 8 + tb) * Tt + k0 + tid] = sums[tid][0] + sums[tid][1];
}

// ---------------- PV via fp16 mma: cp.async P + ldmatrix.trans ----------------
__global__ __launch_bounds__(256, 2)
void pv_fp16_kernel(const __half* __restrict__ P, const __half* __restrict__ qkvH,
                    const float* __restrict__ psum, __half* __restrict__ att) {
    int tb = blockIdx.x, bh = blockIdx.y;
    int b = bh / Hh, h = bh % Hh;
    int t0 = tb * 128;

    __shared__ __align__(16) __half Pt[64 * 128];
    __shared__ __align__(16) __half Vt[64 * 64];
    __shared__ float invs[1024];

    int tid = threadIdx.x;
    int warp = tid >> 5, lane = tid & 31;
    int wm = warp & 3, wn = warp >> 2;
    int grp = lane >> 2, tig = lane & 3;
    int lr = lane & 7, sub = lane >> 3;

    uint32_t Ptb = smem_u32(Pt), Vtb = smem_u32(Vt);

    int nk = 2 * (tb + 1);
    int Kext = nk * 64;
    for (int i = tid; i < Kext; i += 256) {
        int tb0 = i >> 7;
        float s = 0.f;
        for (int t2 = tb0; t2 < 8; t2++)
            s += psum[((size_t)bh * 8 + t2) * Tt + i];
        invs[i] = 1.f / s;
    }

    float acc[2][4][4];
#pragma unroll
    for (int i = 0; i < 2; i++)
#pragma unroll
        for (int j = 0; j < 4; j++)
#pragma unroll
            for (int q = 0; q < 4; q++) acc[i][j][q] = 0.f;

    int rowB[2];
#pragma unroll
    for (int p = 0; p < 2; p++) rowB[p] = wn * 32 + p * 16 + (sub >> 1) * 8 + lr;
    int chB = sub & 1;
    int tcolA = wm * 32 + (sub & 1) * 8;
    int krowA = (sub >> 1) * 8 + lr;

#pragma unroll 1
    for (int kt = 0; kt < nk; kt++) {
        int k0 = kt * 64;
        __syncthreads();
        const __half* Pg = P + ((size_t)bh * Tt + k0) * Tt + t0;
#pragma unroll
        for (int i = 0; i < 4; i++) {
            int idx = tid + i * 256;
            int r = idx >> 4, c = idx & 15;
            uint32_t so = (uint32_t)(r * 256 + ((c ^ (r & 7)) << 4));
            cp_async16(Ptb + so, Pg + (size_t)r * Tt + c * 8);
        }
        cp_commit();
        const __half* Vg = qkvH + (size_t)(b * Tt + k0) * QKV_P + 2 * Cc + h * HSs;
#pragma unroll
        for (int i = 0; i < 8; i++) {
            int idx = tid + i * 256;
            int kk = idx >> 5, sp = idx & 31;
            uint32_t v = *reinterpret_cast<const uint32_t*>(Vg + (size_t)kk * QKV_P + sp * 2);
            float iv = invs[k0 + kk];
            __half2 h2 = *(const __half2*)&v;
            __half s0 = __float2half(__half2float(h2.x) * iv);
            __half s1 = __float2half(__half2float(h2.y) * iv);
            int s_ = sp * 2;
            Vt[s_ * 64 + ((((kk >> 3) ^ (s_ & 7)) << 3) | (kk & 7))] = s0;
            s_++;
            Vt[s_ * 64 + ((((kk >> 3) ^ (s_ & 7)) << 3) | (kk & 7))] = s1;
        }
        cp_wait<0>();
        __syncthreads();
#pragma unroll
        for (int k16 = 0; k16 < 4; k16++) {
            uint32_t afr[2][4];
#pragma unroll
            for (int fm = 0; fm < 2; fm++) {
                int krow = k16 * 16 + krowA;
                int tcol = tcolA + fm * 16;
                uint32_t addr = Ptb + krow * 256 + ((((tcol >> 3) ^ (krow & 7)) << 4));
                ldm_x4_trans(afr[fm], addr);
            }
            int cb = k16 * 2;
            uint32_t bfr[2][4];
#pragma unroll
            for (int p = 0; p < 2; p++) {
                int r = rowB[p];
                ldm_x4(bfr[p], Vtb + r * 128 + (((cb + chB) ^ (r & 7)) << 4));
            }
#pragma unroll
            for (int fm = 0; fm < 2; fm++)
#pragma unroll
                for (int fn = 0; fn < 4; fn++)
                    mma_f16(acc[fm][fn], afr[fm], &bfr[fn >> 1][(fn & 1) * 2]);
        }
    }

#pragma unroll
    for (int fm = 0; fm < 2; fm++) {
        int m_lo = t0 + wm * 32 + fm * 16 + grp;
        int m_hi = m_lo + 8;
#pragma unroll
        for (int fn = 0; fn < 4; fn++) {
            int s = wn * 32 + fn * 8 + tig * 2;
#pragma unroll
            for (int e = 0; e < 2; e++) {
                att[(size_t)(b * Tt + m_lo) * Cc + h * HSs + s + e] = __float2half(acc[fm][fn][e]);
                att[(size_t)(b * Tt + m_hi) * Cc + h * HSs + s + e] = __float2half(acc[fm][fn][e + 2]);
            }
        }
    }
}

// ========== 128x128 fp16 GEMM, 3-stage (LM head + QKV) =======================
// MODE 0: fp32 out, +bias, column guard < Vv (LM head)
// MODE 1: fp16 out, +bias, no guard (QKV; ldc = QKV_P)
constexpr int LM_NKT = Cc / 64;       // 6
constexpr int LM_STAGE = 32768;       // A 16KB + B 16KB
constexpr int LM_SMEM = 3 * LM_STAGE; // 96KB

template<int MODE>
__global__ __launch_bounds__(256, 2)
void g128_fp16_kernel(const __half* __restrict__ A, const __half* __restrict__ Bt,
                      const float* __restrict__ bias, void* __restrict__ Cv, int ldc) {
    extern __shared__ __half smh[];
    int tid = threadIdx.x;
    int warp = tid >> 5, lane = tid & 31;
    int wm = warp & 3, wn = warp >> 2;
    int grp = lane >> 2, tig = lane & 3;
    int lr = lane & 7, sub = lane >> 3;
    int m0 = blockIdx.x * 128, n0 = blockIdx.y * 128;
    const __half* Ab = A + (size_t)m0 * Cc;
    const __half* Bb = Bt + (size_t)n0 * Cc;

    uint32_t sbase = smem_u32(smh);

    auto issue = [&](int kt, int stage) {
        uint32_t as = sbase + stage * (uint32_t)LM_STAGE;
        uint32_t bs = as + 16384u;
#pragma unroll
        for (int it = 0; it < 4; it++) {
            int slot = tid + it * 256;
            int r = slot >> 3, c = slot & 7;
            uint32_t so = (uint32_t)(r * 128 + ((c ^ (r & 7)) << 4));
            cp_async16(as + so, Ab + (size_t)r * Cc + kt * 64 + c * 8);
            cp_async16(bs + so, Bb + (size_t)r * Cc + kt * 64 + c * 8);
        }
    };

    float acc[2][8][4];
#pragma unroll
    for (int i = 0; i < 2; i++)
#pragma unroll
        for (int j = 0; j < 8; j++)
#pragma unroll
            for (int q = 0; q < 4; q++) acc[i][j][q] = 0.f;

    int rowA[2], rowB[4];
#pragma unroll
    for (int fm = 0; fm < 2; fm++) rowA[fm] = wm * 32 + fm * 16 + (sub & 1) * 8 + lr;
#pragma unroll
    for (int p = 0; p < 4; p++) rowB[p] = wn * 64 + p * 16 + (sub >> 1) * 8 + lr;
    int chA = sub >> 1, chB = sub & 1;

    issue(0, 0); cp_commit();
    issue(1, 1); cp_commit();

    int stage = 0;
#pragma unroll 1
    for (int kt = 0; kt < LM_NKT; kt++) {
        if (kt + 1 < LM_NKT) { cp_wait<1>(); } else { cp_wait<0>(); }
        __syncthreads();
        if (kt + 2 < LM_NKT) {
            int ns = stage + 2; if (ns >= 3) ns -= 3;
            issue(kt + 2, ns);
            cp_commit();
        }
        uint32_t as = sbase + stage * (uint32_t)LM_STAGE;
        uint32_t bs = as + 16384u;
#pragma unroll
        for (int k16 = 0; k16 < 4; k16++) {
            int cb = k16 * 2;
            uint32_t afr[2][4];
#pragma unroll
            for (int fm = 0; fm < 2; fm++) {
                int r = rowA[fm];
                ldm_x4(afr[fm], as + r * 128 + (((cb + chA) ^ (r & 7)) << 4));
            }
            uint32_t bfr[4][4];
#pragma unroll
            for (int p = 0; p < 4; p++) {
                int r = rowB[p];
                ldm_x4(bfr[p], bs + r * 128 + (((cb + chB) ^ (r & 7)) << 4));
            }
#pragma unroll
            for (int fm = 0; fm < 2; fm++)
#pragma unroll
                for (int fn = 0; fn < 8; fn++)
                    mma_f16(acc[fm][fn], afr[fm], &bfr[fn >> 1][(fn & 1) * 2]);
        }
        if (++stage >= 3) stage = 0;
    }

#pragma unroll
    for (int fm = 0; fm < 2; fm++) {
        int m_lo = m0 + wm * 32 + fm * 16 + grp;
        int m_hi = m_lo + 8;
#pragma unroll
        for (int fn = 0; fn < 8; fn++) {
            int n = n0 + wn * 64 + fn * 8 + tig * 2;
#pragma unroll
            for (int e = 0; e < 2; e++) {
                int nn = n + e;
                if (MODE == 0 && nn >= Vv) continue;
                float bv = bias[nn];
                float v0 = acc[fm][fn][e]     + bv;
                float v1 = acc[fm][fn][e + 2] + bv;
                if constexpr (MODE == 0) {
                    float* C = (float*)Cv;
                    C[(size_t)m_lo * ldc + nn] = v0;
                    C[(size_t)m_hi * ldc + nn] = v1;
                } else {
                    __half* C = (__half*)Cv;
                    C[(size_t)m_lo * ldc + nn] = __float2half(v0);
                    C[(size_t)m_hi * ldc + nn] = __float2half(v1);
                }
            }
        }
    }
}

// ---------------- host launcher ---------------------------------------------
static float* symaddr(const void* s) {
    void* p = nullptr;
    cudaGetSymbolAddress(&p, s);
    return (float*)p;
}

extern "C" void kernel_launch(void* const* d_in, const int* in_sizes, int n_in,
                              void* d_out, int out_size) {
    const int*   x    = (const int*)d_in[0];
    const float* tok  = (const float*)d_in[1];
    const float* pos  = (const float*)d_in[2];
    const float* Wq   = (const float*)d_in[3];
    const float* bq   = (const float*)d_in[4];
    const float* Wk   = (const float*)d_in[5];
    const float* bk   = (const float*)d_in[6];
    const float* Wv   = (const float*)d_in[7];
    const float* bv   = (const float*)d_in[8];
    const float* Wo   = (const float*)d_in[9];
    const float* bo   = (const float*)d_in[10];
    const float* ln1g = (const float*)d_in[11];
    const float* ln1b = (const float*)d_in[12];
    const float* W1   = (const float*)d_in[13];
    const float* b1   = (const float*)d_in[14];
    const float* W2   = (const float*)d_in[15];
    const float* b2   = (const float*)d_in[16];
    const float* ln2g = (const float*)d_in[17];
    const float* ln2b = (const float*)d_in[18];
    const float* Wlm  = (const float*)d_in[19];
    const float* blm  = (const float*)d_in[20];
    float* out = (float*)d_out;

    float* ph      = symaddr(g_h);
    __half* paH    = (__half*)symaddr(g_aH);
    __half* pqkvH  = (__half*)symaddr(g_qkvH);
    __half* pattH  = (__half*)symaddr(g_attH);
    __half* pmH    = (__half*)symaddr(g_mH);
    __half* pP     = (__half*)symaddr(g_P);
    float* ppsum   = symaddr(g_psum);
    __half* pWqkvT = (__half*)symaddr(g_WqkvT);
    float* pbqkv   = symaddr(g_bqkv);
    __half* pWoT   = (__half*)symaddr(g_WoT);
    __half* pW1T   = (__half*)symaddr(g_W1T);
    __half* pW2T   = (__half*)symaddr(g_W2T);
    __half* phH    = (__half*)symaddr(g_hH);
    __half* pWlmH  = (__half*)symaddr(g_WlmH);

    static bool attr_done = false;
    if (!attr_done) {
        cudaFuncSetAttribute((const void*)h16_gemm_kernel<1>,  cudaFuncAttributeMaxDynamicSharedMemorySize, H16_SMEM);
        cudaFuncSetAttribute((const void*)h16_gemm_kernel<2>,  cudaFuncAttributeMaxDynamicSharedMemorySize, H16_SMEM);
        cudaFuncSetAttribute((const void*)h16_gemm_kernel<18>, cudaFuncAttributeMaxDynamicSharedMemorySize, H16_SMEM);
        cudaFuncSetAttribute((const void*)g128_fp16_kernel<0>, cudaFuncAttributeMaxDynamicSharedMemorySize, LM_SMEM);
        cudaFuncSetAttribute((const void*)g128_fp16_kernel<1>, cudaFuncAttributeMaxDynamicSharedMemorySize, LM_SMEM);
        attr_done = true;
    }

    embed_kernel<<<(M_ROWS * Cc + 255) / 256, 256>>>(x, tok, pos, ph);
    prep_kernel<<<NB_WLM + NB_TRA + NB_QKV, 256>>>(
        Wlm, pWlmH, Wo, W1, W2, pWoT, pW1T, pW2T,
        Wq, Wk, Wv, bq, bk, bv, pWqkvT, pbqkv);

    dim3 g_qkv_grid(M_ROWS / 128, QKV_P / 128);   // (16, 9) 128-tile
    dim3 g_c_grid(M_ROWS / 64, Cc / 128);         // (32, 3)

    for (int l = 0; l < NLl; l++) {
        ln_kernel<<<M_ROWS, 128>>>(ph, ln1g + l * Cc, ln1b + l * Cc, paH);

        g128_fp16_kernel<1><<<g_qkv_grid, 256, LM_SMEM>>>(
            paH, pWqkvT + (size_t)l * QKV_P * Cc, pbqkv + l * QKV_P, pqkvH, QKV_P);

        scores_p_kernel<<<dim3(36, 1, BH), 256>>>(pqkvH, pP, ppsum);
        pv_fp16_kernel<<<dim3(8, BH), 256>>>(pP, pqkvH, ppsum, pattH);

        h16_gemm_kernel<2><<<g_c_grid, 256, H16_SMEM>>>(
            pattH, pWoT + (size_t)l * Cc * Cc, bo + l * Cc, ph, nullptr, Cc);

        ln_kernel<<<M_ROWS, 128>>>(ph, ln2g + l * Cc, ln2b + l * Cc, paH);

        h16_gemm_kernel<1><<<g_c_grid, 256, H16_SMEM>>>(
            paH, pW1T + (size_t)l * Cc * Cc, b1 + l * Cc, pmH, nullptr, Cc);

        if (l == NLl - 1) {
            h16_gemm_kernel<18><<<g_c_grid, 256, H16_SMEM>>>(
                pmH, pW2T + (size_t)l * Cc * Cc, b2 + l * Cc, ph, phH, Cc);
        } else {
            h16_gemm_kernel<2><<<g_c_grid, 256, H16_SMEM>>>(
                pmH, pW2T + (size_t)l * Cc * Cc, b2 + l * Cc, ph, nullptr, Cc);
        }
    }

    // LM head (fp16 tensor cores, 3-stage pipeline, 128x128)
    g128_fp16_kernel<0><<<dim3(M_ROWS / 128, V_PAD / 128), 256, LM_SMEM>>>(
        phH, pWlmH, blm, out, Vv);
}